// round 1
// baseline (speedup 1.0000x reference)
#include <cuda_runtime.h>

#define NH 12
#define TT 2048
#define BB 4
#define DM 768
#define HD 64
#define MTOT (BB*TT)   // 8192

// log2(e) / sqrt(64)
#define QSCALE 0.18033688011112042f

// Scratch (device globals: allocation-free)
__device__ float g_Q[BB*NH*TT*HD];
__device__ float g_K[BB*NH*TT*HD];
__device__ float g_V[BB*NH*TT*HD];
__device__ float g_A[MTOT*DM];      // attention output, [8192][768] row-major, col = h*64+e
__device__ float g_W2[DM*DM];       // gated flattened Wo
__device__ float g_b2[DM];          // gated summed bo

typedef unsigned long long ull;

__device__ __forceinline__ void ffma2(ull& d, ull a, ull b) {
    asm("fma.rn.f32x2 %0, %1, %2, %0;" : "+l"(d) : "l"(a), "l"(b));
}
__device__ __forceinline__ ull mul2(ull a, ull b) {
    ull d; asm("mul.rn.f32x2 %0, %1, %2;" : "=l"(d) : "l"(a), "l"(b)); return d;
}
__device__ __forceinline__ ull dup2(float x) {
    ull r; asm("mov.b64 %0, {%1, %1};" : "=l"(r) : "f"(x)); return r;
}
__device__ __forceinline__ float2 unpk(ull v) {
    float2 f; asm("mov.b64 {%0, %1}, %2;" : "=f"(f.x), "=f"(f.y) : "l"(v)); return f;
}
__device__ __forceinline__ float fexp2(float x) {
    float y; asm("ex2.approx.ftz.f32 %0, %1;" : "=f"(y) : "f"(x)); return y;
}

// ---------------------------------------------------------------------------
// Prep: fold gate into Wo (flattened [768][768]) and bo (summed over heads)
// ---------------------------------------------------------------------------
__global__ void prep_w2(const float* __restrict__ Wo, const float* __restrict__ gate) {
    int idx = blockIdx.x * 256 + threadIdx.x;
    if (idx >= NH*HD*DM) return;
    int h = idx / (HD*DM);
    float g = gate[h];
    g = (g < 1e-6f) ? 0.0f : g;
    // Wo[h][e][d] flattens to exactly W2[(h*64+e)][d]
    g_W2[idx] = Wo[idx] * g;
}

__global__ void prep_b2(const float* __restrict__ bo, const float* __restrict__ gate) {
    int d = blockIdx.x * 256 + threadIdx.x;
    if (d >= DM) return;
    float s = 0.0f;
    #pragma unroll
    for (int h = 0; h < NH; h++) {
        float g = gate[h];
        g = (g < 1e-6f) ? 0.0f : g;
        s += g * bo[h*DM + d];
    }
    g_b2[d] = s;
}

// ---------------------------------------------------------------------------
// QKV projection GEMM: C[128x128] = X[128x768] * W[768x(2 heads x 64)] + bias
// grid: (M/128, H/2, 3 proj). f32x2 inner product, 8x8 microtile, BK=16.
// ---------------------------------------------------------------------------
__global__ void __launch_bounds__(256, 2)
qkv_gemm(const float* __restrict__ X,
         const float* __restrict__ Wq, const float* __restrict__ bq,
         const float* __restrict__ Wk, const float* __restrict__ bk,
         const float* __restrict__ Wv, const float* __restrict__ bv)
{
    __shared__ __align__(16) float As[16][132];   // [k][m] transposed
    __shared__ __align__(16) float Bs[16][132];   // [k][n]

    const int m0 = blockIdx.x * 128;
    const int h0 = blockIdx.y * 2;
    const int proj = blockIdx.z;

    const float* W; const float* bias; float* obuf;
    if (proj == 0)      { W = Wq; bias = bq; obuf = g_Q; }
    else if (proj == 1) { W = Wk; bias = bk; obuf = g_K; }
    else                { W = Wv; bias = bv; obuf = g_V; }

    const int tid = threadIdx.x;
    const int i0 = (tid >> 4) * 8;
    const int j0 = (tid & 15) * 8;

    ull acc[8][4];
    #pragma unroll
    for (int r = 0; r < 8; r++)
        #pragma unroll
        for (int c = 0; c < 4; c++) acc[r][c] = 0ull;

    for (int k0 = 0; k0 < DM; k0 += 16) {
        #pragma unroll
        for (int it = 0; it < 2; it++) {
            int f = tid + it*256;
            int row = f >> 2, kc = (f & 3) << 2;
            float4 v = *(const float4*)(X + (size_t)(m0+row)*DM + k0 + kc);
            As[kc+0][row] = v.x; As[kc+1][row] = v.y;
            As[kc+2][row] = v.z; As[kc+3][row] = v.w;
        }
        #pragma unroll
        for (int it = 0; it < 2; it++) {
            int f = tid + it*256;
            int kr = f >> 5, nc = (f & 31) << 2;
            int head = h0 + (nc >> 6);
            int e = nc & 63;
            float4 v = *(const float4*)(W + (size_t)head*(DM*HD) + (size_t)(k0+kr)*HD + e);
            *(float4*)&Bs[kr][nc] = v;
        }
        __syncthreads();
        #pragma unroll
        for (int k = 0; k < 16; k++) {
            float4 a0 = *(const float4*)&As[k][i0];
            float4 a1 = *(const float4*)&As[k][i0+4];
            ulonglong2 b0 = *(const ulonglong2*)&Bs[k][j0];
            ulonglong2 b1 = *(const ulonglong2*)&Bs[k][j0+4];
            float av[8] = {a0.x, a0.y, a0.z, a0.w, a1.x, a1.y, a1.z, a1.w};
            #pragma unroll
            for (int r = 0; r < 8; r++) {
                ull ad = dup2(av[r]);
                ffma2(acc[r][0], ad, b0.x);
                ffma2(acc[r][1], ad, b0.y);
                ffma2(acc[r][2], ad, b1.x);
                ffma2(acc[r][3], ad, b1.y);
            }
        }
        __syncthreads();
    }

    #pragma unroll
    for (int r = 0; r < 8; r++) {
        int m = m0 + i0 + r;
        int bidx = m >> 11, t = m & (TT-1);
        #pragma unroll
        for (int c = 0; c < 4; c++) {
            int col = j0 + c*2;
            int head = h0 + (col >> 6);
            int e = col & 63;
            float2 v = unpk(acc[r][c]);
            v.x += bias[head*HD + e];
            v.y += bias[head*HD + e + 1];
            if (proj == 0) { v.x *= QSCALE; v.y *= QSCALE; }
            *(float2*)&obuf[((size_t)(bidx*NH + head)*TT + t)*HD + e] = v;
        }
    }
}

// ---------------------------------------------------------------------------
// Output projection GEMM: out[128x128] = A[128x768] * W2[768x768] + b2
// grid: (M/128, 768/128)
// ---------------------------------------------------------------------------
__global__ void __launch_bounds__(256, 2)
oproj_gemm(float* __restrict__ out)
{
    __shared__ __align__(16) float As[16][132];
    __shared__ __align__(16) float Bs[16][132];

    const int m0 = blockIdx.x * 128;
    const int n0 = blockIdx.y * 128;
    const int tid = threadIdx.x;
    const int i0 = (tid >> 4) * 8;
    const int j0 = (tid & 15) * 8;

    ull acc[8][4];
    #pragma unroll
    for (int r = 0; r < 8; r++)
        #pragma unroll
        for (int c = 0; c < 4; c++) acc[r][c] = 0ull;

    for (int k0 = 0; k0 < DM; k0 += 16) {
        #pragma unroll
        for (int it = 0; it < 2; it++) {
            int f = tid + it*256;
            int row = f >> 2, kc = (f & 3) << 2;
            float4 v = *(const float4*)(g_A + (size_t)(m0+row)*DM + k0 + kc);
            As[kc+0][row] = v.x; As[kc+1][row] = v.y;
            As[kc+2][row] = v.z; As[kc+3][row] = v.w;
        }
        #pragma unroll
        for (int it = 0; it < 2; it++) {
            int f = tid + it*256;
            int kr = f >> 5, nc = (f & 31) << 2;
            float4 v = *(const float4*)(g_W2 + (size_t)(k0+kr)*DM + n0 + nc);
            *(float4*)&Bs[kr][nc] = v;
        }
        __syncthreads();
        #pragma unroll
        for (int k = 0; k < 16; k++) {
            float4 a0 = *(const float4*)&As[k][i0];
            float4 a1 = *(const float4*)&As[k][i0+4];
            ulonglong2 b0 = *(const ulonglong2*)&Bs[k][j0];
            ulonglong2 b1 = *(const ulonglong2*)&Bs[k][j0+4];
            float av[8] = {a0.x, a0.y, a0.z, a0.w, a1.x, a1.y, a1.z, a1.w};
            #pragma unroll
            for (int r = 0; r < 8; r++) {
                ull ad = dup2(av[r]);
                ffma2(acc[r][0], ad, b0.x);
                ffma2(acc[r][1], ad, b0.y);
                ffma2(acc[r][2], ad, b1.x);
                ffma2(acc[r][3], ad, b1.y);
            }
        }
        __syncthreads();
    }

    #pragma unroll
    for (int r = 0; r < 8; r++) {
        int m = m0 + i0 + r;
        #pragma unroll
        for (int c = 0; c < 4; c++) {
            int col = n0 + j0 + c*2;
            float2 v = unpk(acc[r][c]);
            v.x += g_b2[col];
            v.y += g_b2[col + 1];
            *(float2*)&out[(size_t)m*DM + col] = v;
        }
    }
}

// ---------------------------------------------------------------------------
// Flash attention: per (qtile, b*h). BQ=64, BKV=64, hd=64. Online softmax.
// Q/K stored e-major with 16B-chunk XOR swizzle (conflict-light transposes).
// P overlays the K buffer (48KB static smem exactly). exp2-based softmax:
// Q pre-scaled by log2(e)/sqrt(hd) in qkv_gemm.
// ---------------------------------------------------------------------------
#define SWZ(c, e) (((((c) >> 2) ^ ((e) & 15)) << 2) | ((c) & 3))
#define SWZ4(c4, e) ((((c4) >> 2) ^ ((e) & 15)) << 2)

__global__ void __launch_bounds__(256, 2)
flash_kernel()
{
    __shared__ __align__(16) float Qs[64*64];   // [e][i] swizzled
    __shared__ __align__(16) float KPs[64*64];  // K: [e][j] swizzled;  P: [i][j] plain
    __shared__ __align__(16) float Vs[64*64];   // [j][e] plain

    const int qt = blockIdx.x;
    const int bh = blockIdx.y;
    const float* Qp = g_Q + (size_t)bh*TT*HD;
    const float* Kp = g_K + (size_t)bh*TT*HD;
    const float* Vp = g_V + (size_t)bh*TT*HD;

    const int tid = threadIdx.x;
    const int i0 = (tid >> 4) * 4;   // 4 query rows
    const int j0 = (tid & 15) * 4;   // 4 key cols (also 4 output dims in PV)

    // Load Q tile transposed + swizzled
    #pragma unroll
    for (int it = 0; it < 4; it++) {
        int f = tid + it*256;
        int i = f >> 4, e4 = (f & 15) << 2;
        float4 v = *(const float4*)(Qp + (size_t)(qt*64 + i)*HD + e4);
        Qs[(e4+0)*64 + SWZ(i, e4+0)] = v.x;
        Qs[(e4+1)*64 + SWZ(i, e4+1)] = v.y;
        Qs[(e4+2)*64 + SWZ(i, e4+2)] = v.z;
        Qs[(e4+3)*64 + SWZ(i, e4+3)] = v.w;
    }

    float m_i[4], l_i[4];
    ull o[4][2];
    #pragma unroll
    for (int r = 0; r < 4; r++) {
        m_i[r] = -1e30f; l_i[r] = 0.0f;
        o[r][0] = 0ull; o[r][1] = 0ull;
    }

    for (int kt = 0; kt < TT/64; kt++) {
        __syncthreads();  // previous PV done with KPs(P) and Vs
        const float* Kt = Kp + (size_t)kt*64*HD;
        const float* Vt = Vp + (size_t)kt*64*HD;
        #pragma unroll
        for (int it = 0; it < 4; it++) {
            int f = tid + it*256;
            int j = f >> 4, e4 = (f & 15) << 2;
            float4 kv = *(const float4*)(Kt + (size_t)j*HD + e4);
            KPs[(e4+0)*64 + SWZ(j, e4+0)] = kv.x;
            KPs[(e4+1)*64 + SWZ(j, e4+1)] = kv.y;
            KPs[(e4+2)*64 + SWZ(j, e4+2)] = kv.z;
            KPs[(e4+3)*64 + SWZ(j, e4+3)] = kv.w;
            float4 vv = *(const float4*)(Vt + (size_t)j*HD + e4);
            *(float4*)&Vs[j*64 + e4] = vv;
        }
        __syncthreads();

        // S = Q K^T  (4x4 per thread, f32x2 packed over j)
        ull s[4][2] = {0ull, 0ull, 0ull, 0ull, 0ull, 0ull, 0ull, 0ull};
        #pragma unroll 8
        for (int e = 0; e < 64; e++) {
            float4 a = *(const float4*)&Qs[e*64 + SWZ4(i0, e)];
            ulonglong2 b = *(const ulonglong2*)&KPs[e*64 + SWZ4(j0, e)];
            ull a0 = dup2(a.x), a1 = dup2(a.y), a2 = dup2(a.z), a3 = dup2(a.w);
            ffma2(s[0][0], a0, b.x); ffma2(s[0][1], a0, b.y);
            ffma2(s[1][0], a1, b.x); ffma2(s[1][1], a1, b.y);
            ffma2(s[2][0], a2, b.x); ffma2(s[2][1], a2, b.y);
            ffma2(s[3][0], a3, b.x); ffma2(s[3][1], a3, b.y);
        }

        // Online softmax per row; p staged in regs
        float pv[4][4];
        #pragma unroll
        for (int r = 0; r < 4; r++) {
            float2 sa = unpk(s[r][0]), sb = unpk(s[r][1]);
            float mx = fmaxf(fmaxf(sa.x, sa.y), fmaxf(sb.x, sb.y));
            #pragma unroll
            for (int msk = 8; msk > 0; msk >>= 1)
                mx = fmaxf(mx, __shfl_xor_sync(0xffffffffu, mx, msk));
            float mn = fmaxf(m_i[r], mx);
            float corr = fexp2(m_i[r] - mn);
            float p0 = fexp2(sa.x - mn), p1 = fexp2(sa.y - mn);
            float p2 = fexp2(sb.x - mn), p3 = fexp2(sb.y - mn);
            float rs = (p0 + p1) + (p2 + p3);
            #pragma unroll
            for (int msk = 8; msk > 0; msk >>= 1)
                rs += __shfl_xor_sync(0xffffffffu, rs, msk);
            l_i[r] = l_i[r]*corr + rs;
            m_i[r] = mn;
            ull cd = dup2(corr);
            o[r][0] = mul2(o[r][0], cd);
            o[r][1] = mul2(o[r][1], cd);
            pv[r][0] = p0; pv[r][1] = p1; pv[r][2] = p2; pv[r][3] = p3;
        }
        __syncthreads();  // everyone done reading K before P overwrites it

        #pragma unroll
        for (int r = 0; r < 4; r++)
            *(float4*)&KPs[(i0+r)*64 + j0] = make_float4(pv[r][0], pv[r][1], pv[r][2], pv[r][3]);
        __syncthreads();

        // O += P V  (f32x2 packed over e)
        #pragma unroll 4
        for (int j = 0; j < 64; j += 4) {
            float4 P0 = *(const float4*)&KPs[(i0+0)*64 + j];
            float4 P1 = *(const float4*)&KPs[(i0+1)*64 + j];
            float4 P2 = *(const float4*)&KPs[(i0+2)*64 + j];
            float4 P3 = *(const float4*)&KPs[(i0+3)*64 + j];
            float pr0[4] = {P0.x, P0.y, P0.z, P0.w};
            float pr1[4] = {P1.x, P1.y, P1.z, P1.w};
            float pr2[4] = {P2.x, P2.y, P2.z, P2.w};
            float pr3[4] = {P3.x, P3.y, P3.z, P3.w};
            #pragma unroll
            for (int u = 0; u < 4; u++) {
                ulonglong2 vv = *(const ulonglong2*)&Vs[(j+u)*64 + j0];
                ull d0 = dup2(pr0[u]), d1 = dup2(pr1[u]), d2 = dup2(pr2[u]), d3 = dup2(pr3[u]);
                ffma2(o[0][0], d0, vv.x); ffma2(o[0][1], d0, vv.y);
                ffma2(o[1][0], d1, vv.x); ffma2(o[1][1], d1, vv.y);
                ffma2(o[2][0], d2, vv.x); ffma2(o[2][1], d2, vv.y);
                ffma2(o[3][0], d3, vv.x); ffma2(o[3][1], d3, vv.y);
            }
        }
    }

    // Normalize + write to g_A in [8192][768] layout (col = h*64 + e)
    const int b = bh / NH, h = bh % NH;
    #pragma unroll
    for (int r = 0; r < 4; r++) {
        float inv = 1.0f / l_i[r];
        float2 oa = unpk(o[r][0]), ob = unpk(o[r][1]);
        float4 res = make_float4(oa.x*inv, oa.y*inv, ob.x*inv, ob.y*inv);
        int t = qt*64 + i0 + r;
        *(float4*)&g_A[(size_t)(b*TT + t)*DM + h*HD + j0] = res;
    }
}

// ---------------------------------------------------------------------------
extern "C" void kernel_launch(void* const* d_in, const int* in_sizes, int n_in,
                              void* d_out, int out_size)
{
    const float* X    = (const float*)d_in[0];
    const float* Wq   = (const float*)d_in[1];
    const float* bq   = (const float*)d_in[2];
    const float* Wk   = (const float*)d_in[3];
    const float* bk   = (const float*)d_in[4];
    const float* Wv   = (const float*)d_in[5];
    const float* bv   = (const float*)d_in[6];
    const float* Wo   = (const float*)d_in[7];
    const float* bo   = (const float*)d_in[8];
    const float* gate = (const float*)d_in[9];
    float* out = (float*)d_out;

    prep_w2<<<(NH*HD*DM + 255)/256, 256>>>(Wo, gate);
    prep_b2<<<(DM + 255)/256, 256>>>(bo, gate);
    qkv_gemm<<<dim3(MTOT/128, NH/2, 3), 256>>>(X, Wq, bq, Wk, bk, Wv, bv);
    flash_kernel<<<dim3(TT/64, BB*NH), 256>>>();
    oproj_gemm<<<dim3(MTOT/128, DM/128), 256>>>(out);
}

// round 2
// speedup vs baseline: 1.1104x; 1.1104x over previous
#include <cuda_runtime.h>

#define NH 12
#define TT 2048
#define BB 4
#define DM 768
#define HD 64
#define MTOT (BB*TT)   // 8192

// log2(e) / sqrt(64)
#define QSCALE 0.18033688011112042f

// Scratch (device globals: allocation-free)
__device__ float g_Q[BB*NH*TT*HD];
__device__ float g_K[BB*NH*TT*HD];
__device__ float g_V[BB*NH*TT*HD];
__device__ float g_A[MTOT*DM];      // attention output, [8192][768] row-major, col = h*64+e
__device__ float g_W2[DM*DM];       // gated flattened Wo
__device__ float g_b2[DM];          // gated summed bo

typedef unsigned long long ull;

__device__ __forceinline__ void ffma2(ull& d, ull a, ull b) {
    asm("fma.rn.f32x2 %0, %1, %2, %0;" : "+l"(d) : "l"(a), "l"(b));
}
__device__ __forceinline__ ull mul2(ull a, ull b) {
    ull d; asm("mul.rn.f32x2 %0, %1, %2;" : "=l"(d) : "l"(a), "l"(b)); return d;
}
__device__ __forceinline__ ull add2(ull a, ull b) {
    ull d; asm("add.rn.f32x2 %0, %1, %2;" : "=l"(d) : "l"(a), "l"(b)); return d;
}
__device__ __forceinline__ ull dup2(float x) {
    ull r; asm("mov.b64 %0, {%1, %1};" : "=l"(r) : "f"(x)); return r;
}
__device__ __forceinline__ ull pack2(float a, float b) {
    ull r; asm("mov.b64 %0, {%1, %2};" : "=l"(r) : "f"(a), "f"(b)); return r;
}
__device__ __forceinline__ float2 unpk(ull v) {
    float2 f; asm("mov.b64 {%0, %1}, %2;" : "=f"(f.x), "=f"(f.y) : "l"(v)); return f;
}
__device__ __forceinline__ float fexp2(float x) {
    float y; asm("ex2.approx.ftz.f32 %0, %1;" : "=f"(y) : "f"(x)); return y;
}

// ---------------------------------------------------------------------------
// Prep: fold gate into Wo (flattened [768][768]) and bo (summed over heads)
// ---------------------------------------------------------------------------
__global__ void prep_w2(const float* __restrict__ Wo, const float* __restrict__ gate) {
    int idx = blockIdx.x * 256 + threadIdx.x;
    if (idx >= NH*HD*DM) return;
    int h = idx / (HD*DM);
    float g = gate[h];
    g = (g < 1e-6f) ? 0.0f : g;
    g_W2[idx] = Wo[idx] * g;
}

__global__ void prep_b2(const float* __restrict__ bo, const float* __restrict__ gate) {
    int d = blockIdx.x * 256 + threadIdx.x;
    if (d >= DM) return;
    float s = 0.0f;
    #pragma unroll
    for (int h = 0; h < NH; h++) {
        float g = gate[h];
        g = (g < 1e-6f) ? 0.0f : g;
        s += g * bo[h*DM + d];
    }
    g_b2[d] = s;
}

// ---------------------------------------------------------------------------
// QKV projection GEMM (unchanged: already FMA-bound)
// ---------------------------------------------------------------------------
__global__ void __launch_bounds__(256, 2)
qkv_gemm(const float* __restrict__ X,
         const float* __restrict__ Wq, const float* __restrict__ bq,
         const float* __restrict__ Wk, const float* __restrict__ bk,
         const float* __restrict__ Wv, const float* __restrict__ bv)
{
    __shared__ __align__(16) float As[16][132];
    __shared__ __align__(16) float Bs[16][132];

    const int m0 = blockIdx.x * 128;
    const int h0 = blockIdx.y * 2;
    const int proj = blockIdx.z;

    const float* W; const float* bias; float* obuf;
    if (proj == 0)      { W = Wq; bias = bq; obuf = g_Q; }
    else if (proj == 1) { W = Wk; bias = bk; obuf = g_K; }
    else                { W = Wv; bias = bv; obuf = g_V; }

    const int tid = threadIdx.x;
    const int i0 = (tid >> 4) * 8;
    const int j0 = (tid & 15) * 8;

    ull acc[8][4];
    #pragma unroll
    for (int r = 0; r < 8; r++)
        #pragma unroll
        for (int c = 0; c < 4; c++) acc[r][c] = 0ull;

    for (int k0 = 0; k0 < DM; k0 += 16) {
        #pragma unroll
        for (int it = 0; it < 2; it++) {
            int f = tid + it*256;
            int row = f >> 2, kc = (f & 3) << 2;
            float4 v = *(const float4*)(X + (size_t)(m0+row)*DM + k0 + kc);
            As[kc+0][row] = v.x; As[kc+1][row] = v.y;
            As[kc+2][row] = v.z; As[kc+3][row] = v.w;
        }
        #pragma unroll
        for (int it = 0; it < 2; it++) {
            int f = tid + it*256;
            int kr = f >> 5, nc = (f & 31) << 2;
            int head = h0 + (nc >> 6);
            int e = nc & 63;
            float4 v = *(const float4*)(W + (size_t)head*(DM*HD) + (size_t)(k0+kr)*HD + e);
            *(float4*)&Bs[kr][nc] = v;
        }
        __syncthreads();
        #pragma unroll
        for (int k = 0; k < 16; k++) {
            float4 a0 = *(const float4*)&As[k][i0];
            float4 a1 = *(const float4*)&As[k][i0+4];
            ulonglong2 b0 = *(const ulonglong2*)&Bs[k][j0];
            ulonglong2 b1 = *(const ulonglong2*)&Bs[k][j0+4];
            float av[8] = {a0.x, a0.y, a0.z, a0.w, a1.x, a1.y, a1.z, a1.w};
            #pragma unroll
            for (int r = 0; r < 8; r++) {
                ull ad = dup2(av[r]);
                ffma2(acc[r][0], ad, b0.x);
                ffma2(acc[r][1], ad, b0.y);
                ffma2(acc[r][2], ad, b1.x);
                ffma2(acc[r][3], ad, b1.y);
            }
        }
        __syncthreads();
    }

    #pragma unroll
    for (int r = 0; r < 8; r++) {
        int m = m0 + i0 + r;
        int bidx = m >> 11, t = m & (TT-1);
        #pragma unroll
        for (int c = 0; c < 4; c++) {
            int col = j0 + c*2;
            int head = h0 + (col >> 6);
            int e = col & 63;
            float2 v = unpk(acc[r][c]);
            v.x += bias[head*HD + e];
            v.y += bias[head*HD + e + 1];
            if (proj == 0) { v.x *= QSCALE; v.y *= QSCALE; }
            *(float2*)&obuf[((size_t)(bidx*NH + head)*TT + t)*HD + e] = v;
        }
    }
}

// ---------------------------------------------------------------------------
// Output projection GEMM (unchanged)
// ---------------------------------------------------------------------------
__global__ void __launch_bounds__(256, 2)
oproj_gemm(float* __restrict__ out)
{
    __shared__ __align__(16) float As[16][132];
    __shared__ __align__(16) float Bs[16][132];

    const int m0 = blockIdx.x * 128;
    const int n0 = blockIdx.y * 128;
    const int tid = threadIdx.x;
    const int i0 = (tid >> 4) * 8;
    const int j0 = (tid & 15) * 8;

    ull acc[8][4];
    #pragma unroll
    for (int r = 0; r < 8; r++)
        #pragma unroll
        for (int c = 0; c < 4; c++) acc[r][c] = 0ull;

    for (int k0 = 0; k0 < DM; k0 += 16) {
        #pragma unroll
        for (int it = 0; it < 2; it++) {
            int f = tid + it*256;
            int row = f >> 2, kc = (f & 3) << 2;
            float4 v = *(const float4*)(g_A + (size_t)(m0+row)*DM + k0 + kc);
            As[kc+0][row] = v.x; As[kc+1][row] = v.y;
            As[kc+2][row] = v.z; As[kc+3][row] = v.w;
        }
        #pragma unroll
        for (int it = 0; it < 2; it++) {
            int f = tid + it*256;
            int kr = f >> 5, nc = (f & 31) << 2;
            float4 v = *(const float4*)(g_W2 + (size_t)(k0+kr)*DM + n0 + nc);
            *(float4*)&Bs[kr][nc] = v;
        }
        __syncthreads();
        #pragma unroll
        for (int k = 0; k < 16; k++) {
            float4 a0 = *(const float4*)&As[k][i0];
            float4 a1 = *(const float4*)&As[k][i0+4];
            ulonglong2 b0 = *(const ulonglong2*)&Bs[k][j0];
            ulonglong2 b1 = *(const ulonglong2*)&Bs[k][j0+4];
            float av[8] = {a0.x, a0.y, a0.z, a0.w, a1.x, a1.y, a1.z, a1.w};
            #pragma unroll
            for (int r = 0; r < 8; r++) {
                ull ad = dup2(av[r]);
                ffma2(acc[r][0], ad, b0.x);
                ffma2(acc[r][1], ad, b0.y);
                ffma2(acc[r][2], ad, b1.x);
                ffma2(acc[r][3], ad, b1.y);
            }
        }
        __syncthreads();
    }

    #pragma unroll
    for (int r = 0; r < 8; r++) {
        int m = m0 + i0 + r;
        #pragma unroll
        for (int c = 0; c < 4; c++) {
            int col = n0 + j0 + c*2;
            float2 v = unpk(acc[r][c]);
            v.x += g_b2[col];
            v.y += g_b2[col + 1];
            *(float2*)&out[(size_t)m*DM + col] = v;
        }
    }
}

// ---------------------------------------------------------------------------
// Flash attention v2: BQ=128, BKV=128, 512 threads, 1 block/SM.
// Thread (ig=tid>>5, lane=tid&31): QK rows i0=ig*8 (f32x2-packed pairs),
// cols j0=lane*4. Warp == one row-group => full-row shfl reductions, Q reads
// broadcast. P goes through smem transposed [j][i] with chunk-XOR swizzle
// ((j>>2)&7); PV splits kv dim across half-warps (jh), combined at the end.
// Dynamic smem 160KB: Qs[64][128] | Ks[64][128] | Vs[128][64] | PT[128][128].
// ---------------------------------------------------------------------------
__global__ void __launch_bounds__(512, 1)
flash_kernel()
{
    extern __shared__ __align__(16) float sm[];
    float* Qs = sm;            // [e][i]  64x128
    float* Ks = sm + 8192;     // [e][j]  64x128
    float* Vs = sm + 16384;    // [j][e]  128x64
    float* PT = sm + 24576;    // [j][i]  128x128, chunk-swizzled

    const int qt  = blockIdx.x;   // 16 q-tiles
    const int bh  = blockIdx.y;   // 48
    const int tid = threadIdx.x;
    const int ig   = tid >> 5;        // 0..15 row group
    const int lane = tid & 31;
    const int i0 = ig * 8;
    const int j0 = lane * 4;
    const int jh = lane >> 4;         // PV: kv half
    const int e0 = (lane & 15) * 4;   // PV: 4 output dims

    const float* Qp = g_Q + (size_t)bh*TT*HD;
    const float* Kp = g_K + (size_t)bh*TT*HD;
    const float* Vp = g_V + (size_t)bh*TT*HD;

    // Load Q tile -> Qs[e][i] (transposed scalar scatter, conflict-free)
    {
        int r = tid & 127;
        int ebase = (tid >> 7) * 4;
        const float* qrow = Qp + (size_t)(qt*128 + r)*HD;
        #pragma unroll
        for (int c4 = 0; c4 < 4; c4++) {
            int e = c4*16 + ebase;
            float4 v = *(const float4*)(qrow + e);
            Qs[(e+0)*128 + r] = v.x; Qs[(e+1)*128 + r] = v.y;
            Qs[(e+2)*128 + r] = v.z; Qs[(e+3)*128 + r] = v.w;
        }
    }

    float m_i[8], l_i[8];
    ull o2[4][4];   // [i-pair][e-col]: rows (i0+2ip, i0+2ip+1) at col e0+c
    #pragma unroll
    for (int r = 0; r < 8; r++) { m_i[r] = -1e30f; l_i[r] = 0.0f; }
    #pragma unroll
    for (int ip = 0; ip < 4; ip++)
        #pragma unroll
        for (int c = 0; c < 4; c++) o2[ip][c] = 0ull;

    for (int kt = 0; kt < TT/128; kt++) {
        __syncthreads();   // prior tile done reading Ks/Vs
        // K -> Ks[e][j] (transposed), V -> Vs[j][e] (direct)
        {
            int r = tid & 127;
            int ebase = (tid >> 7) * 4;
            const float* krow = Kp + (size_t)(kt*128 + r)*HD;
            #pragma unroll
            for (int c4 = 0; c4 < 4; c4++) {
                int e = c4*16 + ebase;
                float4 v = *(const float4*)(krow + e);
                Ks[(e+0)*128 + r] = v.x; Ks[(e+1)*128 + r] = v.y;
                Ks[(e+2)*128 + r] = v.z; Ks[(e+3)*128 + r] = v.w;
            }
            const float* vtile = Vp + (size_t)kt*128*HD;
            #pragma unroll
            for (int it = 0; it < 4; it++) {
                int f = tid + it*512;   // float4 index into 128x64
                *(float4*)&Vs[f*4] = *(const float4*)(vtile + f*4);
            }
        }
        __syncthreads();

        // --- QK: s2[ip][c] = f32x2 over row pair ---
        ull s2[4][4];
        #pragma unroll
        for (int ip = 0; ip < 4; ip++)
            #pragma unroll
            for (int c = 0; c < 4; c++) s2[ip][c] = 0ull;

        #pragma unroll 4
        for (int e = 0; e < 64; e++) {
            ulonglong2 qa = *(const ulonglong2*)(Qs + e*128 + i0);
            ulonglong2 qb = *(const ulonglong2*)(Qs + e*128 + i0 + 4);
            float4 kv = *(const float4*)(Ks + e*128 + j0);
            ull k0 = dup2(kv.x), k1 = dup2(kv.y), k2 = dup2(kv.z), k3 = dup2(kv.w);
            ffma2(s2[0][0], qa.x, k0); ffma2(s2[0][1], qa.x, k1);
            ffma2(s2[0][2], qa.x, k2); ffma2(s2[0][3], qa.x, k3);
            ffma2(s2[1][0], qa.y, k0); ffma2(s2[1][1], qa.y, k1);
            ffma2(s2[1][2], qa.y, k2); ffma2(s2[1][3], qa.y, k3);
            ffma2(s2[2][0], qb.x, k0); ffma2(s2[2][1], qb.x, k1);
            ffma2(s2[2][2], qb.x, k2); ffma2(s2[2][3], qb.x, k3);
            ffma2(s2[3][0], qb.y, k0); ffma2(s2[3][1], qb.y, k1);
            ffma2(s2[3][2], qb.y, k2); ffma2(s2[3][3], qb.y, k3);
        }

        // --- online softmax + P^T store ---
        const int swj = lane & 7;   // ((j0+c)>>2)&7 == lane&7 for c<4
        #pragma unroll
        for (int ip = 0; ip < 4; ip++) {
            float2 c0 = unpk(s2[ip][0]), c1 = unpk(s2[ip][1]);
            float2 c2 = unpk(s2[ip][2]), c3 = unpk(s2[ip][3]);
            float mxa = fmaxf(fmaxf(c0.x, c1.x), fmaxf(c2.x, c3.x));
            float mxb = fmaxf(fmaxf(c0.y, c1.y), fmaxf(c2.y, c3.y));
            #pragma unroll
            for (int msk = 16; msk > 0; msk >>= 1) {
                mxa = fmaxf(mxa, __shfl_xor_sync(0xffffffffu, mxa, msk));
                mxb = fmaxf(mxb, __shfl_xor_sync(0xffffffffu, mxb, msk));
            }
            float mna = fmaxf(m_i[2*ip],   mxa);
            float mnb = fmaxf(m_i[2*ip+1], mxb);
            float ca = fexp2(m_i[2*ip]   - mna);
            float cb = fexp2(m_i[2*ip+1] - mnb);
            float pa0 = fexp2(c0.x - mna), pa1 = fexp2(c1.x - mna);
            float pa2 = fexp2(c2.x - mna), pa3 = fexp2(c3.x - mna);
            float pb0 = fexp2(c0.y - mnb), pb1 = fexp2(c1.y - mnb);
            float pb2 = fexp2(c2.y - mnb), pb3 = fexp2(c3.y - mnb);
            float sa = (pa0 + pa1) + (pa2 + pa3);
            float sb = (pb0 + pb1) + (pb2 + pb3);
            #pragma unroll
            for (int msk = 16; msk > 0; msk >>= 1) {
                sa += __shfl_xor_sync(0xffffffffu, sa, msk);
                sb += __shfl_xor_sync(0xffffffffu, sb, msk);
            }
            l_i[2*ip]   = l_i[2*ip]*ca   + sa;
            l_i[2*ip+1] = l_i[2*ip+1]*cb + sb;
            m_i[2*ip] = mna; m_i[2*ip+1] = mnb;
            ull corr2 = pack2(ca, cb);
            o2[ip][0] = mul2(o2[ip][0], corr2);
            o2[ip][1] = mul2(o2[ip][1], corr2);
            o2[ip][2] = mul2(o2[ip][2], corr2);
            o2[ip][3] = mul2(o2[ip][3], corr2);
            // store row pair (i0+2ip, i0+2ip+1) into PT columns j0..j0+3
            int i = i0 + 2*ip;
            int phys = (((i >> 2) ^ swj) << 2) | (i & 3);  // swizzled float idx
            ull pp0 = pack2(pa0, pb0), pp1 = pack2(pa1, pb1);
            ull pp2 = pack2(pa2, pb2), pp3 = pack2(pa3, pb3);
            *(ull*)(PT + (j0+0)*128 + phys) = pp0;
            *(ull*)(PT + (j0+1)*128 + phys) = pp1;
            *(ull*)(PT + (j0+2)*128 + phys) = pp2;
            *(ull*)(PT + (j0+3)*128 + phys) = pp3;
        }
        __syncthreads();

        // --- PV: each half-warp handles 64 of the 128 kv positions ---
        const int c0chunk = (i0 >> 2);   // 2*ig
        #pragma unroll 2
        for (int jj = 0; jj < 64; jj++) {
            int j = jh*64 + jj;
            int sw = (j >> 2) & 7;
            const float* prow = PT + j*128;
            ulonglong2 pA = *(const ulonglong2*)(prow + ((c0chunk     ^ sw) << 2));
            ulonglong2 pB = *(const ulonglong2*)(prow + (((c0chunk+1) ^ sw) << 2));
            float4 vv = *(const float4*)(Vs + j*64 + e0);
            ull v0 = dup2(vv.x), v1 = dup2(vv.y), v2 = dup2(vv.z), v3 = dup2(vv.w);
            ffma2(o2[0][0], pA.x, v0); ffma2(o2[0][1], pA.x, v1);
            ffma2(o2[0][2], pA.x, v2); ffma2(o2[0][3], pA.x, v3);
            ffma2(o2[1][0], pA.y, v0); ffma2(o2[1][1], pA.y, v1);
            ffma2(o2[1][2], pA.y, v2); ffma2(o2[1][3], pA.y, v3);
            ffma2(o2[2][0], pB.x, v0); ffma2(o2[2][1], pB.x, v1);
            ffma2(o2[2][2], pB.x, v2); ffma2(o2[2][3], pB.x, v3);
            ffma2(o2[3][0], pB.y, v0); ffma2(o2[3][1], pB.y, v1);
            ffma2(o2[3][2], pB.y, v2); ffma2(o2[3][3], pB.y, v3);
        }
    }

    // --- combine jh halves via smem scratch, normalize, write g_A ---
    __syncthreads();
    ull* sc = (ull*)sm;   // [64 row-pairs][64 e] of f32x2 -> 32KB (fits in Qs)
    if (jh == 1) {
        #pragma unroll
        for (int ip = 0; ip < 4; ip++)
            #pragma unroll
            for (int c = 0; c < 4; c++)
                sc[(ig*4 + ip)*64 + e0 + c] = o2[ip][c];
    }
    __syncthreads();
    if (jh == 0) {
        const int b = bh / NH, h = bh % NH;
        #pragma unroll
        for (int ip = 0; ip < 4; ip++) {
            float ila = 1.0f / l_i[2*ip];
            float ilb = 1.0f / l_i[2*ip+1];
            ull il2 = pack2(ila, ilb);
            int t0 = qt*128 + i0 + 2*ip;
            float* ra = g_A + ((size_t)(b*TT + t0))*DM + h*HD;
            float* rb = ra + DM;
            #pragma unroll
            for (int c = 0; c < 4; c++) {
                ull tot = add2(o2[ip][c], sc[(ig*4 + ip)*64 + e0 + c]);
                tot = mul2(tot, il2);
                float2 f = unpk(tot);
                ra[e0 + c] = f.x;
                rb[e0 + c] = f.y;
            }
        }
    }
}

// ---------------------------------------------------------------------------
extern "C" void kernel_launch(void* const* d_in, const int* in_sizes, int n_in,
                              void* d_out, int out_size)
{
    const float* X    = (const float*)d_in[0];
    const float* Wq   = (const float*)d_in[1];
    const float* bq   = (const float*)d_in[2];
    const float* Wk   = (const float*)d_in[3];
    const float* bk   = (const float*)d_in[4];
    const float* Wv   = (const float*)d_in[5];
    const float* bv   = (const float*)d_in[6];
    const float* Wo   = (const float*)d_in[7];
    const float* bo   = (const float*)d_in[8];
    const float* gate = (const float*)d_in[9];
    float* out = (float*)d_out;

    static int smem_set = 0;
    if (!smem_set) {
        cudaFuncSetAttribute(flash_kernel,
                             cudaFuncAttributeMaxDynamicSharedMemorySize,
                             163840);
        smem_set = 1;
    }

    prep_w2<<<(NH*HD*DM + 255)/256, 256>>>(Wo, gate);
    prep_b2<<<(DM + 255)/256, 256>>>(bo, gate);
    qkv_gemm<<<dim3(MTOT/128, NH/2, 3), 256>>>(X, Wq, bq, Wk, bk, Wv, bv);
    flash_kernel<<<dim3(TT/128, BB*NH), 512, 163840>>>();
    oproj_gemm<<<dim3(MTOT/128, DM/128), 256>>>(out);
}

// round 3
// speedup vs baseline: 1.1115x; 1.0009x over previous
#include <cuda_runtime.h>

#define NH 12
#define TT 2048
#define BB 4
#define DM 768
#define HD 64
#define MTOT (BB*TT)   // 8192

// log2(e) / sqrt(64)
#define QSCALE 0.18033688011112042f

// Scratch (device globals: allocation-free)
__device__ float g_Q[BB*NH*TT*HD];
__device__ float g_K[BB*NH*TT*HD];
__device__ float g_V[BB*NH*TT*HD];
__device__ float g_A[MTOT*DM];      // attention output, [8192][768] row-major, col = h*64+e
__device__ float g_W2[DM*DM];       // gated flattened Wo
__device__ float g_b2[DM];          // gated summed bo

typedef unsigned long long ull;

__device__ __forceinline__ void ffma2(ull& d, ull a, ull b) {
    asm("fma.rn.f32x2 %0, %1, %2, %0;" : "+l"(d) : "l"(a), "l"(b));
}
__device__ __forceinline__ ull mul2(ull a, ull b) {
    ull d; asm("mul.rn.f32x2 %0, %1, %2;" : "=l"(d) : "l"(a), "l"(b)); return d;
}
__device__ __forceinline__ ull add2(ull a, ull b) {
    ull d; asm("add.rn.f32x2 %0, %1, %2;" : "=l"(d) : "l"(a), "l"(b)); return d;
}
__device__ __forceinline__ ull dup2(float x) {
    ull r; asm("mov.b64 %0, {%1, %1};" : "=l"(r) : "f"(x)); return r;
}
__device__ __forceinline__ ull pack2(float a, float b) {
    ull r; asm("mov.b64 %0, {%1, %2};" : "=l"(r) : "f"(a), "f"(b)); return r;
}
__device__ __forceinline__ float2 unpk(ull v) {
    float2 f; asm("mov.b64 {%0, %1}, %2;" : "=f"(f.x), "=f"(f.y) : "l"(v)); return f;
}
__device__ __forceinline__ float fexp2(float x) {
    float y; asm("ex2.approx.ftz.f32 %0, %1;" : "=f"(y) : "f"(x)); return y;
}

// ---------------------------------------------------------------------------
// Prep: fold gate into Wo (flattened [768][768]) and bo (summed over heads)
// ---------------------------------------------------------------------------
__global__ void prep_w2(const float* __restrict__ Wo, const float* __restrict__ gate) {
    int idx = blockIdx.x * 256 + threadIdx.x;
    if (idx >= NH*HD*DM) return;
    int h = idx / (HD*DM);
    float g = gate[h];
    g = (g < 1e-6f) ? 0.0f : g;
    g_W2[idx] = Wo[idx] * g;
}

__global__ void prep_b2(const float* __restrict__ bo, const float* __restrict__ gate) {
    int d = blockIdx.x * 256 + threadIdx.x;
    if (d >= DM) return;
    float s = 0.0f;
    #pragma unroll
    for (int h = 0; h < NH; h++) {
        float g = gate[h];
        g = (g < 1e-6f) ? 0.0f : g;
        s += g * bo[h*DM + d];
    }
    g_b2[d] = s;
}

// ---------------------------------------------------------------------------
// QKV projection GEMM (unchanged: already FMA-bound)
// ---------------------------------------------------------------------------
__global__ void __launch_bounds__(256, 2)
qkv_gemm(const float* __restrict__ X,
         const float* __restrict__ Wq, const float* __restrict__ bq,
         const float* __restrict__ Wk, const float* __restrict__ bk,
         const float* __restrict__ Wv, const float* __restrict__ bv)
{
    __shared__ __align__(16) float As[16][132];
    __shared__ __align__(16) float Bs[16][132];

    const int m0 = blockIdx.x * 128;
    const int h0 = blockIdx.y * 2;
    const int proj = blockIdx.z;

    const float* W; const float* bias; float* obuf;
    if (proj == 0)      { W = Wq; bias = bq; obuf = g_Q; }
    else if (proj == 1) { W = Wk; bias = bk; obuf = g_K; }
    else                { W = Wv; bias = bv; obuf = g_V; }

    const int tid = threadIdx.x;
    const int i0 = (tid >> 4) * 8;
    const int j0 = (tid & 15) * 8;

    ull acc[8][4];
    #pragma unroll
    for (int r = 0; r < 8; r++)
        #pragma unroll
        for (int c = 0; c < 4; c++) acc[r][c] = 0ull;

    for (int k0 = 0; k0 < DM; k0 += 16) {
        #pragma unroll
        for (int it = 0; it < 2; it++) {
            int f = tid + it*256;
            int row = f >> 2, kc = (f & 3) << 2;
            float4 v = *(const float4*)(X + (size_t)(m0+row)*DM + k0 + kc);
            As[kc+0][row] = v.x; As[kc+1][row] = v.y;
            As[kc+2][row] = v.z; As[kc+3][row] = v.w;
        }
        #pragma unroll
        for (int it = 0; it < 2; it++) {
            int f = tid + it*256;
            int kr = f >> 5, nc = (f & 31) << 2;
            int head = h0 + (nc >> 6);
            int e = nc & 63;
            float4 v = *(const float4*)(W + (size_t)head*(DM*HD) + (size_t)(k0+kr)*HD + e);
            *(float4*)&Bs[kr][nc] = v;
        }
        __syncthreads();
        #pragma unroll
        for (int k = 0; k < 16; k++) {
            float4 a0 = *(const float4*)&As[k][i0];
            float4 a1 = *(const float4*)&As[k][i0+4];
            ulonglong2 b0 = *(const ulonglong2*)&Bs[k][j0];
            ulonglong2 b1 = *(const ulonglong2*)&Bs[k][j0+4];
            float av[8] = {a0.x, a0.y, a0.z, a0.w, a1.x, a1.y, a1.z, a1.w};
            #pragma unroll
            for (int r = 0; r < 8; r++) {
                ull ad = dup2(av[r]);
                ffma2(acc[r][0], ad, b0.x);
                ffma2(acc[r][1], ad, b0.y);
                ffma2(acc[r][2], ad, b1.x);
                ffma2(acc[r][3], ad, b1.y);
            }
        }
        __syncthreads();
    }

    #pragma unroll
    for (int r = 0; r < 8; r++) {
        int m = m0 + i0 + r;
        int bidx = m >> 11, t = m & (TT-1);
        #pragma unroll
        for (int c = 0; c < 4; c++) {
            int col = j0 + c*2;
            int head = h0 + (col >> 6);
            int e = col & 63;
            float2 v = unpk(acc[r][c]);
            v.x += bias[head*HD + e];
            v.y += bias[head*HD + e + 1];
            if (proj == 0) { v.x *= QSCALE; v.y *= QSCALE; }
            *(float2*)&obuf[((size_t)(bidx*NH + head)*TT + t)*HD + e] = v;
        }
    }
}

// ---------------------------------------------------------------------------
// Output projection GEMM (unchanged)
// ---------------------------------------------------------------------------
__global__ void __launch_bounds__(256, 2)
oproj_gemm(float* __restrict__ out)
{
    __shared__ __align__(16) float As[16][132];
    __shared__ __align__(16) float Bs[16][132];

    const int m0 = blockIdx.x * 128;
    const int n0 = blockIdx.y * 128;
    const int tid = threadIdx.x;
    const int i0 = (tid >> 4) * 8;
    const int j0 = (tid & 15) * 8;

    ull acc[8][4];
    #pragma unroll
    for (int r = 0; r < 8; r++)
        #pragma unroll
        for (int c = 0; c < 4; c++) acc[r][c] = 0ull;

    for (int k0 = 0; k0 < DM; k0 += 16) {
        #pragma unroll
        for (int it = 0; it < 2; it++) {
            int f = tid + it*256;
            int row = f >> 2, kc = (f & 3) << 2;
            float4 v = *(const float4*)(g_A + (size_t)(m0+row)*DM + k0 + kc);
            As[kc+0][row] = v.x; As[kc+1][row] = v.y;
            As[kc+2][row] = v.z; As[kc+3][row] = v.w;
        }
        #pragma unroll
        for (int it = 0; it < 2; it++) {
            int f = tid + it*256;
            int kr = f >> 5, nc = (f & 31) << 2;
            float4 v = *(const float4*)(g_W2 + (size_t)(k0+kr)*DM + n0 + nc);
            *(float4*)&Bs[kr][nc] = v;
        }
        __syncthreads();
        #pragma unroll
        for (int k = 0; k < 16; k++) {
            float4 a0 = *(const float4*)&As[k][i0];
            float4 a1 = *(const float4*)&As[k][i0+4];
            ulonglong2 b0 = *(const ulonglong2*)&Bs[k][j0];
            ulonglong2 b1 = *(const ulonglong2*)&Bs[k][j0+4];
            float av[8] = {a0.x, a0.y, a0.z, a0.w, a1.x, a1.y, a1.z, a1.w};
            #pragma unroll
            for (int r = 0; r < 8; r++) {
                ull ad = dup2(av[r]);
                ffma2(acc[r][0], ad, b0.x);
                ffma2(acc[r][1], ad, b0.y);
                ffma2(acc[r][2], ad, b1.x);
                ffma2(acc[r][3], ad, b1.y);
            }
        }
        __syncthreads();
    }

    #pragma unroll
    for (int r = 0; r < 8; r++) {
        int m = m0 + i0 + r;
        #pragma unroll
        for (int c = 0; c < 4; c++) {
            int col = n0 + j0 + c*2;
            float2 v = unpk(acc[r][c]);
            v.x += g_b2[col];
            v.y += g_b2[col + 1];
            *(float2*)&out[(size_t)m*DM + col] = v;
        }
    }
}

// ---------------------------------------------------------------------------
// Flash attention v2: BQ=128, BKV=128, 512 threads, 1 block/SM.
// Thread (ig=tid>>5, lane=tid&31): QK rows i0=ig*8 (f32x2-packed pairs),
// cols j0=lane*4. Warp == one row-group => full-row shfl reductions, Q reads
// broadcast. P goes through smem transposed [j][i] with chunk-XOR swizzle
// ((j>>2)&7); PV splits kv dim across half-warps (jh), combined at the end.
// Dynamic smem 160KB: Qs[64][128] | Ks[64][128] | Vs[128][64] | PT[128][128].
// ---------------------------------------------------------------------------
__global__ void __launch_bounds__(512, 1)
flash_kernel()
{
    extern __shared__ __align__(16) float sm[];
    float* Qs = sm;            // [e][i]  64x128
    float* Ks = sm + 8192;     // [e][j]  64x128
    float* Vs = sm + 16384;    // [j][e]  128x64
    float* PT = sm + 24576;    // [j][i]  128x128, chunk-swizzled

    const int qt  = blockIdx.x;   // 16 q-tiles
    const int bh  = blockIdx.y;   // 48
    const int tid = threadIdx.x;
    const int ig   = tid >> 5;        // 0..15 row group
    const int lane = tid & 31;
    const int i0 = ig * 8;
    const int j0 = lane * 4;
    const int jh = lane >> 4;         // PV: kv half
    const int e0 = (lane & 15) * 4;   // PV: 4 output dims

    const float* Qp = g_Q + (size_t)bh*TT*HD;
    const float* Kp = g_K + (size_t)bh*TT*HD;
    const float* Vp = g_V + (size_t)bh*TT*HD;

    // Load Q tile -> Qs[e][i] (transposed scalar scatter, conflict-free)
    {
        int r = tid & 127;
        int ebase = (tid >> 7) * 4;
        const float* qrow = Qp + (size_t)(qt*128 + r)*HD;
        #pragma unroll
        for (int c4 = 0; c4 < 4; c4++) {
            int e = c4*16 + ebase;
            float4 v = *(const float4*)(qrow + e);
            Qs[(e+0)*128 + r] = v.x; Qs[(e+1)*128 + r] = v.y;
            Qs[(e+2)*128 + r] = v.z; Qs[(e+3)*128 + r] = v.w;
        }
    }

    float m_i[8], l_i[8];
    ull o2[4][4];   // [i-pair][e-col]: rows (i0+2ip, i0+2ip+1) at col e0+c
    #pragma unroll
    for (int r = 0; r < 8; r++) { m_i[r] = -1e30f; l_i[r] = 0.0f; }
    #pragma unroll
    for (int ip = 0; ip < 4; ip++)
        #pragma unroll
        for (int c = 0; c < 4; c++) o2[ip][c] = 0ull;

    for (int kt = 0; kt < TT/128; kt++) {
        __syncthreads();   // prior tile done reading Ks/Vs
        // K -> Ks[e][j] (transposed), V -> Vs[j][e] (direct)
        {
            int r = tid & 127;
            int ebase = (tid >> 7) * 4;
            const float* krow = Kp + (size_t)(kt*128 + r)*HD;
            #pragma unroll
            for (int c4 = 0; c4 < 4; c4++) {
                int e = c4*16 + ebase;
                float4 v = *(const float4*)(krow + e);
                Ks[(e+0)*128 + r] = v.x; Ks[(e+1)*128 + r] = v.y;
                Ks[(e+2)*128 + r] = v.z; Ks[(e+3)*128 + r] = v.w;
            }
            const float* vtile = Vp + (size_t)kt*128*HD;
            #pragma unroll
            for (int it = 0; it < 4; it++) {
                int f = tid + it*512;   // float4 index into 128x64
                *(float4*)&Vs[f*4] = *(const float4*)(vtile + f*4);
            }
        }
        __syncthreads();

        // --- QK: s2[ip][c] = f32x2 over row pair ---
        ull s2[4][4];
        #pragma unroll
        for (int ip = 0; ip < 4; ip++)
            #pragma unroll
            for (int c = 0; c < 4; c++) s2[ip][c] = 0ull;

        #pragma unroll 4
        for (int e = 0; e < 64; e++) {
            ulonglong2 qa = *(const ulonglong2*)(Qs + e*128 + i0);
            ulonglong2 qb = *(const ulonglong2*)(Qs + e*128 + i0 + 4);
            float4 kv = *(const float4*)(Ks + e*128 + j0);
            ull k0 = dup2(kv.x), k1 = dup2(kv.y), k2 = dup2(kv.z), k3 = dup2(kv.w);
            ffma2(s2[0][0], qa.x, k0); ffma2(s2[0][1], qa.x, k1);
            ffma2(s2[0][2], qa.x, k2); ffma2(s2[0][3], qa.x, k3);
            ffma2(s2[1][0], qa.y, k0); ffma2(s2[1][1], qa.y, k1);
            ffma2(s2[1][2], qa.y, k2); ffma2(s2[1][3], qa.y, k3);
            ffma2(s2[2][0], qb.x, k0); ffma2(s2[2][1], qb.x, k1);
            ffma2(s2[2][2], qb.x, k2); ffma2(s2[2][3], qb.x, k3);
            ffma2(s2[3][0], qb.y, k0); ffma2(s2[3][1], qb.y, k1);
            ffma2(s2[3][2], qb.y, k2); ffma2(s2[3][3], qb.y, k3);
        }

        // --- online softmax + P^T store ---
        const int swj = lane & 7;   // ((j0+c)>>2)&7 == lane&7 for c<4
        #pragma unroll
        for (int ip = 0; ip < 4; ip++) {
            float2 c0 = unpk(s2[ip][0]), c1 = unpk(s2[ip][1]);
            float2 c2 = unpk(s2[ip][2]), c3 = unpk(s2[ip][3]);
            float mxa = fmaxf(fmaxf(c0.x, c1.x), fmaxf(c2.x, c3.x));
            float mxb = fmaxf(fmaxf(c0.y, c1.y), fmaxf(c2.y, c3.y));
            #pragma unroll
            for (int msk = 16; msk > 0; msk >>= 1) {
                mxa = fmaxf(mxa, __shfl_xor_sync(0xffffffffu, mxa, msk));
                mxb = fmaxf(mxb, __shfl_xor_sync(0xffffffffu, mxb, msk));
            }
            float mna = fmaxf(m_i[2*ip],   mxa);
            float mnb = fmaxf(m_i[2*ip+1], mxb);
            float ca = fexp2(m_i[2*ip]   - mna);
            float cb = fexp2(m_i[2*ip+1] - mnb);
            float pa0 = fexp2(c0.x - mna), pa1 = fexp2(c1.x - mna);
            float pa2 = fexp2(c2.x - mna), pa3 = fexp2(c3.x - mna);
            float pb0 = fexp2(c0.y - mnb), pb1 = fexp2(c1.y - mnb);
            float pb2 = fexp2(c2.y - mnb), pb3 = fexp2(c3.y - mnb);
            float sa = (pa0 + pa1) + (pa2 + pa3);
            float sb = (pb0 + pb1) + (pb2 + pb3);
            #pragma unroll
            for (int msk = 16; msk > 0; msk >>= 1) {
                sa += __shfl_xor_sync(0xffffffffu, sa, msk);
                sb += __shfl_xor_sync(0xffffffffu, sb, msk);
            }
            l_i[2*ip]   = l_i[2*ip]*ca   + sa;
            l_i[2*ip+1] = l_i[2*ip+1]*cb + sb;
            m_i[2*ip] = mna; m_i[2*ip+1] = mnb;
            ull corr2 = pack2(ca, cb);
            o2[ip][0] = mul2(o2[ip][0], corr2);
            o2[ip][1] = mul2(o2[ip][1], corr2);
            o2[ip][2] = mul2(o2[ip][2], corr2);
            o2[ip][3] = mul2(o2[ip][3], corr2);
            // store row pair (i0+2ip, i0+2ip+1) into PT columns j0..j0+3
            int i = i0 + 2*ip;
            int phys = (((i >> 2) ^ swj) << 2) | (i & 3);  // swizzled float idx
            ull pp0 = pack2(pa0, pb0), pp1 = pack2(pa1, pb1);
            ull pp2 = pack2(pa2, pb2), pp3 = pack2(pa3, pb3);
            *(ull*)(PT + (j0+0)*128 + phys) = pp0;
            *(ull*)(PT + (j0+1)*128 + phys) = pp1;
            *(ull*)(PT + (j0+2)*128 + phys) = pp2;
            *(ull*)(PT + (j0+3)*128 + phys) = pp3;
        }
        __syncthreads();

        // --- PV: each half-warp handles 64 of the 128 kv positions ---
        const int c0chunk = (i0 >> 2);   // 2*ig
        #pragma unroll 2
        for (int jj = 0; jj < 64; jj++) {
            int j = jh*64 + jj;
            int sw = (j >> 2) & 7;
            const float* prow = PT + j*128;
            ulonglong2 pA = *(const ulonglong2*)(prow + ((c0chunk     ^ sw) << 2));
            ulonglong2 pB = *(const ulonglong2*)(prow + (((c0chunk+1) ^ sw) << 2));
            float4 vv = *(const float4*)(Vs + j*64 + e0);
            ull v0 = dup2(vv.x), v1 = dup2(vv.y), v2 = dup2(vv.z), v3 = dup2(vv.w);
            ffma2(o2[0][0], pA.x, v0); ffma2(o2[0][1], pA.x, v1);
            ffma2(o2[0][2], pA.x, v2); ffma2(o2[0][3], pA.x, v3);
            ffma2(o2[1][0], pA.y, v0); ffma2(o2[1][1], pA.y, v1);
            ffma2(o2[1][2], pA.y, v2); ffma2(o2[1][3], pA.y, v3);
            ffma2(o2[2][0], pB.x, v0); ffma2(o2[2][1], pB.x, v1);
            ffma2(o2[2][2], pB.x, v2); ffma2(o2[2][3], pB.x, v3);
            ffma2(o2[3][0], pB.y, v0); ffma2(o2[3][1], pB.y, v1);
            ffma2(o2[3][2], pB.y, v2); ffma2(o2[3][3], pB.y, v3);
        }
    }

    // --- combine jh halves via smem scratch, normalize, write g_A ---
    __syncthreads();
    ull* sc = (ull*)sm;   // [64 row-pairs][64 e] of f32x2 -> 32KB (fits in Qs)
    if (jh == 1) {
        #pragma unroll
        for (int ip = 0; ip < 4; ip++)
            #pragma unroll
            for (int c = 0; c < 4; c++)
                sc[(ig*4 + ip)*64 + e0 + c] = o2[ip][c];
    }
    __syncthreads();
    if (jh == 0) {
        const int b = bh / NH, h = bh % NH;
        #pragma unroll
        for (int ip = 0; ip < 4; ip++) {
            float ila = 1.0f / l_i[2*ip];
            float ilb = 1.0f / l_i[2*ip+1];
            ull il2 = pack2(ila, ilb);
            int t0 = qt*128 + i0 + 2*ip;
            float* ra = g_A + ((size_t)(b*TT + t0))*DM + h*HD;
            float* rb = ra + DM;
            #pragma unroll
            for (int c = 0; c < 4; c++) {
                ull tot = add2(o2[ip][c], sc[(ig*4 + ip)*64 + e0 + c]);
                tot = mul2(tot, il2);
                float2 f = unpk(tot);
                ra[e0 + c] = f.x;
                rb[e0 + c] = f.y;
            }
        }
    }
}

// ---------------------------------------------------------------------------
extern "C" void kernel_launch(void* const* d_in, const int* in_sizes, int n_in,
                              void* d_out, int out_size)
{
    const float* X    = (const float*)d_in[0];
    const float* Wq   = (const float*)d_in[1];
    const float* bq   = (const float*)d_in[2];
    const float* Wk   = (const float*)d_in[3];
    const float* bk   = (const float*)d_in[4];
    const float* Wv   = (const float*)d_in[5];
    const float* bv   = (const float*)d_in[6];
    const float* Wo   = (const float*)d_in[7];
    const float* bo   = (const float*)d_in[8];
    const float* gate = (const float*)d_in[9];
    float* out = (float*)d_out;

    static int smem_set = 0;
    if (!smem_set) {
        cudaFuncSetAttribute(flash_kernel,
                             cudaFuncAttributeMaxDynamicSharedMemorySize,
                             163840);
        smem_set = 1;
    }

    prep_w2<<<(NH*HD*DM + 255)/256, 256>>>(Wo, gate);
    prep_b2<<<(DM + 255)/256, 256>>>(bo, gate);
    qkv_gemm<<<dim3(MTOT/128, NH/2, 3), 256>>>(X, Wq, bq, Wk, bk, Wv, bv);
    flash_kernel<<<dim3(TT/128, BB*NH), 512, 163840>>>();
    oproj_gemm<<<dim3(MTOT/128, DM/128), 256>>>(out);
}

// round 5
// speedup vs baseline: 2.4010x; 2.1602x over previous
#include <cuda_runtime.h>
#include <cuda_fp16.h>
#include <cstdint>

#define NH 12
#define TT 2048
#define BB 4
#define DM 768
#define HD 64
#define MTOT (BB*TT)
#define NBH (BB*NH)
#define QSCALE 0.18033688011112042f   // log2(e)/sqrt(64)

// ---------------- global scratch (allocation-free) ----------------
__device__ __half g_W3h[NH*192*DM], g_W3l[NH*192*DM];   // [h][n=q|k|v*64+e][k]
__device__ __half g_W2Th[DM*DM],    g_W2Tl[DM*DM];      // [n][k], gate folded
__device__ float  g_b2[DM];
__device__ __half g_Qh[NBH*TT*HD], g_Ql[NBH*TT*HD];     // [bh][t][e] (scale folded)
__device__ __half g_Kh[NBH*TT*HD], g_Kl[NBH*TT*HD];     // [bh][t][e]
__device__ __half g_VTh[NBH*HD*TT], g_VTl[NBH*HD*TT];   // [bh][e][t]
__device__ float  g_A[MTOT*DM];                          // attn out [8192][768]

// ---------------- helpers ----------------
__device__ __forceinline__ uint32_t smem_u32(const void* p) {
    uint32_t a;
    asm("{ .reg .u64 t; cvta.to.shared.u64 t, %1; cvt.u32.u64 %0, t; }" : "=r"(a) : "l"(p));
    return a;
}
__device__ __forceinline__ float fexp2(float x) {
    float y; asm("ex2.approx.ftz.f32 %0, %1;" : "=f"(y) : "f"(x)); return y;
}
__device__ __forceinline__ void fsplit(float x, __half& h, __half& l) {
    h = __float2half_rn(x);
    l = __float2half_rn(x - __half2float(h));
}
__device__ __forceinline__ void ldsm4(uint32_t* r, uint32_t addr) {
    asm volatile("ldmatrix.sync.aligned.m8n8.x4.shared.b16 {%0,%1,%2,%3}, [%4];"
        : "=r"(r[0]), "=r"(r[1]), "=r"(r[2]), "=r"(r[3]) : "r"(addr));
}
__device__ __forceinline__ void ldsm2(uint32_t* r, uint32_t addr) {
    asm volatile("ldmatrix.sync.aligned.m8n8.x2.shared.b16 {%0,%1}, [%2];"
        : "=r"(r[0]), "=r"(r[1]) : "r"(addr));
}
__device__ __forceinline__ void mma16816(float* d, const uint32_t* a, const uint32_t* b) {
    asm volatile("mma.sync.aligned.m16n8k16.row.col.f32.f16.f16.f32 "
        "{%0,%1,%2,%3}, {%4,%5,%6,%7}, {%8,%9}, {%0,%1,%2,%3};"
        : "+f"(d[0]), "+f"(d[1]), "+f"(d[2]), "+f"(d[3])
        : "r"(a[0]), "r"(a[1]), "r"(a[2]), "r"(a[3]), "r"(b[0]), "r"(b[1]));
}
// A fragment (16x16) from row-major [m][k], pitch in halves
__device__ __forceinline__ void lda_frag(uint32_t* r, uint32_t sbase, int m0, int k0,
                                         int pitch, int lane) {
    uint32_t addr = sbase + (uint32_t)(((m0 + (lane & 7) + ((lane >> 3) & 1) * 8) * pitch
                                       + k0 + ((lane >> 4) & 1) * 8) * 2);
    ldsm4(r, addr);
}
// B fragment (16k x 8n) from row-major [n][k]
__device__ __forceinline__ void ldb_frag(uint32_t* r, uint32_t sbase, int n0, int k0,
                                         int pitch, int lane) {
    uint32_t addr = sbase + (uint32_t)(((n0 + (lane & 7)) * pitch
                                       + k0 + ((lane >> 3) & 1) * 8) * 2);
    ldsm2(r, addr);
}

// ---------------- prep ----------------
__global__ void prep_w3(const float* __restrict__ Wq, const float* __restrict__ Wk,
                        const float* __restrict__ Wv) {
    int idx = blockIdx.x * 256 + threadIdx.x;
    if (idx >= NH*192*DM) return;
    int k = idx % DM;
    int n = (idx / DM) % 192;
    int h = idx / (192*DM);
    int part = n >> 6, e = n & 63;
    const float* W = (part == 0) ? Wq : (part == 1) ? Wk : Wv;
    float v = W[((size_t)h*DM + k)*HD + e];
    if (part == 0) v *= QSCALE;
    __half hh, hl; fsplit(v, hh, hl);
    g_W3h[idx] = hh; g_W3l[idx] = hl;
}
__global__ void prep_w2(const float* __restrict__ Wo, const float* __restrict__ gate) {
    int idx = blockIdx.x * 256 + threadIdx.x;
    if (idx >= DM*DM) return;
    int k = idx % DM, n = idx / DM;
    int h = k >> 6, e = k & 63;
    float g = gate[h]; g = (g < 1e-6f) ? 0.0f : g;
    float v = Wo[((size_t)h*HD + e)*DM + n] * g;
    __half hh, hl; fsplit(v, hh, hl);
    g_W2Th[idx] = hh; g_W2Tl[idx] = hl;
}
__global__ void prep_b2(const float* __restrict__ bo, const float* __restrict__ gate) {
    int d = blockIdx.x * 256 + threadIdx.x;
    if (d >= DM) return;
    float s = 0.0f;
    #pragma unroll
    for (int h = 0; h < NH; h++) {
        float g = gate[h]; g = (g < 1e-6f) ? 0.0f : g;
        s += g * bo[h*DM + d];
    }
    g_b2[d] = s;
}

// ---------------- QKV projection: block 128m x 192n, K=768, BK=32 ----------------
// smem: Ah[128][40] @0, Al @10240, Bh[192][40] @20480, Bl @35840  (51200 B)
#define G_SMEM 51200

__global__ void __launch_bounds__(256)
qkv_mma(const float* __restrict__ X, const float* __restrict__ bq,
        const float* __restrict__ bk, const float* __restrict__ bv)
{
    extern __shared__ __align__(16) char smc[];
    const uint32_t sb = smem_u32(smc);
    const uint32_t sAh = sb, sAl = sb + 10240, sBh = sb + 20480, sBl = sb + 35840;
    __half* pAh = (__half*)smc;           __half* pAl = (__half*)(smc + 10240);
    __half* pBh = (__half*)(smc + 20480); __half* pBl = (__half*)(smc + 35840);

    const int m0 = blockIdx.x * 128, h = blockIdx.y;
    const int tid = threadIdx.x, lane = tid & 31, w = tid >> 5;
    const int WM = (w >> 2) * 64, WN = (w & 3) * 48;

    const __half* W3h = g_W3h + (size_t)h*192*DM;
    const __half* W3l = g_W3l + (size_t)h*192*DM;

    float acc[4][6][4];
    #pragma unroll
    for (int mt = 0; mt < 4; mt++)
        #pragma unroll
        for (int nt = 0; nt < 6; nt++)
            #pragma unroll
            for (int c = 0; c < 4; c++) acc[mt][nt][c] = 0.0f;

    #pragma unroll 1
    for (int ch = 0; ch < 24; ch++) {
        int k0 = ch * 32;
        #pragma unroll
        for (int i = 0; i < 4; i++) {
            int f = tid + i*256, r = f >> 3, c4 = (f & 7) * 4;
            float4 v = *(const float4*)(X + (size_t)(m0 + r)*DM + k0 + c4);
            __half h0,l0,h1,l1,h2,l2,h3,l3;
            fsplit(v.x,h0,l0); fsplit(v.y,h1,l1); fsplit(v.z,h2,l2); fsplit(v.w,h3,l3);
            *(__half2*)(pAh + r*40 + c4)     = __halves2half2(h0, h1);
            *(__half2*)(pAh + r*40 + c4 + 2) = __halves2half2(h2, h3);
            *(__half2*)(pAl + r*40 + c4)     = __halves2half2(l0, l1);
            *(__half2*)(pAl + r*40 + c4 + 2) = __halves2half2(l2, l3);
        }
        #pragma unroll
        for (int i = 0; i < 3; i++) {
            int f = tid + i*256, r = f >> 2, c8 = (f & 3) * 8;
            *(uint4*)(pBh + r*40 + c8) = *(const uint4*)(W3h + (size_t)r*DM + k0 + c8);
            *(uint4*)(pBl + r*40 + c8) = *(const uint4*)(W3l + (size_t)r*DM + k0 + c8);
        }
        __syncthreads();
        #pragma unroll
        for (int ks = 0; ks < 2; ks++) {
            int kk = ks * 16;
            uint32_t ah[4][4], al[4][4], bhf[6][2], blf[6][2];
            #pragma unroll
            for (int mt = 0; mt < 4; mt++) {
                lda_frag(ah[mt], sAh, WM + mt*16, kk, 40, lane);
                lda_frag(al[mt], sAl, WM + mt*16, kk, 40, lane);
            }
            #pragma unroll
            for (int nt = 0; nt < 6; nt++) {
                ldb_frag(bhf[nt], sBh, WN + nt*8, kk, 40, lane);
                ldb_frag(blf[nt], sBl, WN + nt*8, kk, 40, lane);
            }
            #pragma unroll
            for (int mt = 0; mt < 4; mt++)
                #pragma unroll
                for (int nt = 0; nt < 6; nt++) {
                    mma16816(acc[mt][nt], ah[mt], bhf[nt]);
                    mma16816(acc[mt][nt], al[mt], bhf[nt]);
                    mma16816(acc[mt][nt], ah[mt], blf[nt]);
                }
        }
        __syncthreads();
    }

    // epilogue: bias + split-write Q,K (token-major) and V (transposed)
    #pragma unroll
    for (int mt = 0; mt < 4; mt++)
        #pragma unroll
        for (int rh = 0; rh < 2; rh++) {
            int m = m0 + WM + mt*16 + (lane >> 2) + rh*8;
            int b = m >> 11, t = m & (TT-1);
            int bhi = b*NH + h;
            #pragma unroll
            for (int nt = 0; nt < 6; nt++) {
                int col = WN + nt*8 + (lane & 3)*2;
                int part = col >> 6, e = col & 63;
                float v0 = acc[mt][nt][rh*2 + 0];
                float v1 = acc[mt][nt][rh*2 + 1];
                if (part == 0)      { v0 += bq[h*HD+e]*QSCALE; v1 += bq[h*HD+e+1]*QSCALE; }
                else if (part == 1) { v0 += bk[h*HD+e];        v1 += bk[h*HD+e+1]; }
                else                { v0 += bv[h*HD+e];        v1 += bv[h*HD+e+1]; }
                __half h0,l0,h1,l1;
                fsplit(v0,h0,l0); fsplit(v1,h1,l1);
                if (part < 2) {
                    size_t off = ((size_t)bhi*TT + t)*HD + e;
                    __half* dh = (part == 0) ? g_Qh : g_Kh;
                    __half* dl = (part == 0) ? g_Ql : g_Kl;
                    *(__half2*)(dh + off) = __halves2half2(h0, h1);
                    *(__half2*)(dl + off) = __halves2half2(l0, l1);
                } else {
                    size_t off = ((size_t)bhi*HD + e)*TT + t;
                    g_VTh[off] = h0;      g_VTl[off] = l0;
                    g_VTh[off + TT] = h1; g_VTl[off + TT] = l1;
                }
            }
        }
}

// ---------------- Output projection: block 128m x 192n ----------------
__global__ void __launch_bounds__(256)
oproj_mma(float* __restrict__ out)
{
    extern __shared__ __align__(16) char smc[];
    const uint32_t sb = smem_u32(smc);
    const uint32_t sAh = sb, sAl = sb + 10240, sBh = sb + 20480, sBl = sb + 35840;
    __half* pAh = (__half*)smc;           __half* pAl = (__half*)(smc + 10240);
    __half* pBh = (__half*)(smc + 20480); __half* pBl = (__half*)(smc + 35840);

    const int m0 = blockIdx.x * 128, n0g = blockIdx.y * 192;
    const int tid = threadIdx.x, lane = tid & 31, w = tid >> 5;
    const int WM = (w >> 2) * 64, WN = (w & 3) * 48;

    const __half* W2h = g_W2Th + (size_t)n0g*DM;
    const __half* W2l = g_W2Tl + (size_t)n0g*DM;

    float acc[4][6][4];
    #pragma unroll
    for (int mt = 0; mt < 4; mt++)
        #pragma unroll
        for (int nt = 0; nt < 6; nt++)
            #pragma unroll
            for (int c = 0; c < 4; c++) acc[mt][nt][c] = 0.0f;

    #pragma unroll 1
    for (int ch = 0; ch < 24; ch++) {
        int k0 = ch * 32;
        #pragma unroll
        for (int i = 0; i < 4; i++) {
            int f = tid + i*256, r = f >> 3, c4 = (f & 7) * 4;
            float4 v = *(const float4*)(g_A + (size_t)(m0 + r)*DM + k0 + c4);
            __half h0,l0,h1,l1,h2,l2,h3,l3;
            fsplit(v.x,h0,l0); fsplit(v.y,h1,l1); fsplit(v.z,h2,l2); fsplit(v.w,h3,l3);
            *(__half2*)(pAh + r*40 + c4)     = __halves2half2(h0, h1);
            *(__half2*)(pAh + r*40 + c4 + 2) = __halves2half2(h2, h3);
            *(__half2*)(pAl + r*40 + c4)     = __halves2half2(l0, l1);
            *(__half2*)(pAl + r*40 + c4 + 2) = __halves2half2(l2, l3);
        }
        #pragma unroll
        for (int i = 0; i < 3; i++) {
            int f = tid + i*256, r = f >> 2, c8 = (f & 3) * 8;
            *(uint4*)(pBh + r*40 + c8) = *(const uint4*)(W2h + (size_t)r*DM + k0 + c8);
            *(uint4*)(pBl + r*40 + c8) = *(const uint4*)(W2l + (size_t)r*DM + k0 + c8);
        }
        __syncthreads();
        #pragma unroll
        for (int ks = 0; ks < 2; ks++) {
            int kk = ks * 16;
            uint32_t ah[4][4], al[4][4], bhf[6][2], blf[6][2];
            #pragma unroll
            for (int mt = 0; mt < 4; mt++) {
                lda_frag(ah[mt], sAh, WM + mt*16, kk, 40, lane);
                lda_frag(al[mt], sAl, WM + mt*16, kk, 40, lane);
            }
            #pragma unroll
            for (int nt = 0; nt < 6; nt++) {
                ldb_frag(bhf[nt], sBh, WN + nt*8, kk, 40, lane);
                ldb_frag(blf[nt], sBl, WN + nt*8, kk, 40, lane);
            }
            #pragma unroll
            for (int mt = 0; mt < 4; mt++)
                #pragma unroll
                for (int nt = 0; nt < 6; nt++) {
                    mma16816(acc[mt][nt], ah[mt], bhf[nt]);
                    mma16816(acc[mt][nt], al[mt], bhf[nt]);
                    mma16816(acc[mt][nt], ah[mt], blf[nt]);
                }
        }
        __syncthreads();
    }

    #pragma unroll
    for (int mt = 0; mt < 4; mt++)
        #pragma unroll
        for (int rh = 0; rh < 2; rh++) {
            int m = m0 + WM + mt*16 + (lane >> 2) + rh*8;
            #pragma unroll
            for (int nt = 0; nt < 6; nt++) {
                int col = n0g + WN + nt*8 + (lane & 3)*2;
                float2 v;
                v.x = acc[mt][nt][rh*2 + 0] + g_b2[col];
                v.y = acc[mt][nt][rh*2 + 1] + g_b2[col + 1];
                *(float2*)(out + (size_t)m*DM + col) = v;
            }
        }
}

// ---------------- Flash attention on mma.sync ----------------
// smem (bytes): Qh 0 [128][72], Ql 18432, Kh 36864, Kl 55296,
//               Vh 73728 [64][136], Vl 91136, Ph 108544 [128][136], Pl 143360,
//               l4 178176 (4*128 f32)  => 180224 total
#define FQH 0u
#define FQL 18432u
#define FKH 36864u
#define FKL 55296u
#define FVH 73728u
#define FVL 91136u
#define FPH 108544u
#define FPL 143360u
#define FL4 178176u
#define F_SMEM 180224

__global__ void __launch_bounds__(256)
flash_mma()
{
    extern __shared__ __align__(16) char smc[];
    const uint32_t sb = smem_u32(smc);
    const int qt = blockIdx.x, bhid = blockIdx.y;
    const int tid = threadIdx.x, lane = tid & 31, w = tid >> 5;
    const int WM = (w >> 2) * 64, wn = w & 3;
    float* l4 = (float*)(smc + FL4);

    const __half* Qh = g_Qh + ((size_t)bhid*TT + qt*128)*HD;
    const __half* Ql = g_Ql + ((size_t)bhid*TT + qt*128)*HD;

    // stage Q tile [128][64] -> pitch 72
    #pragma unroll
    for (int i = 0; i < 4; i++) {
        int f = tid + i*256, r = f >> 3, c8 = (f & 7) * 8;
        *(uint4*)(smc + FQH + (uint32_t)(r*72 + c8)*2) = *(const uint4*)(Qh + (size_t)r*HD + c8);
        *(uint4*)(smc + FQL + (uint32_t)(r*72 + c8)*2) = *(const uint4*)(Ql + (size_t)r*HD + c8);
    }

    float oacc[4][2][4];
    float lreg[4][2];
    #pragma unroll
    for (int mt = 0; mt < 4; mt++) {
        lreg[mt][0] = 0.0f; lreg[mt][1] = 0.0f;
        #pragma unroll
        for (int nt = 0; nt < 2; nt++)
            #pragma unroll
            for (int c = 0; c < 4; c++) oacc[mt][nt][c] = 0.0f;
    }

    #pragma unroll 1
    for (int kt = 0; kt < 16; kt++) {
        // stage K [128][64] and V^T [64][128]
        const __half* Kh = g_Kh + ((size_t)bhid*TT + kt*128)*HD;
        const __half* Kl = g_Kl + ((size_t)bhid*TT + kt*128)*HD;
        #pragma unroll
        for (int i = 0; i < 4; i++) {
            int f = tid + i*256, r = f >> 3, c8 = (f & 7) * 8;
            *(uint4*)(smc + FKH + (uint32_t)(r*72 + c8)*2) = *(const uint4*)(Kh + (size_t)r*HD + c8);
            *(uint4*)(smc + FKL + (uint32_t)(r*72 + c8)*2) = *(const uint4*)(Kl + (size_t)r*HD + c8);
        }
        #pragma unroll
        for (int i = 0; i < 4; i++) {
            int f = tid + i*256, e = f >> 4, c8 = (f & 15) * 8;
            size_t src = ((size_t)bhid*HD + e)*TT + kt*128 + c8;
            *(uint4*)(smc + FVH + (uint32_t)(e*136 + c8)*2) = *(const uint4*)(g_VTh + src);
            *(uint4*)(smc + FVL + (uint32_t)(e*136 + c8)*2) = *(const uint4*)(g_VTl + src);
        }
        __syncthreads();

        // --- QK^T: S[128][128], warp region 64x32 ---
        float sacc[4][4][4];
        #pragma unroll
        for (int mt = 0; mt < 4; mt++)
            #pragma unroll
            for (int nt = 0; nt < 4; nt++)
                #pragma unroll
                for (int c = 0; c < 4; c++) sacc[mt][nt][c] = 0.0f;
        #pragma unroll
        for (int ks = 0; ks < 4; ks++) {
            int kk = ks * 16;
            uint32_t ah[4][4], al[4][4], bhf[4][2], blf[4][2];
            #pragma unroll
            for (int mt = 0; mt < 4; mt++) {
                lda_frag(ah[mt], sb + FQH, WM + mt*16, kk, 72, lane);
                lda_frag(al[mt], sb + FQL, WM + mt*16, kk, 72, lane);
            }
            #pragma unroll
            for (int nt = 0; nt < 4; nt++) {
                ldb_frag(bhf[nt], sb + FKH, wn*32 + nt*8, kk, 72, lane);
                ldb_frag(blf[nt], sb + FKL, wn*32 + nt*8, kk, 72, lane);
            }
            #pragma unroll
            for (int mt = 0; mt < 4; mt++)
                #pragma unroll
                for (int nt = 0; nt < 4; nt++) {
                    mma16816(sacc[mt][nt], ah[mt], bhf[nt]);
                    mma16816(sacc[mt][nt], al[mt], bhf[nt]);
                    mma16816(sacc[mt][nt], ah[mt], blf[nt]);
                }
        }

        // --- softmax (no max: logits bounded) + P split store + l accumulate ---
        #pragma unroll
        for (int mt = 0; mt < 4; mt++) {
            int row0 = WM + mt*16 + (lane >> 2);
            #pragma unroll
            for (int nt = 0; nt < 4; nt++) {
                int col = wn*32 + nt*8 + (lane & 3)*2;
                float p0 = fexp2(sacc[mt][nt][0]);
                float p1 = fexp2(sacc[mt][nt][1]);
                float p2 = fexp2(sacc[mt][nt][2]);
                float p3 = fexp2(sacc[mt][nt][3]);
                lreg[mt][0] += p0 + p1;
                lreg[mt][1] += p2 + p3;
                __half h0,l0,h1,l1,h2,l2,h3,l3;
                fsplit(p0,h0,l0); fsplit(p1,h1,l1); fsplit(p2,h2,l2); fsplit(p3,h3,l3);
                *(__half2*)(smc + FPH + (uint32_t)(row0*136 + col)*2)       = __halves2half2(h0,h1);
                *(__half2*)(smc + FPL + (uint32_t)(row0*136 + col)*2)       = __halves2half2(l0,l1);
                *(__half2*)(smc + FPH + (uint32_t)((row0+8)*136 + col)*2)   = __halves2half2(h2,h3);
                *(__half2*)(smc + FPL + (uint32_t)((row0+8)*136 + col)*2)   = __halves2half2(l2,l3);
            }
        }
        __syncthreads();

        // --- PV: O += P[128][128] * V^T[64][128]^T, warp region 64x16 ---
        #pragma unroll
        for (int ks = 0; ks < 8; ks++) {
            int kk = ks * 16;
            uint32_t pah[4][4], pal[4][4], vbh[2][2], vbl[2][2];
            #pragma unroll
            for (int mt = 0; mt < 4; mt++) {
                lda_frag(pah[mt], sb + FPH, WM + mt*16, kk, 136, lane);
                lda_frag(pal[mt], sb + FPL, WM + mt*16, kk, 136, lane);
            }
            #pragma unroll
            for (int nt = 0; nt < 2; nt++) {
                ldb_frag(vbh[nt], sb + FVH, wn*16 + nt*8, kk, 136, lane);
                ldb_frag(vbl[nt], sb + FVL, wn*16 + nt*8, kk, 136, lane);
            }
            #pragma unroll
            for (int mt = 0; mt < 4; mt++)
                #pragma unroll
                for (int nt = 0; nt < 2; nt++) {
                    mma16816(oacc[mt][nt], pah[mt], vbh[nt]);
                    mma16816(oacc[mt][nt], pal[mt], vbh[nt]);
                    mma16816(oacc[mt][nt], pah[mt], vbl[nt]);
                }
        }
        __syncthreads();
    }

    // --- l reduction across lanes (cols) and warps (wn) ---
    #pragma unroll
    for (int mt = 0; mt < 4; mt++)
        #pragma unroll
        for (int rh = 0; rh < 2; rh++) {
            float v = lreg[mt][rh];
            v += __shfl_xor_sync(0xffffffffu, v, 1);
            v += __shfl_xor_sync(0xffffffffu, v, 2);
            if ((lane & 3) == 0)
                l4[wn*128 + WM + mt*16 + (lane >> 2) + rh*8] = v;
        }
    __syncthreads();

    const int b = bhid / NH, h = bhid % NH;
    #pragma unroll
    for (int mt = 0; mt < 4; mt++)
        #pragma unroll
        for (int rh = 0; rh < 2; rh++) {
            int row = WM + mt*16 + (lane >> 2) + rh*8;
            float lt = l4[row] + l4[128 + row] + l4[256 + row] + l4[384 + row];
            float inv = 1.0f / lt;
            int t = qt*128 + row;
            #pragma unroll
            for (int nt = 0; nt < 2; nt++) {
                int e = wn*16 + nt*8 + (lane & 3)*2;
                float2 v;
                v.x = oacc[mt][nt][rh*2 + 0] * inv;
                v.y = oacc[mt][nt][rh*2 + 1] * inv;
                *(float2*)(g_A + ((size_t)(b*TT + t))*DM + h*HD + e) = v;
            }
        }
}

// ---------------------------------------------------------------------------
extern "C" void kernel_launch(void* const* d_in, const int* in_sizes, int n_in,
                              void* d_out, int out_size)
{
    const float* X    = (const float*)d_in[0];
    const float* Wq   = (const float*)d_in[1];
    const float* bq   = (const float*)d_in[2];
    const float* Wk   = (const float*)d_in[3];
    const float* bk   = (const float*)d_in[4];
    const float* Wv   = (const float*)d_in[5];
    const float* bv   = (const float*)d_in[6];
    const float* Wo   = (const float*)d_in[7];
    const float* bo   = (const float*)d_in[8];
    const float* gate = (const float*)d_in[9];
    float* out = (float*)d_out;

    static int init = 0;
    if (!init) {
        cudaFuncSetAttribute(qkv_mma,   cudaFuncAttributeMaxDynamicSharedMemorySize, G_SMEM);
        cudaFuncSetAttribute(oproj_mma, cudaFuncAttributeMaxDynamicSharedMemorySize, G_SMEM);
        cudaFuncSetAttribute(flash_mma, cudaFuncAttributeMaxDynamicSharedMemorySize, F_SMEM);
        init = 1;
    }

    prep_w3<<<(NH*192*DM + 255)/256, 256>>>(Wq, Wk, Wv);
    prep_w2<<<(DM*DM + 255)/256, 256>>>(Wo, gate);
    prep_b2<<<(DM + 255)/256, 256>>>(bo, gate);
    qkv_mma<<<dim3(MTOT/128, NH), 256, G_SMEM>>>(X, bq, bk, bv);
    flash_mma<<<dim3(TT/128, NBH), 256, F_SMEM>>>();
    oproj_mma<<<dim3(MTOT/128, DM/192), 256, G_SMEM>>>(out);
}

// round 6
// speedup vs baseline: 2.8434x; 1.1842x over previous
#include <cuda_runtime.h>
#include <cuda_fp16.h>
#include <cstdint>

#define NH 12
#define TT 2048
#define BB 4
#define DM 768
#define HD 64
#define MTOT (BB*TT)
#define NBH (BB*NH)
#define QSCALE 0.18033688011112042f   // log2(e)/sqrt(64)

// ---------------- global scratch (allocation-free) ----------------
__device__ __half g_Xh[MTOT*DM],  g_Xl[MTOT*DM];        // split input
__device__ __half g_W3h[NH*192*DM], g_W3l[NH*192*DM];   // [h][n=q|k|v*64+e][k]
__device__ __half g_W2Th[DM*DM],    g_W2Tl[DM*DM];      // [n][k], gate folded
__device__ float  g_b2[DM];
__device__ __half g_Qh[NBH*TT*HD], g_Ql[NBH*TT*HD];     // [bh][t][e] (scale folded)
__device__ __half g_Kh[NBH*TT*HD], g_Kl[NBH*TT*HD];     // [bh][t][e]
__device__ __half g_VTh[NBH*HD*TT], g_VTl[NBH*HD*TT];   // [bh][e][t]
__device__ __half g_Ah[MTOT*DM],  g_Al[MTOT*DM];        // attn out split [8192][768]

// ---------------- helpers ----------------
__device__ __forceinline__ uint32_t smem_u32(const void* p) {
    uint32_t a;
    asm("{ .reg .u64 t; cvta.to.shared.u64 t, %1; cvt.u32.u64 %0, t; }" : "=r"(a) : "l"(p));
    return a;
}
__device__ __forceinline__ float fexp2(float x) {
    float y; asm("ex2.approx.ftz.f32 %0, %1;" : "=f"(y) : "f"(x)); return y;
}
__device__ __forceinline__ void fsplit(float x, __half& h, __half& l) {
    h = __float2half_rn(x);
    l = __float2half_rn(x - __half2float(h));
}
__device__ __forceinline__ void cp16(uint32_t dst, const void* src) {
    asm volatile("cp.async.cg.shared.global [%0], [%1], 16;" :: "r"(dst), "l"(src));
}
#define CP_COMMIT() asm volatile("cp.async.commit_group;" ::: "memory")
#define CP_WAIT0()  asm volatile("cp.async.wait_group 0;" ::: "memory")
#define CP_WAIT1()  asm volatile("cp.async.wait_group 1;" ::: "memory")

__device__ __forceinline__ void ldsm4(uint32_t* r, uint32_t addr) {
    asm volatile("ldmatrix.sync.aligned.m8n8.x4.shared.b16 {%0,%1,%2,%3}, [%4];"
        : "=r"(r[0]), "=r"(r[1]), "=r"(r[2]), "=r"(r[3]) : "r"(addr));
}
__device__ __forceinline__ void ldsm2(uint32_t* r, uint32_t addr) {
    asm volatile("ldmatrix.sync.aligned.m8n8.x2.shared.b16 {%0,%1}, [%2];"
        : "=r"(r[0]), "=r"(r[1]) : "r"(addr));
}
__device__ __forceinline__ void mma16816(float* d, const uint32_t* a, const uint32_t* b) {
    asm volatile("mma.sync.aligned.m16n8k16.row.col.f32.f16.f16.f32 "
        "{%0,%1,%2,%3}, {%4,%5,%6,%7}, {%8,%9}, {%0,%1,%2,%3};"
        : "+f"(d[0]), "+f"(d[1]), "+f"(d[2]), "+f"(d[3])
        : "r"(a[0]), "r"(a[1]), "r"(a[2]), "r"(a[3]), "r"(b[0]), "r"(b[1]));
}
__device__ __forceinline__ void lda_frag(uint32_t* r, uint32_t sbase, int m0, int k0,
                                         int pitch, int lane) {
    uint32_t addr = sbase + (uint32_t)(((m0 + (lane & 7) + ((lane >> 3) & 1) * 8) * pitch
                                       + k0 + ((lane >> 4) & 1) * 8) * 2);
    ldsm4(r, addr);
}
__device__ __forceinline__ void ldb_frag(uint32_t* r, uint32_t sbase, int n0, int k0,
                                         int pitch, int lane) {
    uint32_t addr = sbase + (uint32_t)(((n0 + (lane & 7)) * pitch
                                       + k0 + ((lane >> 3) & 1) * 8) * 2);
    ldsm2(r, addr);
}

// ---------------- prep ----------------
__global__ void prep_x(const float* __restrict__ X) {
    int idx = (blockIdx.x * 256 + threadIdx.x) * 4;
    float4 v = *(const float4*)(X + idx);
    __half h0,l0,h1,l1,h2,l2,h3,l3;
    fsplit(v.x,h0,l0); fsplit(v.y,h1,l1); fsplit(v.z,h2,l2); fsplit(v.w,h3,l3);
    *(__half2*)(g_Xh + idx)     = __halves2half2(h0, h1);
    *(__half2*)(g_Xh + idx + 2) = __halves2half2(h2, h3);
    *(__half2*)(g_Xl + idx)     = __halves2half2(l0, l1);
    *(__half2*)(g_Xl + idx + 2) = __halves2half2(l2, l3);
}
__global__ void prep_w3(const float* __restrict__ Wq, const float* __restrict__ Wk,
                        const float* __restrict__ Wv) {
    int idx = blockIdx.x * 256 + threadIdx.x;
    if (idx >= NH*192*DM) return;
    int k = idx % DM;
    int n = (idx / DM) % 192;
    int h = idx / (192*DM);
    int part = n >> 6, e = n & 63;
    const float* W = (part == 0) ? Wq : (part == 1) ? Wk : Wv;
    float v = W[((size_t)h*DM + k)*HD + e];
    if (part == 0) v *= QSCALE;
    __half hh, hl; fsplit(v, hh, hl);
    g_W3h[idx] = hh; g_W3l[idx] = hl;
}
__global__ void prep_w2(const float* __restrict__ Wo, const float* __restrict__ gate) {
    int idx = blockIdx.x * 256 + threadIdx.x;
    if (idx >= DM*DM) return;
    int k = idx % DM, n = idx / DM;
    int h = k >> 6, e = k & 63;
    float g = gate[h]; g = (g < 1e-6f) ? 0.0f : g;
    float v = Wo[((size_t)h*HD + e)*DM + n] * g;
    __half hh, hl; fsplit(v, hh, hl);
    g_W2Th[idx] = hh; g_W2Tl[idx] = hl;
}
__global__ void prep_b2(const float* __restrict__ bo, const float* __restrict__ gate) {
    int d = blockIdx.x * 256 + threadIdx.x;
    if (d >= DM) return;
    float s = 0.0f;
    #pragma unroll
    for (int h = 0; h < NH; h++) {
        float g = gate[h]; g = (g < 1e-6f) ? 0.0f : g;
        s += g * bo[h*DM + d];
    }
    g_b2[d] = s;
}

// ======================= GEMM 128m x 192n, K=768, BK=32 ====================
// per-stage smem: Ah[128][40] @0, Al @10240, Bh[192][40] @20480, Bl @35840
// 2 stages => 102400 B
#define GS_AH 0u
#define GS_AL 10240u
#define GS_BH 20480u
#define GS_BL 35840u
#define G_STAGE 51200u
#define G_SMEM 102400

__device__ __forceinline__ void gemm_load_stage(
    uint32_t sb, int s, int k0, int tid,
    const __half* Ah, const __half* Al, const __half* Bh, const __half* Bl)
{
    uint32_t base = sb + (uint32_t)s * G_STAGE;
    #pragma unroll
    for (int i = 0; i < 2; i++) {
        int f = tid + i*256, r = f >> 2, c = (f & 3) * 8;
        cp16(base + GS_AH + (uint32_t)(r*80 + c*2), Ah + (size_t)r*DM + k0 + c);
        cp16(base + GS_AL + (uint32_t)(r*80 + c*2), Al + (size_t)r*DM + k0 + c);
    }
    #pragma unroll
    for (int i = 0; i < 3; i++) {
        int f = tid + i*256, r = f >> 2, c = (f & 3) * 8;
        cp16(base + GS_BH + (uint32_t)(r*80 + c*2), Bh + (size_t)r*DM + k0 + c);
        cp16(base + GS_BL + (uint32_t)(r*80 + c*2), Bl + (size_t)r*DM + k0 + c);
    }
}

__device__ __forceinline__ void gemm_main(
    uint32_t sb, int tid, int lane, int WM, int WN,
    const __half* Ah, const __half* Al, const __half* Bh, const __half* Bl,
    float acc[4][6][4])
{
    gemm_load_stage(sb, 0, 0, tid, Ah, Al, Bh, Bl);
    CP_COMMIT();
    #pragma unroll 1
    for (int ch = 0; ch < 24; ch++) {
        if (ch < 23) {
            gemm_load_stage(sb, (ch+1) & 1, (ch+1)*32, tid, Ah, Al, Bh, Bl);
            CP_COMMIT();
            CP_WAIT1();
        } else {
            CP_WAIT0();
        }
        __syncthreads();
        uint32_t base = sb + (uint32_t)(ch & 1) * G_STAGE;
        #pragma unroll
        for (int ks = 0; ks < 2; ks++) {
            int kk = ks * 16;
            uint32_t ah[4][4], al[4][4], bhf[6][2], blf[6][2];
            #pragma unroll
            for (int mt = 0; mt < 4; mt++) {
                lda_frag(ah[mt], base + GS_AH, WM + mt*16, kk, 40, lane);
                lda_frag(al[mt], base + GS_AL, WM + mt*16, kk, 40, lane);
            }
            #pragma unroll
            for (int nt = 0; nt < 6; nt++) {
                ldb_frag(bhf[nt], base + GS_BH, WN + nt*8, kk, 40, lane);
                ldb_frag(blf[nt], base + GS_BL, WN + nt*8, kk, 40, lane);
            }
            #pragma unroll
            for (int mt = 0; mt < 4; mt++)
                #pragma unroll
                for (int nt = 0; nt < 6; nt++) {
                    mma16816(acc[mt][nt], ah[mt], bhf[nt]);
                    mma16816(acc[mt][nt], al[mt], bhf[nt]);
                    mma16816(acc[mt][nt], ah[mt], blf[nt]);
                }
        }
        __syncthreads();
    }
}

// ---------------- QKV projection ----------------
__global__ void __launch_bounds__(256)
qkv_mma(const float* __restrict__ bq, const float* __restrict__ bk,
        const float* __restrict__ bv)
{
    extern __shared__ __align__(16) char smc[];
    const uint32_t sb = smem_u32(smc);
    const int m0 = blockIdx.x * 128, h = blockIdx.y;
    const int tid = threadIdx.x, lane = tid & 31, w = tid >> 5;
    const int WM = (w >> 2) * 64, WN = (w & 3) * 48;

    float acc[4][6][4];
    #pragma unroll
    for (int mt = 0; mt < 4; mt++)
        #pragma unroll
        for (int nt = 0; nt < 6; nt++)
            #pragma unroll
            for (int c = 0; c < 4; c++) acc[mt][nt][c] = 0.0f;

    gemm_main(sb, tid, lane, WM, WN,
              g_Xh + (size_t)m0*DM, g_Xl + (size_t)m0*DM,
              g_W3h + (size_t)h*192*DM, g_W3l + (size_t)h*192*DM, acc);

    #pragma unroll
    for (int mt = 0; mt < 4; mt++)
        #pragma unroll
        for (int rh = 0; rh < 2; rh++) {
            int m = m0 + WM + mt*16 + (lane >> 2) + rh*8;
            int b = m >> 11, t = m & (TT-1);
            int bhi = b*NH + h;
            #pragma unroll
            for (int nt = 0; nt < 6; nt++) {
                int col = WN + nt*8 + (lane & 3)*2;
                int part = col >> 6, e = col & 63;
                float v0 = acc[mt][nt][rh*2 + 0];
                float v1 = acc[mt][nt][rh*2 + 1];
                if (part == 0)      { v0 += bq[h*HD+e]*QSCALE; v1 += bq[h*HD+e+1]*QSCALE; }
                else if (part == 1) { v0 += bk[h*HD+e];        v1 += bk[h*HD+e+1]; }
                else                { v0 += bv[h*HD+e];        v1 += bv[h*HD+e+1]; }
                __half h0,l0,h1,l1;
                fsplit(v0,h0,l0); fsplit(v1,h1,l1);
                if (part < 2) {
                    size_t off = ((size_t)bhi*TT + t)*HD + e;
                    __half* dh = (part == 0) ? g_Qh : g_Kh;
                    __half* dl = (part == 0) ? g_Ql : g_Kl;
                    *(__half2*)(dh + off) = __halves2half2(h0, h1);
                    *(__half2*)(dl + off) = __halves2half2(l0, l1);
                } else {
                    size_t off = ((size_t)bhi*HD + e)*TT + t;
                    g_VTh[off] = h0;      g_VTl[off] = l0;
                    g_VTh[off + TT] = h1; g_VTl[off + TT] = l1;
                }
            }
        }
}

// ---------------- Output projection ----------------
__global__ void __launch_bounds__(256)
oproj_mma(float* __restrict__ out)
{
    extern __shared__ __align__(16) char smc[];
    const uint32_t sb = smem_u32(smc);
    const int m0 = blockIdx.x * 128, n0g = blockIdx.y * 192;
    const int tid = threadIdx.x, lane = tid & 31, w = tid >> 5;
    const int WM = (w >> 2) * 64, WN = (w & 3) * 48;

    float acc[4][6][4];
    #pragma unroll
    for (int mt = 0; mt < 4; mt++)
        #pragma unroll
        for (int nt = 0; nt < 6; nt++)
            #pragma unroll
            for (int c = 0; c < 4; c++) acc[mt][nt][c] = 0.0f;

    gemm_main(sb, tid, lane, WM, WN,
              g_Ah + (size_t)m0*DM, g_Al + (size_t)m0*DM,
              g_W2Th + (size_t)n0g*DM, g_W2Tl + (size_t)n0g*DM, acc);

    #pragma unroll
    for (int mt = 0; mt < 4; mt++)
        #pragma unroll
        for (int rh = 0; rh < 2; rh++) {
            int m = m0 + WM + mt*16 + (lane >> 2) + rh*8;
            #pragma unroll
            for (int nt = 0; nt < 6; nt++) {
                int col = n0g + WN + nt*8 + (lane & 3)*2;
                float2 v;
                v.x = acc[mt][nt][rh*2 + 0] + g_b2[col];
                v.y = acc[mt][nt][rh*2 + 1] + g_b2[col + 1];
                *(float2*)(out + (size_t)m*DM + col) = v;
            }
        }
}

// ======================= Flash attention =======================
// smem bytes:
//  QH 0 [128][72], QL 18432
//  K stages s=0,1: KH 36864+s*36864, KL +18432
//  V stages s=0,1: VH 110592+s*34816 [64][136], VL +17408
//  PH 180224 [128][136]
//  l4 215040 (4*128 f32)           total 217088
#define FQH 0u
#define FQL 18432u
#define FKH(s) (36864u + (uint32_t)(s)*36864u)
#define FKL(s) (FKH(s) + 18432u)
#define FVH(s) (110592u + (uint32_t)(s)*34816u)
#define FVL(s) (FVH(s) + 17408u)
#define FPH 180224u
#define FL4 215040u
#define F_SMEM 217088

__device__ __forceinline__ void flash_load_kv(uint32_t sb, int s, int kt, int tid,
                                              const __half* Kh, const __half* Kl,
                                              const __half* VTh, const __half* VTl)
{
    const __half* Khc = Kh + (size_t)kt*128*HD;
    const __half* Klc = Kl + (size_t)kt*128*HD;
    #pragma unroll
    for (int i = 0; i < 4; i++) {
        int f = tid + i*256, r = f >> 3, c = (f & 7) * 8;
        cp16(sb + FKH(s) + (uint32_t)(r*144 + c*2), Khc + (size_t)r*HD + c);
        cp16(sb + FKL(s) + (uint32_t)(r*144 + c*2), Klc + (size_t)r*HD + c);
    }
    #pragma unroll
    for (int i = 0; i < 4; i++) {
        int f = tid + i*256, e = f >> 4, c = (f & 15) * 8;
        size_t src = (size_t)e*TT + kt*128 + c;
        cp16(sb + FVH(s) + (uint32_t)(e*272 + c*2), VTh + src);
        cp16(sb + FVL(s) + (uint32_t)(e*272 + c*2), VTl + src);
    }
}

__global__ void __launch_bounds__(256)
flash_mma()
{
    extern __shared__ __align__(16) char smc[];
    const uint32_t sb = smem_u32(smc);
    const int qt = blockIdx.x, bhid = blockIdx.y;
    const int tid = threadIdx.x, lane = tid & 31, w = tid >> 5;
    const int WM = (w >> 2) * 64, wn = w & 3;
    float* l4 = (float*)(smc + FL4);

    const __half* Qh = g_Qh + ((size_t)bhid*TT + qt*128)*HD;
    const __half* Ql = g_Ql + ((size_t)bhid*TT + qt*128)*HD;
    const __half* Kh = g_Kh + (size_t)bhid*TT*HD;
    const __half* Kl = g_Kl + (size_t)bhid*TT*HD;
    const __half* VTh = g_VTh + (size_t)bhid*HD*TT;
    const __half* VTl = g_VTl + (size_t)bhid*HD*TT;

    // stage Q (one-time) + kv stage 0
    #pragma unroll
    for (int i = 0; i < 4; i++) {
        int f = tid + i*256, r = f >> 3, c = (f & 7) * 8;
        cp16(sb + FQH + (uint32_t)(r*144 + c*2), Qh + (size_t)r*HD + c);
        cp16(sb + FQL + (uint32_t)(r*144 + c*2), Ql + (size_t)r*HD + c);
    }
    flash_load_kv(sb, 0, 0, tid, Kh, Kl, VTh, VTl);
    CP_COMMIT();

    float oacc[4][2][4];
    float lreg[4][2];
    #pragma unroll
    for (int mt = 0; mt < 4; mt++) {
        lreg[mt][0] = 0.0f; lreg[mt][1] = 0.0f;
        #pragma unroll
        for (int nt = 0; nt < 2; nt++)
            #pragma unroll
            for (int c = 0; c < 4; c++) oacc[mt][nt][c] = 0.0f;
    }

    #pragma unroll 1
    for (int kt = 0; kt < 16; kt++) {
        if (kt < 15) {
            flash_load_kv(sb, (kt+1) & 1, kt+1, tid, Kh, Kl, VTh, VTl);
            CP_COMMIT();
            CP_WAIT1();
        } else {
            CP_WAIT0();
        }
        __syncthreads();
        const int s = kt & 1;

        // --- QK^T: warp region 64x32 ---
        float sacc[4][4][4];
        #pragma unroll
        for (int mt = 0; mt < 4; mt++)
            #pragma unroll
            for (int nt = 0; nt < 4; nt++)
                #pragma unroll
                for (int c = 0; c < 4; c++) sacc[mt][nt][c] = 0.0f;
        #pragma unroll
        for (int ks = 0; ks < 4; ks++) {
            int kk = ks * 16;
            uint32_t ah[4][4], al[4][4], bhf[4][2], blf[4][2];
            #pragma unroll
            for (int mt = 0; mt < 4; mt++) {
                lda_frag(ah[mt], sb + FQH, WM + mt*16, kk, 72, lane);
                lda_frag(al[mt], sb + FQL, WM + mt*16, kk, 72, lane);
            }
            #pragma unroll
            for (int nt = 0; nt < 4; nt++) {
                ldb_frag(bhf[nt], sb + FKH(s), wn*32 + nt*8, kk, 72, lane);
                ldb_frag(blf[nt], sb + FKL(s), wn*32 + nt*8, kk, 72, lane);
            }
            #pragma unroll
            for (int mt = 0; mt < 4; mt++)
                #pragma unroll
                for (int nt = 0; nt < 4; nt++) {
                    mma16816(sacc[mt][nt], ah[mt], bhf[nt]);
                    mma16816(sacc[mt][nt], al[mt], bhf[nt]);
                    mma16816(sacc[mt][nt], ah[mt], blf[nt]);
                }
        }

        // --- softmax (no max: logits bounded) + P(half) store + l accumulate ---
        #pragma unroll
        for (int mt = 0; mt < 4; mt++) {
            int row0 = WM + mt*16 + (lane >> 2);
            #pragma unroll
            for (int nt = 0; nt < 4; nt++) {
                int col = wn*32 + nt*8 + (lane & 3)*2;
                float p0 = fexp2(sacc[mt][nt][0]);
                float p1 = fexp2(sacc[mt][nt][1]);
                float p2 = fexp2(sacc[mt][nt][2]);
                float p3 = fexp2(sacc[mt][nt][3]);
                lreg[mt][0] += p0 + p1;
                lreg[mt][1] += p2 + p3;
                *(__half2*)(smc + FPH + (uint32_t)(row0*136 + col)*2)
                    = __halves2half2(__float2half_rn(p0), __float2half_rn(p1));
                *(__half2*)(smc + FPH + (uint32_t)((row0+8)*136 + col)*2)
                    = __halves2half2(__float2half_rn(p2), __float2half_rn(p3));
            }
        }
        __syncthreads();

        // --- PV: O += Ph*(Vh + Vl), warp region 64x16 ---
        #pragma unroll
        for (int ks = 0; ks < 8; ks++) {
            int kk = ks * 16;
            uint32_t pah[4][4], vbh[2][2], vbl[2][2];
            #pragma unroll
            for (int mt = 0; mt < 4; mt++)
                lda_frag(pah[mt], sb + FPH, WM + mt*16, kk, 136, lane);
            #pragma unroll
            for (int nt = 0; nt < 2; nt++) {
                ldb_frag(vbh[nt], sb + FVH(s), wn*16 + nt*8, kk, 136, lane);
                ldb_frag(vbl[nt], sb + FVL(s), wn*16 + nt*8, kk, 136, lane);
            }
            #pragma unroll
            for (int mt = 0; mt < 4; mt++)
                #pragma unroll
                for (int nt = 0; nt < 2; nt++) {
                    mma16816(oacc[mt][nt], pah[mt], vbh[nt]);
                    mma16816(oacc[mt][nt], pah[mt], vbl[nt]);
                }
        }
        __syncthreads();
    }

    // --- l reduction + normalized split write ---
    #pragma unroll
    for (int mt = 0; mt < 4; mt++)
        #pragma unroll
        for (int rh = 0; rh < 2; rh++) {
            float v = lreg[mt][rh];
            v += __shfl_xor_sync(0xffffffffu, v, 1);
            v += __shfl_xor_sync(0xffffffffu, v, 2);
            if ((lane & 3) == 0)
                l4[wn*128 + WM + mt*16 + (lane >> 2) + rh*8] = v;
        }
    __syncthreads();

    const int b = bhid / NH, h = bhid % NH;
    #pragma unroll
    for (int mt = 0; mt < 4; mt++)
        #pragma unroll
        for (int rh = 0; rh < 2; rh++) {
            int row = WM + mt*16 + (lane >> 2) + rh*8;
            float lt = l4[row] + l4[128 + row] + l4[256 + row] + l4[384 + row];
            float inv = 1.0f / lt;
            int t = qt*128 + row;
            #pragma unroll
            for (int nt = 0; nt < 2; nt++) {
                int e = wn*16 + nt*8 + (lane & 3)*2;
                float v0 = oacc[mt][nt][rh*2 + 0] * inv;
                float v1 = oacc[mt][nt][rh*2 + 1] * inv;
                __half h0,l0,h1,l1;
                fsplit(v0,h0,l0); fsplit(v1,h1,l1);
                size_t off = ((size_t)(b*TT + t))*DM + h*HD + e;
                *(__half2*)(g_Ah + off) = __halves2half2(h0, h1);
                *(__half2*)(g_Al + off) = __halves2half2(l0, l1);
            }
        }
}

// ---------------------------------------------------------------------------
extern "C" void kernel_launch(void* const* d_in, const int* in_sizes, int n_in,
                              void* d_out, int out_size)
{
    const float* X    = (const float*)d_in[0];
    const float* Wq   = (const float*)d_in[1];
    const float* bq   = (const float*)d_in[2];
    const float* Wk   = (const float*)d_in[3];
    const float* bk   = (const float*)d_in[4];
    const float* Wv   = (const float*)d_in[5];
    const float* bv   = (const float*)d_in[6];
    const float* Wo   = (const float*)d_in[7];
    const float* bo   = (const float*)d_in[8];
    const float* gate = (const float*)d_in[9];
    float* out = (float*)d_out;

    static int init = 0;
    if (!init) {
        cudaFuncSetAttribute(qkv_mma,   cudaFuncAttributeMaxDynamicSharedMemorySize, G_SMEM);
        cudaFuncSetAttribute(oproj_mma, cudaFuncAttributeMaxDynamicSharedMemorySize, G_SMEM);
        cudaFuncSetAttribute(flash_mma, cudaFuncAttributeMaxDynamicSharedMemorySize, F_SMEM);
        init = 1;
    }

    prep_x<<<MTOT*DM/1024, 256>>>(X);
    prep_w3<<<(NH*192*DM + 255)/256, 256>>>(Wq, Wk, Wv);
    prep_w2<<<(DM*DM + 255)/256, 256>>>(Wo, gate);
    prep_b2<<<(DM + 255)/256, 256>>>(bo, gate);
    qkv_mma<<<dim3(MTOT/128, NH), 256, G_SMEM>>>(bq, bk, bv);
    flash_mma<<<dim3(TT/128, NBH), 256, F_SMEM>>>();
    oproj_mma<<<dim3(MTOT/128, DM/192), 256, G_SMEM>>>(out);
}

// round 7
// speedup vs baseline: 3.1725x; 1.1157x over previous
#include <cuda_runtime.h>
#include <cuda_fp16.h>
#include <cstdint>

#define NH 12
#define TT 2048
#define BB 4
#define DM 768
#define HD 64
#define MTOT (BB*TT)
#define NBH (BB*NH)
#define QSCALE 0.18033688011112042f   // log2(e)/sqrt(64)

// ---------------- global scratch (allocation-free) ----------------
__device__ __half g_Xh[MTOT*DM],  g_Xl[MTOT*DM];        // split input
__device__ __half g_W3h[NH*192*DM], g_W3l[NH*192*DM];   // [h][n=q|k|v*64+e][k]
__device__ __half g_W2Th[DM*DM],    g_W2Tl[DM*DM];      // [n][k], gate folded
__device__ float  g_b2[DM];
__device__ __half g_Qh[NBH*TT*HD], g_Ql[NBH*TT*HD];     // [bh][t][e] (scale folded)
__device__ __half g_Kh[NBH*TT*HD], g_Kl[NBH*TT*HD];     // [bh][t][e]
__device__ __half g_VTh[NBH*HD*TT];                      // [bh][e][t] (hi only)
__device__ __half g_Ah[MTOT*DM],  g_Al[MTOT*DM];        // attn out split [8192][768]

// ---------------- helpers ----------------
__device__ __forceinline__ uint32_t smem_u32(const void* p) {
    uint32_t a;
    asm("{ .reg .u64 t; cvta.to.shared.u64 t, %1; cvt.u32.u64 %0, t; }" : "=r"(a) : "l"(p));
    return a;
}
__device__ __forceinline__ float fexp2(float x) {
    float y; asm("ex2.approx.ftz.f32 %0, %1;" : "=f"(y) : "f"(x)); return y;
}
__device__ __forceinline__ void fsplit(float x, __half& h, __half& l) {
    h = __float2half_rn(x);
    l = __float2half_rn(x - __half2float(h));
}
__device__ __forceinline__ void cp16(uint32_t dst, const void* src) {
    asm volatile("cp.async.cg.shared.global [%0], [%1], 16;" :: "r"(dst), "l"(src));
}
#define CP_COMMIT() asm volatile("cp.async.commit_group;" ::: "memory")
#define CP_WAIT0()  asm volatile("cp.async.wait_group 0;" ::: "memory")
#define CP_WAIT1()  asm volatile("cp.async.wait_group 1;" ::: "memory")

__device__ __forceinline__ void ldsm4(uint32_t* r, uint32_t addr) {
    asm volatile("ldmatrix.sync.aligned.m8n8.x4.shared.b16 {%0,%1,%2,%3}, [%4];"
        : "=r"(r[0]), "=r"(r[1]), "=r"(r[2]), "=r"(r[3]) : "r"(addr));
}
__device__ __forceinline__ void ldsm2(uint32_t* r, uint32_t addr) {
    asm volatile("ldmatrix.sync.aligned.m8n8.x2.shared.b16 {%0,%1}, [%2];"
        : "=r"(r[0]), "=r"(r[1]) : "r"(addr));
}
__device__ __forceinline__ void mma16816(float* d, const uint32_t* a, const uint32_t* b) {
    asm volatile("mma.sync.aligned.m16n8k16.row.col.f32.f16.f16.f32 "
        "{%0,%1,%2,%3}, {%4,%5,%6,%7}, {%8,%9}, {%0,%1,%2,%3};"
        : "+f"(d[0]), "+f"(d[1]), "+f"(d[2]), "+f"(d[3])
        : "r"(a[0]), "r"(a[1]), "r"(a[2]), "r"(a[3]), "r"(b[0]), "r"(b[1]));
}
__device__ __forceinline__ void lda_frag(uint32_t* r, uint32_t sbase, int m0, int k0,
                                         int pitch, int lane) {
    uint32_t addr = sbase + (uint32_t)(((m0 + (lane & 7) + ((lane >> 3) & 1) * 8) * pitch
                                       + k0 + ((lane >> 4) & 1) * 8) * 2);
    ldsm4(r, addr);
}
__device__ __forceinline__ void ldb_frag(uint32_t* r, uint32_t sbase, int n0, int k0,
                                         int pitch, int lane) {
    uint32_t addr = sbase + (uint32_t)(((n0 + (lane & 7)) * pitch
                                       + k0 + ((lane >> 3) & 1) * 8) * 2);
    ldsm2(r, addr);
}
__device__ __forceinline__ uint32_t h2pack(float a, float b) {
    __half2 h = __floats2half2_rn(a, b);
    return *(uint32_t*)&h;
}

// ---------------- prep ----------------
__global__ void prep_x(const float* __restrict__ X) {
    int idx = (blockIdx.x * 256 + threadIdx.x) * 4;
    float4 v = *(const float4*)(X + idx);
    __half h0,l0,h1,l1,h2,l2,h3,l3;
    fsplit(v.x,h0,l0); fsplit(v.y,h1,l1); fsplit(v.z,h2,l2); fsplit(v.w,h3,l3);
    *(__half2*)(g_Xh + idx)     = __halves2half2(h0, h1);
    *(__half2*)(g_Xh + idx + 2) = __halves2half2(h2, h3);
    *(__half2*)(g_Xl + idx)     = __halves2half2(l0, l1);
    *(__half2*)(g_Xl + idx + 2) = __halves2half2(l2, l3);
}
__global__ void prep_w3(const float* __restrict__ Wq, const float* __restrict__ Wk,
                        const float* __restrict__ Wv) {
    int idx = blockIdx.x * 256 + threadIdx.x;
    if (idx >= NH*192*DM) return;
    int k = idx % DM;
    int n = (idx / DM) % 192;
    int h = idx / (192*DM);
    int part = n >> 6, e = n & 63;
    const float* W = (part == 0) ? Wq : (part == 1) ? Wk : Wv;
    float v = W[((size_t)h*DM + k)*HD + e];
    if (part == 0) v *= QSCALE;
    __half hh, hl; fsplit(v, hh, hl);
    g_W3h[idx] = hh; g_W3l[idx] = hl;
}
__global__ void prep_w2(const float* __restrict__ Wo, const float* __restrict__ gate) {
    int idx = blockIdx.x * 256 + threadIdx.x;
    if (idx >= DM*DM) return;
    int k = idx % DM, n = idx / DM;
    int h = k >> 6, e = k & 63;
    float g = gate[h]; g = (g < 1e-6f) ? 0.0f : g;
    float v = Wo[((size_t)h*HD + e)*DM + n] * g;
    __half hh, hl; fsplit(v, hh, hl);
    g_W2Th[idx] = hh; g_W2Tl[idx] = hl;
}
__global__ void prep_b2(const float* __restrict__ bo, const float* __restrict__ gate) {
    int d = blockIdx.x * 256 + threadIdx.x;
    if (d >= DM) return;
    float s = 0.0f;
    #pragma unroll
    for (int h = 0; h < NH; h++) {
        float g = gate[h]; g = (g < 1e-6f) ? 0.0f : g;
        s += g * bo[h*DM + d];
    }
    g_b2[d] = s;
}

// ======================= GEMM 128m x 192n, K=768, BK=32, 512 thr ===========
// per-stage smem: Ah[128][40] @0, Al @10240, Bh[192][40] @20480, Bl @35840
#define GS_AH 0u
#define GS_AL 10240u
#define GS_BH 20480u
#define GS_BL 35840u
#define G_STAGE 51200u
#define G_SMEM 102400

__device__ __forceinline__ void gemm_load_stage(
    uint32_t sb, int s, int k0, int tid,
    const __half* Ah, const __half* Al, const __half* Bh, const __half* Bl)
{
    uint32_t base = sb + (uint32_t)s * G_STAGE;
    {
        int r = tid >> 2, c = (tid & 3) * 8;
        cp16(base + GS_AH + (uint32_t)(r*80 + c*2), Ah + (size_t)r*DM + k0 + c);
        cp16(base + GS_AL + (uint32_t)(r*80 + c*2), Al + (size_t)r*DM + k0 + c);
    }
    #pragma unroll
    for (int i = 0; i < 2; i++) {
        int f = tid + i*512;
        if (f < 768) {
            int r = f >> 2, c = (f & 3) * 8;
            cp16(base + GS_BH + (uint32_t)(r*80 + c*2), Bh + (size_t)r*DM + k0 + c);
            cp16(base + GS_BL + (uint32_t)(r*80 + c*2), Bl + (size_t)r*DM + k0 + c);
        }
    }
}

__device__ __forceinline__ void gemm_main(
    uint32_t sb, int tid, int lane, int WM, int WN,
    const __half* Ah, const __half* Al, const __half* Bh, const __half* Bl,
    float acc[2][6][4])
{
    gemm_load_stage(sb, 0, 0, tid, Ah, Al, Bh, Bl);
    CP_COMMIT();
    #pragma unroll 1
    for (int ch = 0; ch < 24; ch++) {
        if (ch < 23) {
            gemm_load_stage(sb, (ch+1) & 1, (ch+1)*32, tid, Ah, Al, Bh, Bl);
            CP_COMMIT();
            CP_WAIT1();
        } else {
            CP_WAIT0();
        }
        __syncthreads();
        uint32_t base = sb + (uint32_t)(ch & 1) * G_STAGE;
        #pragma unroll
        for (int ks = 0; ks < 2; ks++) {
            int kk = ks * 16;
            uint32_t ah[2][4], al[2][4], bhf[6][2], blf[6][2];
            #pragma unroll
            for (int mt = 0; mt < 2; mt++) {
                lda_frag(ah[mt], base + GS_AH, WM + mt*16, kk, 40, lane);
                lda_frag(al[mt], base + GS_AL, WM + mt*16, kk, 40, lane);
            }
            #pragma unroll
            for (int nt = 0; nt < 6; nt++) {
                ldb_frag(bhf[nt], base + GS_BH, WN + nt*8, kk, 40, lane);
                ldb_frag(blf[nt], base + GS_BL, WN + nt*8, kk, 40, lane);
            }
            #pragma unroll
            for (int mt = 0; mt < 2; mt++)
                #pragma unroll
                for (int nt = 0; nt < 6; nt++) {
                    mma16816(acc[mt][nt], ah[mt], bhf[nt]);
                    mma16816(acc[mt][nt], al[mt], bhf[nt]);
                    mma16816(acc[mt][nt], ah[mt], blf[nt]);
                }
        }
        __syncthreads();
    }
}

// ---------------- QKV projection ----------------
__global__ void __launch_bounds__(512)
qkv_mma(const float* __restrict__ bq, const float* __restrict__ bk,
        const float* __restrict__ bv)
{
    extern __shared__ __align__(16) char smc[];
    const uint32_t sb = smem_u32(smc);
    const int m0 = blockIdx.x * 128, h = blockIdx.y;
    const int tid = threadIdx.x, lane = tid & 31, w = tid >> 5;
    const int WM = (w >> 2) * 32, WN = (w & 3) * 48;

    float acc[2][6][4];
    #pragma unroll
    for (int mt = 0; mt < 2; mt++)
        #pragma unroll
        for (int nt = 0; nt < 6; nt++)
            #pragma unroll
            for (int c = 0; c < 4; c++) acc[mt][nt][c] = 0.0f;

    gemm_main(sb, tid, lane, WM, WN,
              g_Xh + (size_t)m0*DM, g_Xl + (size_t)m0*DM,
              g_W3h + (size_t)h*192*DM, g_W3l + (size_t)h*192*DM, acc);

    #pragma unroll
    for (int mt = 0; mt < 2; mt++)
        #pragma unroll
        for (int rh = 0; rh < 2; rh++) {
            int m = m0 + WM + mt*16 + (lane >> 2) + rh*8;
            int b = m >> 11, t = m & (TT-1);
            int bhi = b*NH + h;
            #pragma unroll
            for (int nt = 0; nt < 6; nt++) {
                int col = WN + nt*8 + (lane & 3)*2;
                int part = col >> 6, e = col & 63;
                float v0 = acc[mt][nt][rh*2 + 0];
                float v1 = acc[mt][nt][rh*2 + 1];
                if (part == 0)      { v0 += bq[h*HD+e]*QSCALE; v1 += bq[h*HD+e+1]*QSCALE; }
                else if (part == 1) { v0 += bk[h*HD+e];        v1 += bk[h*HD+e+1]; }
                else                { v0 += bv[h*HD+e];        v1 += bv[h*HD+e+1]; }
                if (part < 2) {
                    __half h0,l0,h1,l1;
                    fsplit(v0,h0,l0); fsplit(v1,h1,l1);
                    size_t off = ((size_t)bhi*TT + t)*HD + e;
                    __half* dh = (part == 0) ? g_Qh : g_Kh;
                    __half* dl = (part == 0) ? g_Ql : g_Kl;
                    *(__half2*)(dh + off) = __halves2half2(h0, h1);
                    *(__half2*)(dl + off) = __halves2half2(l0, l1);
                } else {
                    size_t off = ((size_t)bhi*HD + e)*TT + t;
                    g_VTh[off]      = __float2half_rn(v0);
                    g_VTh[off + TT] = __float2half_rn(v1);
                }
            }
        }
}

// ---------------- Output projection ----------------
__global__ void __launch_bounds__(512)
oproj_mma(float* __restrict__ out)
{
    extern __shared__ __align__(16) char smc[];
    const uint32_t sb = smem_u32(smc);
    const int m0 = blockIdx.x * 128, n0g = blockIdx.y * 192;
    const int tid = threadIdx.x, lane = tid & 31, w = tid >> 5;
    const int WM = (w >> 2) * 32, WN = (w & 3) * 48;

    float acc[2][6][4];
    #pragma unroll
    for (int mt = 0; mt < 2; mt++)
        #pragma unroll
        for (int nt = 0; nt < 6; nt++)
            #pragma unroll
            for (int c = 0; c < 4; c++) acc[mt][nt][c] = 0.0f;

    gemm_main(sb, tid, lane, WM, WN,
              g_Ah + (size_t)m0*DM, g_Al + (size_t)m0*DM,
              g_W2Th + (size_t)n0g*DM, g_W2Tl + (size_t)n0g*DM, acc);

    #pragma unroll
    for (int mt = 0; mt < 2; mt++)
        #pragma unroll
        for (int rh = 0; rh < 2; rh++) {
            int m = m0 + WM + mt*16 + (lane >> 2) + rh*8;
            #pragma unroll
            for (int nt = 0; nt < 6; nt++) {
                int col = n0g + WN + nt*8 + (lane & 3)*2;
                float2 v;
                v.x = acc[mt][nt][rh*2 + 0] + g_b2[col];
                v.y = acc[mt][nt][rh*2 + 1] + g_b2[col + 1];
                *(float2*)(out + (size_t)m*DM + col) = v;
            }
        }
}

// ======================= Flash attention (FA2 fragment reuse) ==============
// 512 threads, 16 warps: wm = w>>1 (8 row groups of 16), wn = w&1 (kv half).
// smem: QH 0 [128][72], QL 18432, KH(s) 36864+s*36864, KL(s)=KH+18432,
//       VH(s) 110592+s*17408 [64][136], l2r 145408 (2*128 f32) -> 146432
// End: O partials (2 planes x 32KB = 64KB) overlay offset 0.
#define FQH 0u
#define FQL 18432u
#define FKH(s) (36864u + (uint32_t)(s)*36864u)
#define FKL(s) (FKH(s) + 18432u)
#define FVH(s) (110592u + (uint32_t)(s)*17408u)
#define FL2 145408u
#define F_SMEM 146432

__device__ __forceinline__ void flash_load_kv(uint32_t sb, int s, int kt, int tid,
                                              const __half* Kh, const __half* Kl,
                                              const __half* VTh)
{
    const __half* Khc = Kh + (size_t)kt*128*HD;
    const __half* Klc = Kl + (size_t)kt*128*HD;
    #pragma unroll
    for (int i = 0; i < 2; i++) {
        int f = tid + i*512, r = f >> 3, c = (f & 7) * 8;
        cp16(sb + FKH(s) + (uint32_t)(r*144 + c*2), Khc + (size_t)r*HD + c);
        cp16(sb + FKL(s) + (uint32_t)(r*144 + c*2), Klc + (size_t)r*HD + c);
    }
    #pragma unroll
    for (int i = 0; i < 2; i++) {
        int f = tid + i*512, e = f >> 4, c = (f & 15) * 8;
        cp16(sb + FVH(s) + (uint32_t)(e*272 + c*2), VTh + (size_t)e*TT + kt*128 + c);
    }
}

__global__ void __launch_bounds__(512)
flash_mma()
{
    extern __shared__ __align__(16) char smc[];
    const uint32_t sb = smem_u32(smc);
    const int qt = blockIdx.x, bhid = blockIdx.y;
    const int tid = threadIdx.x, lane = tid & 31, w = tid >> 5;
    const int WM = (w >> 1) * 16, wn = w & 1;

    const __half* Qh = g_Qh + ((size_t)bhid*TT + qt*128)*HD;
    const __half* Ql = g_Ql + ((size_t)bhid*TT + qt*128)*HD;
    const __half* Kh = g_Kh + (size_t)bhid*TT*HD;
    const __half* Kl = g_Kl + (size_t)bhid*TT*HD;
    const __half* VTh = g_VTh + (size_t)bhid*HD*TT;

    #pragma unroll
    for (int i = 0; i < 2; i++) {
        int f = tid + i*512, r = f >> 3, c = (f & 7) * 8;
        cp16(sb + FQH + (uint32_t)(r*144 + c*2), Qh + (size_t)r*HD + c);
        cp16(sb + FQL + (uint32_t)(r*144 + c*2), Ql + (size_t)r*HD + c);
    }
    flash_load_kv(sb, 0, 0, tid, Kh, Kl, VTh);
    CP_COMMIT();

    float oacc[8][4];       // partial O: rows WM..+16, e = nt*8 cols, kv slice wn
    float lreg[2];          // partial l for rows (g, g+8)
    #pragma unroll
    for (int nt = 0; nt < 8; nt++)
        #pragma unroll
        for (int c = 0; c < 4; c++) oacc[nt][c] = 0.0f;
    lreg[0] = 0.0f; lreg[1] = 0.0f;

    #pragma unroll 1
    for (int kt = 0; kt < 16; kt++) {
        if (kt < 15) {
            flash_load_kv(sb, (kt+1) & 1, kt+1, tid, Kh, Kl, VTh);
            CP_COMMIT();
            CP_WAIT1();
        } else {
            CP_WAIT0();
        }
        __syncthreads();
        const int s = kt & 1;

        // --- QK^T: warp S region [WM..WM+16) x [wn*64..+64) ---
        float sacc[8][4];
        #pragma unroll
        for (int nt = 0; nt < 8; nt++)
            #pragma unroll
            for (int c = 0; c < 4; c++) sacc[nt][c] = 0.0f;
        #pragma unroll
        for (int ks = 0; ks < 4; ks++) {
            int kk = ks * 16;
            uint32_t ah[4], al[4], bhf[8][2], blf[8][2];
            lda_frag(ah, sb + FQH, WM, kk, 72, lane);
            lda_frag(al, sb + FQL, WM, kk, 72, lane);
            #pragma unroll
            for (int nt = 0; nt < 8; nt++) {
                ldb_frag(bhf[nt], sb + FKH(s), wn*64 + nt*8, kk, 72, lane);
                ldb_frag(blf[nt], sb + FKL(s), wn*64 + nt*8, kk, 72, lane);
            }
            #pragma unroll
            for (int nt = 0; nt < 8; nt++) {
                mma16816(sacc[nt], ah, bhf[nt]);
                mma16816(sacc[nt], al, bhf[nt]);
                mma16816(sacc[nt], ah, blf[nt]);
            }
        }

        // --- softmax + in-register P->A-frag conversion ---
        uint32_t phalf[4][4];    // [ks][afrag regs]
        #pragma unroll
        for (int nt = 0; nt < 8; nt++) {
            float p0 = fexp2(sacc[nt][0]);
            float p1 = fexp2(sacc[nt][1]);
            float p2 = fexp2(sacc[nt][2]);
            float p3 = fexp2(sacc[nt][3]);
            lreg[0] += p0 + p1;
            lreg[1] += p2 + p3;
            int ks = nt >> 1, half = nt & 1;
            phalf[ks][half*2 + 0] = h2pack(p0, p1);
            phalf[ks][half*2 + 1] = h2pack(p2, p3);
        }

        // --- PV: O += P(frag) * V, k slice wn*64..+64 ---
        #pragma unroll
        for (int ks = 0; ks < 4; ks++) {
            #pragma unroll
            for (int nt = 0; nt < 8; nt++) {
                uint32_t vb[2];
                ldb_frag(vb, sb + FVH(s), nt*8, wn*64 + ks*16, 136, lane);
                mma16816(oacc[nt], phalf[ks], vb);
            }
        }
        __syncthreads();
    }

    // --- l partial store ---
    float* l2r = (float*)(smc + FL2);
    {
        float v0 = lreg[0], v1 = lreg[1];
        v0 += __shfl_xor_sync(0xffffffffu, v0, 1);
        v0 += __shfl_xor_sync(0xffffffffu, v0, 2);
        v1 += __shfl_xor_sync(0xffffffffu, v1, 1);
        v1 += __shfl_xor_sync(0xffffffffu, v1, 2);
        if ((lane & 3) == 0) {
            if (wn == 0) {
                l2r[WM + (lane >> 2)]     = v0;
                l2r[WM + (lane >> 2) + 8] = v1;
            }
        }
        __syncthreads();   // ensure everyone past last PV reads; also l2r init
        if ((lane & 3) == 0 && wn == 1) {
            atomicAdd(&l2r[WM + (lane >> 2)],     v0);
            atomicAdd(&l2r[WM + (lane >> 2) + 8], v1);
        }
    }

    // --- O partial store into smem planes (overlay Q/K area) ---
    float* plane = (float*)(smc + (uint32_t)wn * 32768u);
    #pragma unroll
    for (int nt = 0; nt < 8; nt++)
        #pragma unroll
        for (int rh = 0; rh < 2; rh++) {
            int row = WM + (lane >> 2) + rh*8;
            int e = nt*8 + (lane & 3)*2;
            *(float2*)(plane + row*64 + e) = make_float2(oacc[nt][rh*2], oacc[nt][rh*2+1]);
        }
    __syncthreads();

    // --- final reduce + normalize + split write ---
    const int b = bhid / NH, h = bhid % NH;
    float* pl0 = (float*)smc;
    float* pl1 = (float*)(smc + 32768u);
    #pragma unroll
    for (int it = 0; it < 8; it++) {
        int idx = tid + it*512;       // 4096 half2 cells
        int row = idx >> 5, e2 = (idx & 31) * 2;
        float s0 = pl0[row*64 + e2]     + pl1[row*64 + e2];
        float s1 = pl0[row*64 + e2 + 1] + pl1[row*64 + e2 + 1];
        float inv = 1.0f / l2r[row];
        float v0 = s0 * inv, v1 = s1 * inv;
        __half h0,l0,h1,l1;
        fsplit(v0,h0,l0); fsplit(v1,h1,l1);
        size_t off = ((size_t)(b*TT + qt*128 + row))*DM + h*HD + e2;
        *(__half2*)(g_Ah + off) = __halves2half2(h0, h1);
        *(__half2*)(g_Al + off) = __halves2half2(l0, l1);
    }
}

// ---------------------------------------------------------------------------
extern "C" void kernel_launch(void* const* d_in, const int* in_sizes, int n_in,
                              void* d_out, int out_size)
{
    const float* X    = (const float*)d_in[0];
    const float* Wq   = (const float*)d_in[1];
    const float* bq   = (const float*)d_in[2];
    const float* Wk   = (const float*)d_in[3];
    const float* bk   = (const float*)d_in[4];
    const float* Wv   = (const float*)d_in[5];
    const float* bv   = (const float*)d_in[6];
    const float* Wo   = (const float*)d_in[7];
    const float* bo   = (const float*)d_in[8];
    const float* gate = (const float*)d_in[9];
    float* out = (float*)d_out;

    static int init = 0;
    if (!init) {
        cudaFuncSetAttribute(qkv_mma,   cudaFuncAttributeMaxDynamicSharedMemorySize, G_SMEM);
        cudaFuncSetAttribute(oproj_mma, cudaFuncAttributeMaxDynamicSharedMemorySize, G_SMEM);
        cudaFuncSetAttribute(flash_mma, cudaFuncAttributeMaxDynamicSharedMemorySize, F_SMEM);
        init = 1;
    }

    prep_x<<<MTOT*DM/1024, 256>>>(X);
    prep_w3<<<(NH*192*DM + 255)/256, 256>>>(Wq, Wk, Wv);
    prep_w2<<<(DM*DM + 255)/256, 256>>>(Wo, gate);
    prep_b2<<<(DM + 255)/256, 256>>>(bo, gate);
    qkv_mma<<<dim3(MTOT/128, NH), 512, G_SMEM>>>(bq, bk, bv);
    flash_mma<<<dim3(TT/128, NBH), 512, F_SMEM>>>();
    oproj_mma<<<dim3(MTOT/128, DM/192), 512, G_SMEM>>>(out);
}

// round 8
// speedup vs baseline: 3.2103x; 1.0119x over previous
#include <cuda_runtime.h>
#include <cuda_fp16.h>
#include <cstdint>

#define NH 12
#define TT 2048
#define BB 4
#define DM 768
#define HD 64
#define MTOT (BB*TT)
#define NBH (BB*NH)
#define QSCALE 0.18033688011112042f   // log2(e)/sqrt(64)

// ---------------- global scratch (allocation-free) ----------------
__device__ __half g_Xh[MTOT*DM],  g_Xl[MTOT*DM];        // split input
__device__ __half g_W3h[NH*192*DM], g_W3l[NH*192*DM];   // [h][n=q|k|v*64+e][k]
__device__ __half g_W2Th[DM*DM],    g_W2Tl[DM*DM];      // [n][k], gate folded
__device__ float  g_b2[DM];
__device__ __half g_Qh[NBH*TT*HD], g_Ql[NBH*TT*HD];     // [bh][t][e] (scale folded)
__device__ __half g_Kh[NBH*TT*HD], g_Kl[NBH*TT*HD];     // [bh][t][e]
__device__ __half g_VTh[NBH*HD*TT];                      // [bh][e][t] (hi only)
__device__ __half g_Ah[MTOT*DM],  g_Al[MTOT*DM];        // attn out split [8192][768]

// ---------------- helpers ----------------
__device__ __forceinline__ uint32_t smem_u32(const void* p) {
    uint32_t a;
    asm("{ .reg .u64 t; cvta.to.shared.u64 t, %1; cvt.u32.u64 %0, t; }" : "=r"(a) : "l"(p));
    return a;
}
__device__ __forceinline__ float fexp2(float x) {
    float y; asm("ex2.approx.ftz.f32 %0, %1;" : "=f"(y) : "f"(x)); return y;
}
__device__ __forceinline__ void fsplit(float x, __half& h, __half& l) {
    h = __float2half_rn(x);
    l = __float2half_rn(x - __half2float(h));
}
__device__ __forceinline__ void cp16(uint32_t dst, const void* src) {
    asm volatile("cp.async.cg.shared.global [%0], [%1], 16;" :: "r"(dst), "l"(src));
}
#define CP_COMMIT() asm volatile("cp.async.commit_group;" ::: "memory")
#define CP_WAIT0()  asm volatile("cp.async.wait_group 0;" ::: "memory")
#define CP_WAIT1()  asm volatile("cp.async.wait_group 1;" ::: "memory")

__device__ __forceinline__ void ldsm4(uint32_t* r, uint32_t addr) {
    asm volatile("ldmatrix.sync.aligned.m8n8.x4.shared.b16 {%0,%1,%2,%3}, [%4];"
        : "=r"(r[0]), "=r"(r[1]), "=r"(r[2]), "=r"(r[3]) : "r"(addr));
}
__device__ __forceinline__ void mma16816(float* d, const uint32_t* a, const uint32_t* b) {
    asm volatile("mma.sync.aligned.m16n8k16.row.col.f32.f16.f16.f32 "
        "{%0,%1,%2,%3}, {%4,%5,%6,%7}, {%8,%9}, {%0,%1,%2,%3};"
        : "+f"(d[0]), "+f"(d[1]), "+f"(d[2]), "+f"(d[3])
        : "r"(a[0]), "r"(a[1]), "r"(a[2]), "r"(a[3]), "r"(b[0]), "r"(b[1]));
}
// A fragment (16x16) from row-major [m][k]
__device__ __forceinline__ void lda_frag(uint32_t* r, uint32_t sbase, int m0, int k0,
                                         int pitch, int lane) {
    uint32_t addr = sbase + (uint32_t)(((m0 + (lane & 7) + ((lane >> 3) & 1) * 8) * pitch
                                       + k0 + ((lane >> 4) & 1) * 8) * 2);
    ldsm4(r, addr);
}
// paired B fragments (two adjacent 8-n tiles, 16 k) from row-major [n][k]:
// r[0..1] = b-frag @ n0, r[2..3] = b-frag @ n0+8
__device__ __forceinline__ void ldb_frag2(uint32_t* r, uint32_t sbase, int n0, int k0,
                                          int pitch, int lane) {
    uint32_t addr = sbase + (uint32_t)(((n0 + ((lane >> 4) & 1) * 8 + (lane & 7)) * pitch
                                       + k0 + ((lane >> 3) & 1) * 8) * 2);
    ldsm4(r, addr);
}
__device__ __forceinline__ uint32_t h2pack(float a, float b) {
    __half2 h = __floats2half2_rn(a, b);
    return *(uint32_t*)&h;
}

// ---------------- prep ----------------
__global__ void prep_x(const float* __restrict__ X) {
    int idx = (blockIdx.x * 256 + threadIdx.x) * 4;
    float4 v = *(const float4*)(X + idx);
    __half h0,l0,h1,l1,h2,l2,h3,l3;
    fsplit(v.x,h0,l0); fsplit(v.y,h1,l1); fsplit(v.z,h2,l2); fsplit(v.w,h3,l3);
    *(__half2*)(g_Xh + idx)     = __halves2half2(h0, h1);
    *(__half2*)(g_Xh + idx + 2) = __halves2half2(h2, h3);
    *(__half2*)(g_Xl + idx)     = __halves2half2(l0, l1);
    *(__half2*)(g_Xl + idx + 2) = __halves2half2(l2, l3);
}
__global__ void prep_w3(const float* __restrict__ Wq, const float* __restrict__ Wk,
                        const float* __restrict__ Wv) {
    int idx = blockIdx.x * 256 + threadIdx.x;
    if (idx >= NH*192*DM) return;
    int k = idx % DM;
    int n = (idx / DM) % 192;
    int h = idx / (192*DM);
    int part = n >> 6, e = n & 63;
    const float* W = (part == 0) ? Wq : (part == 1) ? Wk : Wv;
    float v = W[((size_t)h*DM + k)*HD + e];
    if (part == 0) v *= QSCALE;
    __half hh, hl; fsplit(v, hh, hl);
    g_W3h[idx] = hh; g_W3l[idx] = hl;
}
__global__ void prep_w2(const float* __restrict__ Wo, const float* __restrict__ gate) {
    int idx = blockIdx.x * 256 + threadIdx.x;
    if (idx >= DM*DM) return;
    int k = idx % DM, n = idx / DM;
    int h = k >> 6, e = k & 63;
    float g = gate[h]; g = (g < 1e-6f) ? 0.0f : g;
    float v = Wo[((size_t)h*HD + e)*DM + n] * g;
    __half hh, hl; fsplit(v, hh, hl);
    g_W2Th[idx] = hh; g_W2Tl[idx] = hl;
}
__global__ void prep_b2(const float* __restrict__ bo, const float* __restrict__ gate) {
    int d = blockIdx.x * 256 + threadIdx.x;
    if (d >= DM) return;
    float s = 0.0f;
    #pragma unroll
    for (int h = 0; h < NH; h++) {
        float g = gate[h]; g = (g < 1e-6f) ? 0.0f : g;
        s += g * bo[h*DM + d];
    }
    g_b2[d] = s;
}

// ======================= GEMM 128m x 192n, K=768, BK=32, 512 thr ===========
#define GS_AH 0u
#define GS_AL 10240u
#define GS_BH 20480u
#define GS_BL 35840u
#define G_STAGE 51200u
#define G_SMEM 102400

__device__ __forceinline__ void gemm_load_stage(
    uint32_t sb, int s, int k0, int tid,
    const __half* Ah, const __half* Al, const __half* Bh, const __half* Bl)
{
    uint32_t base = sb + (uint32_t)s * G_STAGE;
    {
        int r = tid >> 2, c = (tid & 3) * 8;
        cp16(base + GS_AH + (uint32_t)(r*80 + c*2), Ah + (size_t)r*DM + k0 + c);
        cp16(base + GS_AL + (uint32_t)(r*80 + c*2), Al + (size_t)r*DM + k0 + c);
    }
    #pragma unroll
    for (int i = 0; i < 2; i++) {
        int f = tid + i*512;
        if (f < 768) {
            int r = f >> 2, c = (f & 3) * 8;
            cp16(base + GS_BH + (uint32_t)(r*80 + c*2), Bh + (size_t)r*DM + k0 + c);
            cp16(base + GS_BL + (uint32_t)(r*80 + c*2), Bl + (size_t)r*DM + k0 + c);
        }
    }
}

__device__ __forceinline__ void gemm_main(
    uint32_t sb, int tid, int lane, int WM, int WN,
    const __half* Ah, const __half* Al, const __half* Bh, const __half* Bl,
    float acc[2][6][4])
{
    gemm_load_stage(sb, 0, 0, tid, Ah, Al, Bh, Bl);
    CP_COMMIT();
    #pragma unroll 1
    for (int ch = 0; ch < 24; ch++) {
        if (ch < 23) {
            gemm_load_stage(sb, (ch+1) & 1, (ch+1)*32, tid, Ah, Al, Bh, Bl);
            CP_COMMIT();
            CP_WAIT1();
        } else {
            CP_WAIT0();
        }
        __syncthreads();
        uint32_t base = sb + (uint32_t)(ch & 1) * G_STAGE;
        #pragma unroll
        for (int ks = 0; ks < 2; ks++) {
            int kk = ks * 16;
            uint32_t ah[2][4], al[2][4], bhf[3][4], blf[3][4];
            #pragma unroll
            for (int mt = 0; mt < 2; mt++) {
                lda_frag(ah[mt], base + GS_AH, WM + mt*16, kk, 40, lane);
                lda_frag(al[mt], base + GS_AL, WM + mt*16, kk, 40, lane);
            }
            #pragma unroll
            for (int np = 0; np < 3; np++) {
                ldb_frag2(bhf[np], base + GS_BH, WN + np*16, kk, 40, lane);
                ldb_frag2(blf[np], base + GS_BL, WN + np*16, kk, 40, lane);
            }
            #pragma unroll
            for (int mt = 0; mt < 2; mt++)
                #pragma unroll
                for (int np = 0; np < 3; np++)
                    #pragma unroll
                    for (int hp = 0; hp < 2; hp++) {
                        mma16816(acc[mt][np*2+hp], ah[mt], bhf[np] + hp*2);
                        mma16816(acc[mt][np*2+hp], al[mt], bhf[np] + hp*2);
                        mma16816(acc[mt][np*2+hp], ah[mt], blf[np] + hp*2);
                    }
        }
        __syncthreads();
    }
}

// ---------------- QKV projection ----------------
__global__ void __launch_bounds__(512)
qkv_mma(const float* __restrict__ bq, const float* __restrict__ bk,
        const float* __restrict__ bv)
{
    extern __shared__ __align__(16) char smc[];
    const uint32_t sb = smem_u32(smc);
    const int m0 = blockIdx.x * 128, h = blockIdx.y;
    const int tid = threadIdx.x, lane = tid & 31, w = tid >> 5;
    const int WM = (w >> 2) * 32, WN = (w & 3) * 48;

    float acc[2][6][4];
    #pragma unroll
    for (int mt = 0; mt < 2; mt++)
        #pragma unroll
        for (int nt = 0; nt < 6; nt++)
            #pragma unroll
            for (int c = 0; c < 4; c++) acc[mt][nt][c] = 0.0f;

    gemm_main(sb, tid, lane, WM, WN,
              g_Xh + (size_t)m0*DM, g_Xl + (size_t)m0*DM,
              g_W3h + (size_t)h*192*DM, g_W3l + (size_t)h*192*DM, acc);

    #pragma unroll
    for (int mt = 0; mt < 2; mt++)
        #pragma unroll
        for (int rh = 0; rh < 2; rh++) {
            int m = m0 + WM + mt*16 + (lane >> 2) + rh*8;
            int b = m >> 11, t = m & (TT-1);
            int bhi = b*NH + h;
            #pragma unroll
            for (int nt = 0; nt < 6; nt++) {
                int col = WN + nt*8 + (lane & 3)*2;
                int part = col >> 6, e = col & 63;
                float v0 = acc[mt][nt][rh*2 + 0];
                float v1 = acc[mt][nt][rh*2 + 1];
                if (part == 0)      { v0 += bq[h*HD+e]*QSCALE; v1 += bq[h*HD+e+1]*QSCALE; }
                else if (part == 1) { v0 += bk[h*HD+e];        v1 += bk[h*HD+e+1]; }
                else                { v0 += bv[h*HD+e];        v1 += bv[h*HD+e+1]; }
                if (part < 2) {
                    __half h0,l0,h1,l1;
                    fsplit(v0,h0,l0); fsplit(v1,h1,l1);
                    size_t off = ((size_t)bhi*TT + t)*HD + e;
                    __half* dh = (part == 0) ? g_Qh : g_Kh;
                    __half* dl = (part == 0) ? g_Ql : g_Kl;
                    *(__half2*)(dh + off) = __halves2half2(h0, h1);
                    *(__half2*)(dl + off) = __halves2half2(l0, l1);
                } else {
                    size_t off = ((size_t)bhi*HD + e)*TT + t;
                    g_VTh[off]      = __float2half_rn(v0);
                    g_VTh[off + TT] = __float2half_rn(v1);
                }
            }
        }
}

// ---------------- Output projection ----------------
__global__ void __launch_bounds__(512)
oproj_mma(float* __restrict__ out)
{
    extern __shared__ __align__(16) char smc[];
    const uint32_t sb = smem_u32(smc);
    const int m0 = blockIdx.x * 128, n0g = blockIdx.y * 192;
    const int tid = threadIdx.x, lane = tid & 31, w = tid >> 5;
    const int WM = (w >> 2) * 32, WN = (w & 3) * 48;

    float acc[2][6][4];
    #pragma unroll
    for (int mt = 0; mt < 2; mt++)
        #pragma unroll
        for (int nt = 0; nt < 6; nt++)
            #pragma unroll
            for (int c = 0; c < 4; c++) acc[mt][nt][c] = 0.0f;

    gemm_main(sb, tid, lane, WM, WN,
              g_Ah + (size_t)m0*DM, g_Al + (size_t)m0*DM,
              g_W2Th + (size_t)n0g*DM, g_W2Tl + (size_t)n0g*DM, acc);

    #pragma unroll
    for (int mt = 0; mt < 2; mt++)
        #pragma unroll
        for (int rh = 0; rh < 2; rh++) {
            int m = m0 + WM + mt*16 + (lane >> 2) + rh*8;
            #pragma unroll
            for (int nt = 0; nt < 6; nt++) {
                int col = n0g + WN + nt*8 + (lane & 3)*2;
                float2 v;
                v.x = acc[mt][nt][rh*2 + 0] + g_b2[col];
                v.y = acc[mt][nt][rh*2 + 1] + g_b2[col + 1];
                *(float2*)(out + (size_t)m*DM + col) = v;
            }
        }
}

// ======================= Flash attention (FA2 fragment reuse) ==============
#define FQH 0u
#define FQL 18432u
#define FKH(s) (36864u + (uint32_t)(s)*36864u)
#define FKL(s) (FKH(s) + 18432u)
#define FVH(s) (110592u + (uint32_t)(s)*17408u)
#define FL2 145408u
#define F_SMEM 146432

__device__ __forceinline__ void flash_load_kv(uint32_t sb, int s, int kt, int tid,
                                              const __half* Kh, const __half* Kl,
                                              const __half* VTh)
{
    const __half* Khc = Kh + (size_t)kt*128*HD;
    const __half* Klc = Kl + (size_t)kt*128*HD;
    #pragma unroll
    for (int i = 0; i < 2; i++) {
        int f = tid + i*512, r = f >> 3, c = (f & 7) * 8;
        cp16(sb + FKH(s) + (uint32_t)(r*144 + c*2), Khc + (size_t)r*HD + c);
        cp16(sb + FKL(s) + (uint32_t)(r*144 + c*2), Klc + (size_t)r*HD + c);
    }
    #pragma unroll
    for (int i = 0; i < 2; i++) {
        int f = tid + i*512, e = f >> 4, c = (f & 15) * 8;
        cp16(sb + FVH(s) + (uint32_t)(e*272 + c*2), VTh + (size_t)e*TT + kt*128 + c);
    }
}

__global__ void __launch_bounds__(512)
flash_mma()
{
    extern __shared__ __align__(16) char smc[];
    const uint32_t sb = smem_u32(smc);
    const int qt = blockIdx.x, bhid = blockIdx.y;
    const int tid = threadIdx.x, lane = tid & 31, w = tid >> 5;
    const int WM = (w >> 1) * 16, wn = w & 1;

    const __half* Qh = g_Qh + ((size_t)bhid*TT + qt*128)*HD;
    const __half* Ql = g_Ql + ((size_t)bhid*TT + qt*128)*HD;
    const __half* Kh = g_Kh + (size_t)bhid*TT*HD;
    const __half* Kl = g_Kl + (size_t)bhid*TT*HD;
    const __half* VTh = g_VTh + (size_t)bhid*HD*TT;

    #pragma unroll
    for (int i = 0; i < 2; i++) {
        int f = tid + i*512, r = f >> 3, c = (f & 7) * 8;
        cp16(sb + FQH + (uint32_t)(r*144 + c*2), Qh + (size_t)r*HD + c);
        cp16(sb + FQL + (uint32_t)(r*144 + c*2), Ql + (size_t)r*HD + c);
    }
    flash_load_kv(sb, 0, 0, tid, Kh, Kl, VTh);
    CP_COMMIT();

    float oacc[8][4];
    float lreg[2];
    uint32_t qh[4][4], ql[4][4];    // hoisted Q fragments (loop-invariant)
    #pragma unroll
    for (int nt = 0; nt < 8; nt++)
        #pragma unroll
        for (int c = 0; c < 4; c++) oacc[nt][c] = 0.0f;
    lreg[0] = 0.0f; lreg[1] = 0.0f;

    #pragma unroll 1
    for (int kt = 0; kt < 16; kt++) {
        if (kt < 15) {
            flash_load_kv(sb, (kt+1) & 1, kt+1, tid, Kh, Kl, VTh);
            CP_COMMIT();
            CP_WAIT1();
        } else {
            CP_WAIT0();
        }
        __syncthreads();
        const int s = kt & 1;

        if (kt == 0) {
            #pragma unroll
            for (int ks = 0; ks < 4; ks++) {
                lda_frag(qh[ks], sb + FQH, WM, ks*16, 72, lane);
                lda_frag(ql[ks], sb + FQL, WM, ks*16, 72, lane);
            }
        }

        // --- QK^T: warp S region [WM..WM+16) x [wn*64..+64) ---
        float sacc[8][4];
        #pragma unroll
        for (int nt = 0; nt < 8; nt++)
            #pragma unroll
            for (int c = 0; c < 4; c++) sacc[nt][c] = 0.0f;
        #pragma unroll
        for (int ks = 0; ks < 4; ks++) {
            int kk = ks * 16;
            uint32_t bhf[4][4], blf[4][4];
            #pragma unroll
            for (int np = 0; np < 4; np++) {
                ldb_frag2(bhf[np], sb + FKH(s), wn*64 + np*16, kk, 72, lane);
                ldb_frag2(blf[np], sb + FKL(s), wn*64 + np*16, kk, 72, lane);
            }
            #pragma unroll
            for (int np = 0; np < 4; np++)
                #pragma unroll
                for (int hp = 0; hp < 2; hp++) {
                    mma16816(sacc[np*2+hp], qh[ks], bhf[np] + hp*2);
                    mma16816(sacc[np*2+hp], ql[ks], bhf[np] + hp*2);
                    mma16816(sacc[np*2+hp], qh[ks], blf[np] + hp*2);
                }
        }

        // --- softmax + P->A-frag per ks slice, immediately consumed by PV ---
        #pragma unroll
        for (int ks = 0; ks < 4; ks++) {
            uint32_t pa[4];
            #pragma unroll
            for (int half = 0; half < 2; half++) {
                int nt = ks*2 + half;
                float p0 = fexp2(sacc[nt][0]);
                float p1 = fexp2(sacc[nt][1]);
                float p2 = fexp2(sacc[nt][2]);
                float p3 = fexp2(sacc[nt][3]);
                lreg[0] += p0 + p1;
                lreg[1] += p2 + p3;
                pa[half*2 + 0] = h2pack(p0, p1);
                pa[half*2 + 1] = h2pack(p2, p3);
            }
            #pragma unroll
            for (int np = 0; np < 4; np++) {
                uint32_t vb[4];
                ldb_frag2(vb, sb + FVH(s), np*16, wn*64 + ks*16, 136, lane);
                mma16816(oacc[np*2+0], pa, vb);
                mma16816(oacc[np*2+1], pa, vb + 2);
            }
        }
        __syncthreads();
    }

    // --- l partial store ---
    float* l2r = (float*)(smc + FL2);
    {
        float v0 = lreg[0], v1 = lreg[1];
        v0 += __shfl_xor_sync(0xffffffffu, v0, 1);
        v0 += __shfl_xor_sync(0xffffffffu, v0, 2);
        v1 += __shfl_xor_sync(0xffffffffu, v1, 1);
        v1 += __shfl_xor_sync(0xffffffffu, v1, 2);
        if ((lane & 3) == 0) {
            if (wn == 0) {
                l2r[WM + (lane >> 2)]     = v0;
                l2r[WM + (lane >> 2) + 8] = v1;
            }
        }
        __syncthreads();
        if ((lane & 3) == 0 && wn == 1) {
            atomicAdd(&l2r[WM + (lane >> 2)],     v0);
            atomicAdd(&l2r[WM + (lane >> 2) + 8], v1);
        }
    }

    // --- O partial store into smem planes (overlay Q/K area) ---
    float* plane = (float*)(smc + (uint32_t)wn * 32768u);
    #pragma unroll
    for (int nt = 0; nt < 8; nt++)
        #pragma unroll
        for (int rh = 0; rh < 2; rh++) {
            int row = WM + (lane >> 2) + rh*8;
            int e = nt*8 + (lane & 3)*2;
            *(float2*)(plane + row*64 + e) = make_float2(oacc[nt][rh*2], oacc[nt][rh*2+1]);
        }
    __syncthreads();

    // --- final reduce + normalize + split write ---
    const int b = bhid / NH, h = bhid % NH;
    float* pl0 = (float*)smc;
    float* pl1 = (float*)(smc + 32768u);
    #pragma unroll
    for (int it = 0; it < 8; it++) {
        int idx = tid + it*512;
        int row = idx >> 5, e2 = (idx & 31) * 2;
        float s0 = pl0[row*64 + e2]     + pl1[row*64 + e2];
        float s1 = pl0[row*64 + e2 + 1] + pl1[row*64 + e2 + 1];
        float inv = 1.0f / l2r[row];
        float v0 = s0 * inv, v1 = s1 * inv;
        __half h0,l0,h1,l1;
        fsplit(v0,h0,l0); fsplit(v1,h1,l1);
        size_t off = ((size_t)(b*TT + qt*128 + row))*DM + h*HD + e2;
        *(__half2*)(g_Ah + off) = __halves2half2(h0, h1);
        *(__half2*)(g_Al + off) = __halves2half2(l0, l1);
    }
}

// ---------------------------------------------------------------------------
extern "C" void kernel_launch(void* const* d_in, const int* in_sizes, int n_in,
                              void* d_out, int out_size)
{
    const float* X    = (const float*)d_in[0];
    const float* Wq   = (const float*)d_in[1];
    const float* bq   = (const float*)d_in[2];
    const float* Wk   = (const float*)d_in[3];
    const float* bk   = (const float*)d_in[4];
    const float* Wv   = (const float*)d_in[5];
    const float* bv   = (const float*)d_in[6];
    const float* Wo   = (const float*)d_in[7];
    const float* bo   = (const float*)d_in[8];
    const float* gate = (const float*)d_in[9];
    float* out = (float*)d_out;

    static int init = 0;
    if (!init) {
        cudaFuncSetAttribute(qkv_mma,   cudaFuncAttributeMaxDynamicSharedMemorySize, G_SMEM);
        cudaFuncSetAttribute(oproj_mma, cudaFuncAttributeMaxDynamicSharedMemorySize, G_SMEM);
        cudaFuncSetAttribute(flash_mma, cudaFuncAttributeMaxDynamicSharedMemorySize, F_SMEM);
        init = 1;
    }

    prep_x<<<MTOT*DM/1024, 256>>>(X);
    prep_w3<<<(NH*192*DM + 255)/256, 256>>>(Wq, Wk, Wv);
    prep_w2<<<(DM*DM + 255)/256, 256>>>(Wo, gate);
    prep_b2<<<(DM + 255)/256, 256>>>(bo, gate);
    qkv_mma<<<dim3(MTOT/128, NH), 512, G_SMEM>>>(bq, bk, bv);
    flash_mma<<<dim3(TT/128, NBH), 512, F_SMEM>>>();
    oproj_mma<<<dim3(MTOT/128, DM/192), 512, G_SMEM>>>(out);
}

// round 10
// speedup vs baseline: 4.2639x; 1.3282x over previous
#include <cuda_runtime.h>
#include <cuda_fp16.h>
#include <cstdint>

#define NH 12
#define TT 2048
#define BB 4
#define DM 768
#define HD 64
#define MTOT (BB*TT)
#define NBH (BB*NH)
#define QSCALE 0.18033688011112042f   // log2(e)/sqrt(64)

// ---------------- global scratch (allocation-free) ----------------
__device__ __half g_Xh[MTOT*DM],  g_Xl[MTOT*DM];        // split input
__device__ __half g_W3h[NH*192*DM];                      // [h][n=q|k|v*64+e][k] hi only
__device__ __half g_W2Th[DM*DM];                         // [n][k], gate folded, hi only
__device__ float  g_b2[DM];
__device__ __half g_Qh[NBH*TT*HD], g_Ql[NBH*TT*HD];     // [bh][t][e] (scale folded, split)
__device__ __half g_Kh[NBH*TT*HD];                       // [bh][t][e] hi only
__device__ __half g_VTh[NBH*HD*TT];                      // [bh][e][t] hi only
__device__ __half g_Ah[MTOT*DM],  g_Al[MTOT*DM];        // attn out split [8192][768]

// ---------------- helpers ----------------
__device__ __forceinline__ uint32_t smem_u32(const void* p) {
    uint32_t a;
    asm("{ .reg .u64 t; cvta.to.shared.u64 t, %1; cvt.u32.u64 %0, t; }" : "=r"(a) : "l"(p));
    return a;
}
__device__ __forceinline__ float fexp2(float x) {
    float y; asm("ex2.approx.ftz.f32 %0, %1;" : "=f"(y) : "f"(x)); return y;
}
__device__ __forceinline__ void fsplit(float x, __half& h, __half& l) {
    h = __float2half_rn(x);
    l = __float2half_rn(x - __half2float(h));
}
__device__ __forceinline__ void cp16(uint32_t dst, const void* src) {
    asm volatile("cp.async.cg.shared.global [%0], [%1], 16;" :: "r"(dst), "l"(src));
}
#define CP_COMMIT() asm volatile("cp.async.commit_group;" ::: "memory")
#define CP_WAIT0()  asm volatile("cp.async.wait_group 0;" ::: "memory")
#define CP_WAIT1()  asm volatile("cp.async.wait_group 1;" ::: "memory")

__device__ __forceinline__ void ldsm4(uint32_t* r, uint32_t addr) {
    asm volatile("ldmatrix.sync.aligned.m8n8.x4.shared.b16 {%0,%1,%2,%3}, [%4];"
        : "=r"(r[0]), "=r"(r[1]), "=r"(r[2]), "=r"(r[3]) : "r"(addr));
}
__device__ __forceinline__ void mma16816(float* d, const uint32_t* a, const uint32_t* b) {
    asm volatile("mma.sync.aligned.m16n8k16.row.col.f32.f16.f16.f32 "
        "{%0,%1,%2,%3}, {%4,%5,%6,%7}, {%8,%9}, {%0,%1,%2,%3};"
        : "+f"(d[0]), "+f"(d[1]), "+f"(d[2]), "+f"(d[3])
        : "r"(a[0]), "r"(a[1]), "r"(a[2]), "r"(a[3]), "r"(b[0]), "r"(b[1]));
}
// A fragment (16x16) from row-major [m][k]
__device__ __forceinline__ void lda_frag(uint32_t* r, uint32_t sbase, int m0, int k0,
                                         int pitch, int lane) {
    uint32_t addr = sbase + (uint32_t)(((m0 + (lane & 7) + ((lane >> 3) & 1) * 8) * pitch
                                       + k0 + ((lane >> 4) & 1) * 8) * 2);
    ldsm4(r, addr);
}
// paired B fragments (two adjacent 8-n tiles, 16 k) from row-major [n][k]
__device__ __forceinline__ void ldb_frag2(uint32_t* r, uint32_t sbase, int n0, int k0,
                                          int pitch, int lane) {
    uint32_t addr = sbase + (uint32_t)(((n0 + ((lane >> 4) & 1) * 8 + (lane & 7)) * pitch
                                       + k0 + ((lane >> 3) & 1) * 8) * 2);
    ldsm4(r, addr);
}
__device__ __forceinline__ uint32_t h2pack(float a, float b) {
    __half2 h = __floats2half2_rn(a, b);
    return *(uint32_t*)&h;
}

// ---------------- prep ----------------
__global__ void prep_x(const float* __restrict__ X) {
    int idx = (blockIdx.x * 256 + threadIdx.x) * 4;
    float4 v = *(const float4*)(X + idx);
    __half h0,l0,h1,l1,h2,l2,h3,l3;
    fsplit(v.x,h0,l0); fsplit(v.y,h1,l1); fsplit(v.z,h2,l2); fsplit(v.w,h3,l3);
    *(__half2*)(g_Xh + idx)     = __halves2half2(h0, h1);
    *(__half2*)(g_Xh + idx + 2) = __halves2half2(h2, h3);
    *(__half2*)(g_Xl + idx)     = __halves2half2(l0, l1);
    *(__half2*)(g_Xl + idx + 2) = __halves2half2(l2, l3);
}
__global__ void prep_w3(const float* __restrict__ Wq, const float* __restrict__ Wk,
                        const float* __restrict__ Wv) {
    int idx = blockIdx.x * 256 + threadIdx.x;
    if (idx >= NH*192*DM) return;
    int k = idx % DM;
    int n = (idx / DM) % 192;
    int h = idx / (192*DM);
    int part = n >> 6, e = n & 63;
    const float* W = (part == 0) ? Wq : (part == 1) ? Wk : Wv;
    float v = W[((size_t)h*DM + k)*HD + e];
    if (part == 0) v *= QSCALE;
    g_W3h[idx] = __float2half_rn(v);
}
__global__ void prep_w2(const float* __restrict__ Wo, const float* __restrict__ gate) {
    int idx = blockIdx.x * 256 + threadIdx.x;
    if (idx >= DM*DM) return;
    int k = idx % DM, n = idx / DM;
    int h = k >> 6, e = k & 63;
    float g = gate[h]; g = (g < 1e-6f) ? 0.0f : g;
    g_W2Th[idx] = __float2half_rn(Wo[((size_t)h*HD + e)*DM + n] * g);
}
__global__ void prep_b2(const float* __restrict__ bo, const float* __restrict__ gate) {
    int d = blockIdx.x * 256 + threadIdx.x;
    if (d >= DM) return;
    float s = 0.0f;
    #pragma unroll
    for (int h = 0; h < NH; h++) {
        float g = gate[h]; g = (g < 1e-6f) ? 0.0f : g;
        s += g * bo[h*DM + d];
    }
    g_b2[d] = s;
}

// ======================= GEMM 128m x 192n, K=768, BK=32, 512 thr ===========
// per-stage smem: Ah[128][40] @0, Al @10240, Bh[192][40] @20480  (35840 B)
#define GS_AH 0u
#define GS_AL 10240u
#define GS_BH 20480u
#define G_STAGE 35840u
#define G_SMEM 71680

__device__ __forceinline__ void gemm_load_stage(
    uint32_t sb, int s, int k0, int tid,
    const __half* Ah, const __half* Al, const __half* Bh)
{
    uint32_t base = sb + (uint32_t)s * G_STAGE;
    {
        int r = tid >> 2, c = (tid & 3) * 8;
        cp16(base + GS_AH + (uint32_t)(r*80 + c*2), Ah + (size_t)r*DM + k0 + c);
        cp16(base + GS_AL + (uint32_t)(r*80 + c*2), Al + (size_t)r*DM + k0 + c);
    }
    #pragma unroll
    for (int i = 0; i < 2; i++) {
        int f = tid + i*512;
        if (f < 768) {
            int r = f >> 2, c = (f & 3) * 8;
            cp16(base + GS_BH + (uint32_t)(r*80 + c*2), Bh + (size_t)r*DM + k0 + c);
        }
    }
}

__device__ __forceinline__ void gemm_main(
    uint32_t sb, int tid, int lane, int WM, int WN,
    const __half* Ah, const __half* Al, const __half* Bh,
    float acc[2][6][4])
{
    gemm_load_stage(sb, 0, 0, tid, Ah, Al, Bh);
    CP_COMMIT();
    #pragma unroll 1
    for (int ch = 0; ch < 24; ch++) {
        if (ch < 23) {
            gemm_load_stage(sb, (ch+1) & 1, (ch+1)*32, tid, Ah, Al, Bh);
            CP_COMMIT();
            CP_WAIT1();
        } else {
            CP_WAIT0();
        }
        __syncthreads();
        uint32_t base = sb + (uint32_t)(ch & 1) * G_STAGE;
        #pragma unroll
        for (int ks = 0; ks < 2; ks++) {
            int kk = ks * 16;
            uint32_t ah[2][4], al[2][4], bhf[3][4];
            #pragma unroll
            for (int mt = 0; mt < 2; mt++) {
                lda_frag(ah[mt], base + GS_AH, WM + mt*16, kk, 40, lane);
                lda_frag(al[mt], base + GS_AL, WM + mt*16, kk, 40, lane);
            }
            #pragma unroll
            for (int np = 0; np < 3; np++)
                ldb_frag2(bhf[np], base + GS_BH, WN + np*16, kk, 40, lane);
            #pragma unroll
            for (int mt = 0; mt < 2; mt++)
                #pragma unroll
                for (int np = 0; np < 3; np++)
                    #pragma unroll
                    for (int hp = 0; hp < 2; hp++) {
                        mma16816(acc[mt][np*2+hp], ah[mt], bhf[np] + hp*2);
                        mma16816(acc[mt][np*2+hp], al[mt], bhf[np] + hp*2);
                    }
        }
        __syncthreads();
    }
}

// ---------------- QKV projection ----------------
__global__ void __launch_bounds__(512)
qkv_mma(const float* __restrict__ bq, const float* __restrict__ bk,
        const float* __restrict__ bv)
{
    extern __shared__ __align__(16) char smc[];
    const uint32_t sb = smem_u32(smc);
    const int m0 = blockIdx.x * 128, h = blockIdx.y;
    const int tid = threadIdx.x, lane = tid & 31, w = tid >> 5;
    const int WM = (w >> 2) * 32, WN = (w & 3) * 48;

    float acc[2][6][4];
    #pragma unroll
    for (int mt = 0; mt < 2; mt++)
        #pragma unroll
        for (int nt = 0; nt < 6; nt++)
            #pragma unroll
            for (int c = 0; c < 4; c++) acc[mt][nt][c] = 0.0f;

    gemm_main(sb, tid, lane, WM, WN,
              g_Xh + (size_t)m0*DM, g_Xl + (size_t)m0*DM,
              g_W3h + (size_t)h*192*DM, acc);

    #pragma unroll
    for (int mt = 0; mt < 2; mt++)
        #pragma unroll
        for (int rh = 0; rh < 2; rh++) {
            int m = m0 + WM + mt*16 + (lane >> 2) + rh*8;
            int b = m >> 11, t = m & (TT-1);
            int bhi = b*NH + h;
            #pragma unroll
            for (int nt = 0; nt < 6; nt++) {
                int col = WN + nt*8 + (lane & 3)*2;
                int part = col >> 6, e = col & 63;
                float v0 = acc[mt][nt][rh*2 + 0];
                float v1 = acc[mt][nt][rh*2 + 1];
                if (part == 0)      { v0 += bq[h*HD+e]*QSCALE; v1 += bq[h*HD+e+1]*QSCALE; }
                else if (part == 1) { v0 += bk[h*HD+e];        v1 += bk[h*HD+e+1]; }
                else                { v0 += bv[h*HD+e];        v1 += bv[h*HD+e+1]; }
                if (part == 0) {
                    __half h0,l0,h1,l1;
                    fsplit(v0,h0,l0); fsplit(v1,h1,l1);
                    size_t off = ((size_t)bhi*TT + t)*HD + e;
                    *(__half2*)(g_Qh + off) = __halves2half2(h0, h1);
                    *(__half2*)(g_Ql + off) = __halves2half2(l0, l1);
                } else if (part == 1) {
                    size_t off = ((size_t)bhi*TT + t)*HD + e;
                    *(__half2*)(g_Kh + off) = __floats2half2_rn(v0, v1);
                } else {
                    size_t off = ((size_t)bhi*HD + e)*TT + t;
                    g_VTh[off]      = __float2half_rn(v0);
                    g_VTh[off + TT] = __float2half_rn(v1);
                }
            }
        }
}

// ---------------- Output projection ----------------
__global__ void __launch_bounds__(512)
oproj_mma(float* __restrict__ out)
{
    extern __shared__ __align__(16) char smc[];
    const uint32_t sb = smem_u32(smc);
    const int m0 = blockIdx.x * 128, n0g = blockIdx.y * 192;
    const int tid = threadIdx.x, lane = tid & 31, w = tid >> 5;
    const int WM = (w >> 2) * 32, WN = (w & 3) * 48;

    float acc[2][6][4];
    #pragma unroll
    for (int mt = 0; mt < 2; mt++)
        #pragma unroll
        for (int nt = 0; nt < 6; nt++)
            #pragma unroll
            for (int c = 0; c < 4; c++) acc[mt][nt][c] = 0.0f;

    gemm_main(sb, tid, lane, WM, WN,
              g_Ah + (size_t)m0*DM, g_Al + (size_t)m0*DM,
              g_W2Th + (size_t)n0g*DM, acc);

    #pragma unroll
    for (int mt = 0; mt < 2; mt++)
        #pragma unroll
        for (int rh = 0; rh < 2; rh++) {
            int m = m0 + WM + mt*16 + (lane >> 2) + rh*8;
            #pragma unroll
            for (int nt = 0; nt < 6; nt++) {
                int col = n0g + WN + nt*8 + (lane & 3)*2;
                float2 v;
                v.x = acc[mt][nt][rh*2 + 0] + g_b2[col];
                v.y = acc[mt][nt][rh*2 + 1] + g_b2[col + 1];
                *(float2*)(out + (size_t)m*DM + col) = v;
            }
        }
}

// ======================= Flash attention =======================
// smem: QH 0 [128][72], QL 18432, KH(s) 36864+s*18432 [128][72],
//       VH(s) 73728+s*17408 [64][136], l2r 108544 (2*128 f32) -> 109568
// End: O partials (2 planes x 32KB) overlay offset 0.
#define FQH 0u
#define FQL 18432u
#define FKH(s) (36864u + (uint32_t)(s)*18432u)
#define FVH(s) (73728u + (uint32_t)(s)*17408u)
#define FL2 108544u
#define F_SMEM 109568

__device__ __forceinline__ void flash_load_kv(uint32_t sb, int s, int kt, int tid,
                                              const __half* Kh, const __half* VTh)
{
    const __half* Khc = Kh + (size_t)kt*128*HD;
    #pragma unroll
    for (int i = 0; i < 2; i++) {
        int f = tid + i*512, r = f >> 3, c = (f & 7) * 8;
        cp16(sb + FKH(s) + (uint32_t)(r*144 + c*2), Khc + (size_t)r*HD + c);
    }
    #pragma unroll
    for (int i = 0; i < 2; i++) {
        int f = tid + i*512, e = f >> 4, c = (f & 15) * 8;
        cp16(sb + FVH(s) + (uint32_t)(e*272 + c*2), VTh + (size_t)e*TT + kt*128 + c);
    }
}

__global__ void __launch_bounds__(512)
flash_mma()
{
    extern __shared__ __align__(16) char smc[];
    const uint32_t sb = smem_u32(smc);
    const int qt = blockIdx.x, bhid = blockIdx.y;
    const int tid = threadIdx.x, lane = tid & 31, w = tid >> 5;
    const int WM = (w >> 1) * 16, wn = w & 1;

    const __half* Qh = g_Qh + ((size_t)bhid*TT + qt*128)*HD;
    const __half* Ql = g_Ql + ((size_t)bhid*TT + qt*128)*HD;
    const __half* Kh = g_Kh + (size_t)bhid*TT*HD;
    const __half* VTh = g_VTh + (size_t)bhid*HD*TT;

    #pragma unroll
    for (int i = 0; i < 2; i++) {
        int f = tid + i*512, r = f >> 3, c = (f & 7) * 8;
        cp16(sb + FQH + (uint32_t)(r*144 + c*2), Qh + (size_t)r*HD + c);
        cp16(sb + FQL + (uint32_t)(r*144 + c*2), Ql + (size_t)r*HD + c);
    }
    flash_load_kv(sb, 0, 0, tid, Kh, VTh);
    CP_COMMIT();

    float oacc[8][4];
    float lreg[2];
    uint32_t qh[4][4], ql[4][4];    // hoisted Q fragments
    #pragma unroll
    for (int nt = 0; nt < 8; nt++)
        #pragma unroll
        for (int c = 0; c < 4; c++) oacc[nt][c] = 0.0f;
    lreg[0] = 0.0f; lreg[1] = 0.0f;

    #pragma unroll 1
    for (int kt = 0; kt < 16; kt++) {
        if (kt < 15) {
            flash_load_kv(sb, (kt+1) & 1, kt+1, tid, Kh, VTh);
            CP_COMMIT();
            CP_WAIT1();
        } else {
            CP_WAIT0();
        }
        __syncthreads();
        const int s = kt & 1;

        if (kt == 0) {
            #pragma unroll
            for (int ks = 0; ks < 4; ks++) {
                lda_frag(qh[ks], sb + FQH, WM, ks*16, 72, lane);
                lda_frag(ql[ks], sb + FQL, WM, ks*16, 72, lane);
            }
        }

        // --- QK^T: warp S region [WM..WM+16) x [wn*64..+64), 2 passes ---
        float sacc[8][4];
        #pragma unroll
        for (int nt = 0; nt < 8; nt++)
            #pragma unroll
            for (int c = 0; c < 4; c++) sacc[nt][c] = 0.0f;
        #pragma unroll
        for (int ks = 0; ks < 4; ks++) {
            int kk = ks * 16;
            uint32_t bhf[4][4];
            #pragma unroll
            for (int np = 0; np < 4; np++)
                ldb_frag2(bhf[np], sb + FKH(s), wn*64 + np*16, kk, 72, lane);
            #pragma unroll
            for (int np = 0; np < 4; np++)
                #pragma unroll
                for (int hp = 0; hp < 2; hp++) {
                    mma16816(sacc[np*2+hp], qh[ks], bhf[np] + hp*2);
                    mma16816(sacc[np*2+hp], ql[ks], bhf[np] + hp*2);
                }
        }

        // --- softmax + P->A-frag per ks, immediately consumed by PV ---
        #pragma unroll
        for (int ks = 0; ks < 4; ks++) {
            uint32_t pa[4];
            #pragma unroll
            for (int half = 0; half < 2; half++) {
                int nt = ks*2 + half;
                float p0 = fexp2(sacc[nt][0]);
                float p1 = fexp2(sacc[nt][1]);
                float p2 = fexp2(sacc[nt][2]);
                float p3 = fexp2(sacc[nt][3]);
                lreg[0] += p0 + p1;
                lreg[1] += p2 + p3;
                pa[half*2 + 0] = h2pack(p0, p1);
                pa[half*2 + 1] = h2pack(p2, p3);
            }
            #pragma unroll
            for (int np = 0; np < 4; np++) {
                uint32_t vb[4];
                ldb_frag2(vb, sb + FVH(s), np*16, wn*64 + ks*16, 136, lane);
                mma16816(oacc[np*2+0], pa, vb);
                mma16816(oacc[np*2+1], pa, vb + 2);
            }
        }
        __syncthreads();
    }

    // --- l partial store ---
    float* l2r = (float*)(smc + FL2);
    {
        float v0 = lreg[0], v1 = lreg[1];
        v0 += __shfl_xor_sync(0xffffffffu, v0, 1);
        v0 += __shfl_xor_sync(0xffffffffu, v0, 2);
        v1 += __shfl_xor_sync(0xffffffffu, v1, 1);
        v1 += __shfl_xor_sync(0xffffffffu, v1, 2);
        if ((lane & 3) == 0) {
            if (wn == 0) {
                l2r[WM + (lane >> 2)]     = v0;
                l2r[WM + (lane >> 2) + 8] = v1;
            }
        }
        __syncthreads();
        if ((lane & 3) == 0 && wn == 1) {
            atomicAdd(&l2r[WM + (lane >> 2)],     v0);
            atomicAdd(&l2r[WM + (lane >> 2) + 8], v1);
        }
    }

    // --- O partial store into smem planes (overlay Q/K area) ---
    float* plane = (float*)(smc + (uint32_t)wn * 32768u);
    #pragma unroll
    for (int nt = 0; nt < 8; nt++)
        #pragma unroll
        for (int rh = 0; rh < 2; rh++) {
            int row = WM + (lane >> 2) + rh*8;
            int e = nt*8 + (lane & 3)*2;
            *(float2*)(plane + row*64 + e) = make_float2(oacc[nt][rh*2], oacc[nt][rh*2+1]);
        }
    __syncthreads();

    // --- final reduce + normalize + split write ---
    const int b = bhid / NH, h = bhid % NH;
    float* pl0 = (float*)smc;
    float* pl1 = (float*)(smc + 32768u);
    #pragma unroll
    for (int it = 0; it < 8; it++) {
        int idx = tid + it*512;
        int row = idx >> 5, e2 = (idx & 31) * 2;
        float s0 = pl0[row*64 + e2]     + pl1[row*64 + e2];
        float s1 = pl0[row*64 + e2 + 1] + pl1[row*64 + e2 + 1];
        float inv = 1.0f / l2r[row];
        float v0 = s0 * inv, v1 = s1 * inv;
        __half h0,l0,h1,l1;
        fsplit(v0,h0,l0); fsplit(v1,h1,l1);
        size_t off = ((size_t)(b*TT + qt*128 + row))*DM + h*HD + e2;
        *(__half2*)(g_Ah + off) = __halves2half2(h0, h1);
        *(__half2*)(g_Al + off) = __halves2half2(l0, l1);
    }
}

// ---------------------------------------------------------------------------
extern "C" void kernel_launch(void* const* d_in, const int* in_sizes, int n_in,
                              void* d_out, int out_size)
{
    const float* X    = (const float*)d_in[0];
    const float* Wq   = (const float*)d_in[1];
    const float* bq   = (const float*)d_in[2];
    const float* Wk   = (const float*)d_in[3];
    const float* bk   = (const float*)d_in[4];
    const float* Wv   = (const float*)d_in[5];
    const float* bv   = (const float*)d_in[6];
    const float* Wo   = (const float*)d_in[7];
    const float* bo   = (const float*)d_in[8];
    const float* gate = (const float*)d_in[9];
    float* out = (float*)d_out;

    static int init = 0;
    if (!init) {
        cudaFuncSetAttribute(qkv_mma,   cudaFuncAttributeMaxDynamicSharedMemorySize, G_SMEM);
        cudaFuncSetAttribute(oproj_mma, cudaFuncAttributeMaxDynamicSharedMemorySize, G_SMEM);
        cudaFuncSetAttribute(flash_mma, cudaFuncAttributeMaxDynamicSharedMemorySize, F_SMEM);
        init = 1;
    }

    prep_x<<<MTOT*DM/1024, 256>>>(X);
    prep_w3<<<(NH*192*DM + 255)/256, 256>>>(Wq, Wk, Wv);
    prep_w2<<<(DM*DM + 255)/256, 256>>>(Wo, gate);
    prep_b2<<<(DM + 255)/256, 256>>>(bo, gate);
    qkv_mma<<<dim3(MTOT/128, NH), 512, G_SMEM>>>(bq, bk, bv);
    flash_mma<<<dim3(TT/128, NBH), 512, F_SMEM>>>();
    oproj_mma<<<dim3(MTOT/128, DM/192), 512, G_SMEM>>>(out);
}

// round 11
// speedup vs baseline: 5.2771x; 1.2376x over previous
#include <cuda_runtime.h>
#include <cuda_fp16.h>
#include <cstdint>

#define NH 12
#define TT 2048
#define BB 4
#define DM 768
#define HD 64
#define MTOT (BB*TT)
#define NBH (BB*NH)
#define QSCALE 0.18033688011112042f   // log2(e)/sqrt(64)

// ---------------- global scratch (allocation-free) ----------------
__device__ __half g_Xh[MTOT*DM];                         // fp16 input
__device__ __half g_W3h[NH*192*DM];                      // [h][n=q|k|v*64+e][k]
__device__ __half g_W2Th[DM*DM];                         // [n][k], gate folded
__device__ float  g_b2[DM];
__device__ __half g_Qh[NBH*TT*HD], g_Ql[NBH*TT*HD];     // [bh][t][e] (scale folded, split)
__device__ __half g_Kh[NBH*TT*HD];                       // [bh][t][e]
__device__ __half g_VTh[NBH*HD*TT];                      // [bh][e][t]
__device__ __half g_Ah[MTOT*DM];                         // attn out [8192][768]

// ---------------- helpers ----------------
__device__ __forceinline__ uint32_t smem_u32(const void* p) {
    uint32_t a;
    asm("{ .reg .u64 t; cvta.to.shared.u64 t, %1; cvt.u32.u64 %0, t; }" : "=r"(a) : "l"(p));
    return a;
}
__device__ __forceinline__ float fexp2(float x) {
    float y; asm("ex2.approx.ftz.f32 %0, %1;" : "=f"(y) : "f"(x)); return y;
}
__device__ __forceinline__ void fsplit(float x, __half& h, __half& l) {
    h = __float2half_rn(x);
    l = __float2half_rn(x - __half2float(h));
}
__device__ __forceinline__ void cp16(uint32_t dst, const void* src) {
    asm volatile("cp.async.cg.shared.global [%0], [%1], 16;" :: "r"(dst), "l"(src));
}
#define CP_COMMIT() asm volatile("cp.async.commit_group;" ::: "memory")
#define CP_WAIT0()  asm volatile("cp.async.wait_group 0;" ::: "memory")
#define CP_WAIT1()  asm volatile("cp.async.wait_group 1;" ::: "memory")

__device__ __forceinline__ void ldsm4(uint32_t* r, uint32_t addr) {
    asm volatile("ldmatrix.sync.aligned.m8n8.x4.shared.b16 {%0,%1,%2,%3}, [%4];"
        : "=r"(r[0]), "=r"(r[1]), "=r"(r[2]), "=r"(r[3]) : "r"(addr));
}
__device__ __forceinline__ void mma16816(float* d, const uint32_t* a, const uint32_t* b) {
    asm volatile("mma.sync.aligned.m16n8k16.row.col.f32.f16.f16.f32 "
        "{%0,%1,%2,%3}, {%4,%5,%6,%7}, {%8,%9}, {%0,%1,%2,%3};"
        : "+f"(d[0]), "+f"(d[1]), "+f"(d[2]), "+f"(d[3])
        : "r"(a[0]), "r"(a[1]), "r"(a[2]), "r"(a[3]), "r"(b[0]), "r"(b[1]));
}
// A fragment (16x16) from row-major [m][k]
__device__ __forceinline__ void lda_frag(uint32_t* r, uint32_t sbase, int m0, int k0,
                                         int pitch, int lane) {
    uint32_t addr = sbase + (uint32_t)(((m0 + (lane & 7) + ((lane >> 3) & 1) * 8) * pitch
                                       + k0 + ((lane >> 4) & 1) * 8) * 2);
    ldsm4(r, addr);
}
// paired B fragments (two adjacent 8-n tiles, 16 k) from row-major [n][k]
__device__ __forceinline__ void ldb_frag2(uint32_t* r, uint32_t sbase, int n0, int k0,
                                          int pitch, int lane) {
    uint32_t addr = sbase + (uint32_t)(((n0 + ((lane >> 4) & 1) * 8 + (lane & 7)) * pitch
                                       + k0 + ((lane >> 3) & 1) * 8) * 2);
    ldsm4(r, addr);
}
__device__ __forceinline__ uint32_t h2pack(float a, float b) {
    __half2 h = __floats2half2_rn(a, b);
    return *(uint32_t*)&h;
}

// ---------------- prep ----------------
__global__ void prep_x(const float* __restrict__ X) {
    int idx = (blockIdx.x * 256 + threadIdx.x) * 4;
    float4 v = *(const float4*)(X + idx);
    *(__half2*)(g_Xh + idx)     = __floats2half2_rn(v.x, v.y);
    *(__half2*)(g_Xh + idx + 2) = __floats2half2_rn(v.z, v.w);
}
__global__ void prep_w3(const float* __restrict__ Wq, const float* __restrict__ Wk,
                        const float* __restrict__ Wv) {
    int idx = blockIdx.x * 256 + threadIdx.x;
    if (idx >= NH*192*DM) return;
    int k = idx % DM;
    int n = (idx / DM) % 192;
    int h = idx / (192*DM);
    int part = n >> 6, e = n & 63;
    const float* W = (part == 0) ? Wq : (part == 1) ? Wk : Wv;
    float v = W[((size_t)h*DM + k)*HD + e];
    if (part == 0) v *= QSCALE;
    g_W3h[idx] = __float2half_rn(v);
}
__global__ void prep_w2(const float* __restrict__ Wo, const float* __restrict__ gate) {
    int idx = blockIdx.x * 256 + threadIdx.x;
    if (idx >= DM*DM) return;
    int k = idx % DM, n = idx / DM;
    int h = k >> 6, e = k & 63;
    float g = gate[h]; g = (g < 1e-6f) ? 0.0f : g;
    g_W2Th[idx] = __float2half_rn(Wo[((size_t)h*HD + e)*DM + n] * g);
}
__global__ void prep_b2(const float* __restrict__ bo, const float* __restrict__ gate) {
    int d = blockIdx.x * 256 + threadIdx.x;
    if (d >= DM) return;
    float s = 0.0f;
    #pragma unroll
    for (int h = 0; h < NH; h++) {
        float g = gate[h]; g = (g < 1e-6f) ? 0.0f : g;
        s += g * bo[h*DM + d];
    }
    g_b2[d] = s;
}

// ======================= GEMM 128m x 192n, K=768, BK=32, 512 thr ===========
// per-stage smem: Ah[128][40] @0, Bh[192][40] @10240  (25600 B), 2 stages
#define GS_AH 0u
#define GS_BH 10240u
#define G_STAGE 25600u
#define G_SMEM 51200

__device__ __forceinline__ void gemm_load_stage(
    uint32_t sb, int s, int k0, int tid,
    const __half* Ah, const __half* Bh)
{
    uint32_t base = sb + (uint32_t)s * G_STAGE;
    {
        int r = tid >> 2, c = (tid & 3) * 8;
        cp16(base + GS_AH + (uint32_t)(r*80 + c*2), Ah + (size_t)r*DM + k0 + c);
    }
    #pragma unroll
    for (int i = 0; i < 2; i++) {
        int f = tid + i*512;
        if (f < 768) {
            int r = f >> 2, c = (f & 3) * 8;
            cp16(base + GS_BH + (uint32_t)(r*80 + c*2), Bh + (size_t)r*DM + k0 + c);
        }
    }
}

__device__ __forceinline__ void gemm_main(
    uint32_t sb, int tid, int lane, int WM, int WN,
    const __half* Ah, const __half* Bh,
    float acc[2][6][4])
{
    gemm_load_stage(sb, 0, 0, tid, Ah, Bh);
    CP_COMMIT();
    #pragma unroll 1
    for (int ch = 0; ch < 24; ch++) {
        if (ch < 23) {
            gemm_load_stage(sb, (ch+1) & 1, (ch+1)*32, tid, Ah, Bh);
            CP_COMMIT();
            CP_WAIT1();
        } else {
            CP_WAIT0();
        }
        __syncthreads();
        uint32_t base = sb + (uint32_t)(ch & 1) * G_STAGE;
        #pragma unroll
        for (int ks = 0; ks < 2; ks++) {
            int kk = ks * 16;
            uint32_t ah[2][4], bhf[3][4];
            #pragma unroll
            for (int mt = 0; mt < 2; mt++)
                lda_frag(ah[mt], base + GS_AH, WM + mt*16, kk, 40, lane);
            #pragma unroll
            for (int np = 0; np < 3; np++)
                ldb_frag2(bhf[np], base + GS_BH, WN + np*16, kk, 40, lane);
            #pragma unroll
            for (int mt = 0; mt < 2; mt++)
                #pragma unroll
                for (int np = 0; np < 3; np++)
                    #pragma unroll
                    for (int hp = 0; hp < 2; hp++)
                        mma16816(acc[mt][np*2+hp], ah[mt], bhf[np] + hp*2);
        }
        __syncthreads();
    }
}

// ---------------- QKV projection ----------------
__global__ void __launch_bounds__(512)
qkv_mma(const float* __restrict__ bq, const float* __restrict__ bk,
        const float* __restrict__ bv)
{
    extern __shared__ __align__(16) char smc[];
    const uint32_t sb = smem_u32(smc);
    const int m0 = blockIdx.x * 128, h = blockIdx.y;
    const int tid = threadIdx.x, lane = tid & 31, w = tid >> 5;
    const int WM = (w >> 2) * 32, WN = (w & 3) * 48;

    float acc[2][6][4];
    #pragma unroll
    for (int mt = 0; mt < 2; mt++)
        #pragma unroll
        for (int nt = 0; nt < 6; nt++)
            #pragma unroll
            for (int c = 0; c < 4; c++) acc[mt][nt][c] = 0.0f;

    gemm_main(sb, tid, lane, WM, WN,
              g_Xh + (size_t)m0*DM, g_W3h + (size_t)h*192*DM, acc);

    #pragma unroll
    for (int mt = 0; mt < 2; mt++)
        #pragma unroll
        for (int rh = 0; rh < 2; rh++) {
            int m = m0 + WM + mt*16 + (lane >> 2) + rh*8;
            int b = m >> 11, t = m & (TT-1);
            int bhi = b*NH + h;
            #pragma unroll
            for (int nt = 0; nt < 6; nt++) {
                int col = WN + nt*8 + (lane & 3)*2;
                int part = col >> 6, e = col & 63;
                float v0 = acc[mt][nt][rh*2 + 0];
                float v1 = acc[mt][nt][rh*2 + 1];
                if (part == 0)      { v0 += bq[h*HD+e]*QSCALE; v1 += bq[h*HD+e+1]*QSCALE; }
                else if (part == 1) { v0 += bk[h*HD+e];        v1 += bk[h*HD+e+1]; }
                else                { v0 += bv[h*HD+e];        v1 += bv[h*HD+e+1]; }
                if (part == 0) {
                    __half h0,l0,h1,l1;
                    fsplit(v0,h0,l0); fsplit(v1,h1,l1);
                    size_t off = ((size_t)bhi*TT + t)*HD + e;
                    *(__half2*)(g_Qh + off) = __halves2half2(h0, h1);
                    *(__half2*)(g_Ql + off) = __halves2half2(l0, l1);
                } else if (part == 1) {
                    size_t off = ((size_t)bhi*TT + t)*HD + e;
                    *(__half2*)(g_Kh + off) = __floats2half2_rn(v0, v1);
                } else {
                    size_t off = ((size_t)bhi*HD + e)*TT + t;
                    g_VTh[off]      = __float2half_rn(v0);
                    g_VTh[off + TT] = __float2half_rn(v1);
                }
            }
        }
}

// ---------------- Output projection ----------------
__global__ void __launch_bounds__(512)
oproj_mma(float* __restrict__ out)
{
    extern __shared__ __align__(16) char smc[];
    const uint32_t sb = smem_u32(smc);
    const int m0 = blockIdx.x * 128, n0g = blockIdx.y * 192;
    const int tid = threadIdx.x, lane = tid & 31, w = tid >> 5;
    const int WM = (w >> 2) * 32, WN = (w & 3) * 48;

    float acc[2][6][4];
    #pragma unroll
    for (int mt = 0; mt < 2; mt++)
        #pragma unroll
        for (int nt = 0; nt < 6; nt++)
            #pragma unroll
            for (int c = 0; c < 4; c++) acc[mt][nt][c] = 0.0f;

    gemm_main(sb, tid, lane, WM, WN,
              g_Ah + (size_t)m0*DM, g_W2Th + (size_t)n0g*DM, acc);

    #pragma unroll
    for (int mt = 0; mt < 2; mt++)
        #pragma unroll
        for (int rh = 0; rh < 2; rh++) {
            int m = m0 + WM + mt*16 + (lane >> 2) + rh*8;
            #pragma unroll
            for (int nt = 0; nt < 6; nt++) {
                int col = n0g + WN + nt*8 + (lane & 3)*2;
                float2 v;
                v.x = acc[mt][nt][rh*2 + 0] + g_b2[col];
                v.y = acc[mt][nt][rh*2 + 1] + g_b2[col + 1];
                *(float2*)(out + (size_t)m*DM + col) = v;
            }
        }
}

// ======================= Flash attention =======================
// smem: QH 0 [128][72], QL 18432, KH(s) 36864+s*18432 [128][72],
//       VH(s) 73728+s*17408 [64][136], l2r 108544 (2*128 f32) -> 109568
// End: O partials (2 planes x 32KB) overlay offset 0.
#define FQH 0u
#define FQL 18432u
#define FKH(s) (36864u + (uint32_t)(s)*18432u)
#define FVH(s) (73728u + (uint32_t)(s)*17408u)
#define FL2 108544u
#define F_SMEM 109568

__device__ __forceinline__ void flash_load_kv(uint32_t sb, int s, int kt, int tid,
                                              const __half* Kh, const __half* VTh)
{
    const __half* Khc = Kh + (size_t)kt*128*HD;
    #pragma unroll
    for (int i = 0; i < 2; i++) {
        int f = tid + i*512, r = f >> 3, c = (f & 7) * 8;
        cp16(sb + FKH(s) + (uint32_t)(r*144 + c*2), Khc + (size_t)r*HD + c);
    }
    #pragma unroll
    for (int i = 0; i < 2; i++) {
        int f = tid + i*512, e = f >> 4, c = (f & 15) * 8;
        cp16(sb + FVH(s) + (uint32_t)(e*272 + c*2), VTh + (size_t)e*TT + kt*128 + c);
    }
}

__global__ void __launch_bounds__(512)
flash_mma()
{
    extern __shared__ __align__(16) char smc[];
    const uint32_t sb = smem_u32(smc);
    const int qt = blockIdx.x, bhid = blockIdx.y;
    const int tid = threadIdx.x, lane = tid & 31, w = tid >> 5;
    const int WM = (w >> 1) * 16, wn = w & 1;

    const __half* Qh = g_Qh + ((size_t)bhid*TT + qt*128)*HD;
    const __half* Ql = g_Ql + ((size_t)bhid*TT + qt*128)*HD;
    const __half* Kh = g_Kh + (size_t)bhid*TT*HD;
    const __half* VTh = g_VTh + (size_t)bhid*HD*TT;

    #pragma unroll
    for (int i = 0; i < 2; i++) {
        int f = tid + i*512, r = f >> 3, c = (f & 7) * 8;
        cp16(sb + FQH + (uint32_t)(r*144 + c*2), Qh + (size_t)r*HD + c);
        cp16(sb + FQL + (uint32_t)(r*144 + c*2), Ql + (size_t)r*HD + c);
    }
    flash_load_kv(sb, 0, 0, tid, Kh, VTh);
    CP_COMMIT();

    float oacc[8][4];
    float lreg[2];
    uint32_t qh[4][4], ql[4][4];    // hoisted Q fragments
    #pragma unroll
    for (int nt = 0; nt < 8; nt++)
        #pragma unroll
        for (int c = 0; c < 4; c++) oacc[nt][c] = 0.0f;
    lreg[0] = 0.0f; lreg[1] = 0.0f;

    #pragma unroll 1
    for (int kt = 0; kt < 16; kt++) {
        if (kt < 15) {
            flash_load_kv(sb, (kt+1) & 1, kt+1, tid, Kh, VTh);
            CP_COMMIT();
            CP_WAIT1();
        } else {
            CP_WAIT0();
        }
        __syncthreads();
        const int s = kt & 1;

        if (kt == 0) {
            #pragma unroll
            for (int ks = 0; ks < 4; ks++) {
                lda_frag(qh[ks], sb + FQH, WM, ks*16, 72, lane);
                lda_frag(ql[ks], sb + FQL, WM, ks*16, 72, lane);
            }
        }

        // --- QK^T: warp S region [WM..WM+16) x [wn*64..+64), 2 passes ---
        float sacc[8][4];
        #pragma unroll
        for (int nt = 0; nt < 8; nt++)
            #pragma unroll
            for (int c = 0; c < 4; c++) sacc[nt][c] = 0.0f;
        #pragma unroll
        for (int ks = 0; ks < 4; ks++) {
            int kk = ks * 16;
            uint32_t bhf[4][4];
            #pragma unroll
            for (int np = 0; np < 4; np++)
                ldb_frag2(bhf[np], sb + FKH(s), wn*64 + np*16, kk, 72, lane);
            #pragma unroll
            for (int np = 0; np < 4; np++)
                #pragma unroll
                for (int hp = 0; hp < 2; hp++) {
                    mma16816(sacc[np*2+hp], qh[ks], bhf[np] + hp*2);
                    mma16816(sacc[np*2+hp], ql[ks], bhf[np] + hp*2);
                }
        }

        // --- softmax + P->A-frag per ks, immediately consumed by PV ---
        #pragma unroll
        for (int ks = 0; ks < 4; ks++) {
            uint32_t pa[4];
            #pragma unroll
            for (int half = 0; half < 2; half++) {
                int nt = ks*2 + half;
                float p0 = fexp2(sacc[nt][0]);
                float p1 = fexp2(sacc[nt][1]);
                float p2 = fexp2(sacc[nt][2]);
                float p3 = fexp2(sacc[nt][3]);
                lreg[0] += p0 + p1;
                lreg[1] += p2 + p3;
                pa[half*2 + 0] = h2pack(p0, p1);
                pa[half*2 + 1] = h2pack(p2, p3);
            }
            #pragma unroll
            for (int np = 0; np < 4; np++) {
                uint32_t vb[4];
                ldb_frag2(vb, sb + FVH(s), np*16, wn*64 + ks*16, 136, lane);
                mma16816(oacc[np*2+0], pa, vb);
                mma16816(oacc[np*2+1], pa, vb + 2);
            }
        }
        __syncthreads();
    }

    // --- l partial store ---
    float* l2r = (float*)(smc + FL2);
    {
        float v0 = lreg[0], v1 = lreg[1];
        v0 += __shfl_xor_sync(0xffffffffu, v0, 1);
        v0 += __shfl_xor_sync(0xffffffffu, v0, 2);
        v1 += __shfl_xor_sync(0xffffffffu, v1, 1);
        v1 += __shfl_xor_sync(0xffffffffu, v1, 2);
        if ((lane & 3) == 0) {
            if (wn == 0) {
                l2r[WM + (lane >> 2)]     = v0;
                l2r[WM + (lane >> 2) + 8] = v1;
            }
        }
        __syncthreads();
        if ((lane & 3) == 0 && wn == 1) {
            atomicAdd(&l2r[WM + (lane >> 2)],     v0);
            atomicAdd(&l2r[WM + (lane >> 2) + 8], v1);
        }
    }

    // --- O partial store into smem planes (overlay Q/K area) ---
    float* plane = (float*)(smc + (uint32_t)wn * 32768u);
    #pragma unroll
    for (int nt = 0; nt < 8; nt++)
        #pragma unroll
        for (int rh = 0; rh < 2; rh++) {
            int row = WM + (lane >> 2) + rh*8;
            int e = nt*8 + (lane & 3)*2;
            *(float2*)(plane + row*64 + e) = make_float2(oacc[nt][rh*2], oacc[nt][rh*2+1]);
        }
    __syncthreads();

    // --- final reduce + normalize + fp16 write ---
    const int b = bhid / NH, h = bhid % NH;
    float* pl0 = (float*)smc;
    float* pl1 = (float*)(smc + 32768u);
    #pragma unroll
    for (int it = 0; it < 8; it++) {
        int idx = tid + it*512;
        int row = idx >> 5, e2 = (idx & 31) * 2;
        float s0 = pl0[row*64 + e2]     + pl1[row*64 + e2];
        float s1 = pl0[row*64 + e2 + 1] + pl1[row*64 + e2 + 1];
        float inv = 1.0f / l2r[row];
        size_t off = ((size_t)(b*TT + qt*128 + row))*DM + h*HD + e2;
        *(__half2*)(g_Ah + off) = __floats2half2_rn(s0 * inv, s1 * inv);
    }
}

// ---------------------------------------------------------------------------
extern "C" void kernel_launch(void* const* d_in, const int* in_sizes, int n_in,
                              void* d_out, int out_size)
{
    const float* X    = (const float*)d_in[0];
    const float* Wq   = (const float*)d_in[1];
    const float* bq   = (const float*)d_in[2];
    const float* Wk   = (const float*)d_in[3];
    const float* bk   = (const float*)d_in[4];
    const float* Wv   = (const float*)d_in[5];
    const float* bv   = (const float*)d_in[6];
    const float* Wo   = (const float*)d_in[7];
    const float* bo   = (const float*)d_in[8];
    const float* gate = (const float*)d_in[9];
    float* out = (float*)d_out;

    static int init = 0;
    if (!init) {
        cudaFuncSetAttribute(qkv_mma,   cudaFuncAttributeMaxDynamicSharedMemorySize, G_SMEM);
        cudaFuncSetAttribute(oproj_mma, cudaFuncAttributeMaxDynamicSharedMemorySize, G_SMEM);
        cudaFuncSetAttribute(flash_mma, cudaFuncAttributeMaxDynamicSharedMemorySize, F_SMEM);
        init = 1;
    }

    prep_x<<<MTOT*DM/1024, 256>>>(X);
    prep_w3<<<(NH*192*DM + 255)/256, 256>>>(Wq, Wk, Wv);
    prep_w2<<<(DM*DM + 255)/256, 256>>>(Wo, gate);
    prep_b2<<<(DM + 255)/256, 256>>>(bo, gate);
    qkv_mma<<<dim3(MTOT/128, NH), 512, G_SMEM>>>(bq, bk, bv);
    flash_mma<<<dim3(TT/128, NBH), 512, F_SMEM>>>();
    oproj_mma<<<dim3(MTOT/128, DM/192), 512, G_SMEM>>>(out);
}

// round 13
// speedup vs baseline: 5.9239x; 1.1226x over previous
#include <cuda_runtime.h>
#include <cuda_fp16.h>
#include <cstdint>

#define NH 12
#define TT 2048
#define BB 4
#define DM 768
#define HD 64
#define MTOT (BB*TT)
#define NBH (BB*NH)
#define QSCALE 0.18033688011112042f   // log2(e)/sqrt(64)

// ---------------- global scratch (allocation-free) ----------------
__device__ __half g_Xh[MTOT*DM];                         // fp16 input
__device__ __half g_W3h[NH*192*DM];                      // [h][n=q|k|v*64+e][k]
__device__ __half g_W2Th[DM*DM];                         // [n][k], gate folded
__device__ float  g_b2[DM];
__device__ __half g_Qh[NBH*TT*HD];                       // [bh][t][e] (scale folded)
__device__ __half g_Kh[NBH*TT*HD];                       // [bh][t][e]
__device__ __half g_VTh[NBH*HD*TT];                      // [bh][e][t]
__device__ __half g_Ah[MTOT*DM];                         // attn out [8192][768]

// ---------------- helpers ----------------
__device__ __forceinline__ uint32_t smem_u32(const void* p) {
    uint32_t a;
    asm("{ .reg .u64 t; cvta.to.shared.u64 t, %1; cvt.u32.u64 %0, t; }" : "=r"(a) : "l"(p));
    return a;
}
__device__ __forceinline__ float fexp2(float x) {
    float y; asm("ex2.approx.ftz.f32 %0, %1;" : "=f"(y) : "f"(x)); return y;
}
__device__ __forceinline__ void cp16(uint32_t dst, const void* src) {
    asm volatile("cp.async.cg.shared.global [%0], [%1], 16;" :: "r"(dst), "l"(src));
}
#define CP_COMMIT() asm volatile("cp.async.commit_group;" ::: "memory")
#define CP_WAIT0()  asm volatile("cp.async.wait_group 0;" ::: "memory")
#define CP_WAIT1()  asm volatile("cp.async.wait_group 1;" ::: "memory")

__device__ __forceinline__ void ldsm4(uint32_t* r, uint32_t addr) {
    asm volatile("ldmatrix.sync.aligned.m8n8.x4.shared.b16 {%0,%1,%2,%3}, [%4];"
        : "=r"(r[0]), "=r"(r[1]), "=r"(r[2]), "=r"(r[3]) : "r"(addr));
}
__device__ __forceinline__ void mma16816(float* d, const uint32_t* a, const uint32_t* b) {
    asm volatile("mma.sync.aligned.m16n8k16.row.col.f32.f16.f16.f32 "
        "{%0,%1,%2,%3}, {%4,%5,%6,%7}, {%8,%9}, {%0,%1,%2,%3};"
        : "+f"(d[0]), "+f"(d[1]), "+f"(d[2]), "+f"(d[3])
        : "r"(a[0]), "r"(a[1]), "r"(a[2]), "r"(a[3]), "r"(b[0]), "r"(b[1]));
}
// A fragment (16x16) from row-major [m][k]
__device__ __forceinline__ void lda_frag(uint32_t* r, uint32_t sbase, int m0, int k0,
                                         int pitch, int lane) {
    uint32_t addr = sbase + (uint32_t)(((m0 + (lane & 7) + ((lane >> 3) & 1) * 8) * pitch
                                       + k0 + ((lane >> 4) & 1) * 8) * 2);
    ldsm4(r, addr);
}
// paired B fragments (two adjacent 8-n tiles, 16 k) from row-major [n][k]
__device__ __forceinline__ void ldb_frag2(uint32_t* r, uint32_t sbase, int n0, int k0,
                                          int pitch, int lane) {
    uint32_t addr = sbase + (uint32_t)(((n0 + ((lane >> 4) & 1) * 8 + (lane & 7)) * pitch
                                       + k0 + ((lane >> 3) & 1) * 8) * 2);
    ldsm4(r, addr);
}
__device__ __forceinline__ uint32_t h2pack(float a, float b) {
    __half2 h = __floats2half2_rn(a, b);
    return *(uint32_t*)&h;
}

// ---------------- prep ----------------
__global__ void prep_x(const float* __restrict__ X) {
    int idx = (blockIdx.x * 256 + threadIdx.x) * 4;
    float4 v = *(const float4*)(X + idx);
    *(__half2*)(g_Xh + idx)     = __floats2half2_rn(v.x, v.y);
    *(__half2*)(g_Xh + idx + 2) = __floats2half2_rn(v.z, v.w);
}
__global__ void prep_w3(const float* __restrict__ Wq, const float* __restrict__ Wk,
                        const float* __restrict__ Wv) {
    int idx = blockIdx.x * 256 + threadIdx.x;
    if (idx >= NH*192*DM) return;
    int k = idx % DM;
    int n = (idx / DM) % 192;
    int h = idx / (192*DM);
    int part = n >> 6, e = n & 63;
    const float* W = (part == 0) ? Wq : (part == 1) ? Wk : Wv;
    float v = W[((size_t)h*DM + k)*HD + e];
    if (part == 0) v *= QSCALE;
    g_W3h[idx] = __float2half_rn(v);
}
__global__ void prep_w2(const float* __restrict__ Wo, const float* __restrict__ gate) {
    int idx = blockIdx.x * 256 + threadIdx.x;
    if (idx >= DM*DM) return;
    int k = idx % DM, n = idx / DM;
    int h = k >> 6, e = k & 63;
    float g = gate[h]; g = (g < 1e-6f) ? 0.0f : g;
    g_W2Th[idx] = __float2half_rn(Wo[((size_t)h*HD + e)*DM + n] * g);
}
__global__ void prep_b2(const float* __restrict__ bo, const float* __restrict__ gate) {
    int d = blockIdx.x * 256 + threadIdx.x;
    if (d >= DM) return;
    float s = 0.0f;
    #pragma unroll
    for (int h = 0; h < NH; h++) {
        float g = gate[h]; g = (g < 1e-6f) ? 0.0f : g;
        s += g * bo[h*DM + d];
    }
    g_b2[d] = s;
}

// ======================= GEMM 128m x 192n, K=768, BK=32, 512 thr ===========
// per-stage smem: Ah[128][40] @0, Bh[192][40] @10240  (25600 B), 2 stages
#define GS_AH 0u
#define GS_BH 10240u
#define G_STAGE 25600u
#define G_SMEM 51200

__device__ __forceinline__ void gemm_load_stage(
    uint32_t sb, int s, int k0, int tid,
    const __half* Ah, const __half* Bh)
{
    uint32_t base = sb + (uint32_t)s * G_STAGE;
    {
        int r = tid >> 2, c = (tid & 3) * 8;
        cp16(base + GS_AH + (uint32_t)(r*80 + c*2), Ah + (size_t)r*DM + k0 + c);
    }
    #pragma unroll
    for (int i = 0; i < 2; i++) {
        int f = tid + i*512;
        if (f < 768) {
            int r = f >> 2, c = (f & 3) * 8;
            cp16(base + GS_BH + (uint32_t)(r*80 + c*2), Bh + (size_t)r*DM + k0 + c);
        }
    }
}

__device__ __forceinline__ void gemm_main(
    uint32_t sb, int tid, int lane, int WM, int WN,
    const __half* Ah, const __half* Bh,
    float acc[2][6][4])
{
    gemm_load_stage(sb, 0, 0, tid, Ah, Bh);
    CP_COMMIT();
    #pragma unroll 1
    for (int ch = 0; ch < 24; ch++) {
        if (ch < 23) {
            gemm_load_stage(sb, (ch+1) & 1, (ch+1)*32, tid, Ah, Bh);
            CP_COMMIT();
            CP_WAIT1();
        } else {
            CP_WAIT0();
        }
        __syncthreads();
        uint32_t base = sb + (uint32_t)(ch & 1) * G_STAGE;
        #pragma unroll
        for (int ks = 0; ks < 2; ks++) {
            int kk = ks * 16;
            uint32_t ah[2][4], bhf[3][4];
            #pragma unroll
            for (int mt = 0; mt < 2; mt++)
                lda_frag(ah[mt], base + GS_AH, WM + mt*16, kk, 40, lane);
            #pragma unroll
            for (int np = 0; np < 3; np++)
                ldb_frag2(bhf[np], base + GS_BH, WN + np*16, kk, 40, lane);
            #pragma unroll
            for (int mt = 0; mt < 2; mt++)
                #pragma unroll
                for (int np = 0; np < 3; np++)
                    #pragma unroll
                    for (int hp = 0; hp < 2; hp++)
                        mma16816(acc[mt][np*2+hp], ah[mt], bhf[np] + hp*2);
        }
        __syncthreads();
    }
}

// ---------------- QKV projection ----------------
__global__ void __launch_bounds__(512)
qkv_mma(const float* __restrict__ bq, const float* __restrict__ bk,
        const float* __restrict__ bv)
{
    extern __shared__ __align__(16) char smc[];
    const uint32_t sb = smem_u32(smc);
    const int m0 = blockIdx.x * 128, h = blockIdx.y;
    const int tid = threadIdx.x, lane = tid & 31, w = tid >> 5;
    const int WM = (w >> 2) * 32, WN = (w & 3) * 48;

    float acc[2][6][4];
    #pragma unroll
    for (int mt = 0; mt < 2; mt++)
        #pragma unroll
        for (int nt = 0; nt < 6; nt++)
            #pragma unroll
            for (int c = 0; c < 4; c++) acc[mt][nt][c] = 0.0f;

    gemm_main(sb, tid, lane, WM, WN,
              g_Xh + (size_t)m0*DM, g_W3h + (size_t)h*192*DM, acc);

    #pragma unroll
    for (int mt = 0; mt < 2; mt++)
        #pragma unroll
        for (int rh = 0; rh < 2; rh++) {
            int m = m0 + WM + mt*16 + (lane >> 2) + rh*8;
            int b = m >> 11, t = m & (TT-1);
            int bhi = b*NH + h;
            #pragma unroll
            for (int nt = 0; nt < 6; nt++) {
                int col = WN + nt*8 + (lane & 3)*2;
                int part = col >> 6, e = col & 63;
                float v0 = acc[mt][nt][rh*2 + 0];
                float v1 = acc[mt][nt][rh*2 + 1];
                if (part == 0)      { v0 += bq[h*HD+e]*QSCALE; v1 += bq[h*HD+e+1]*QSCALE; }
                else if (part == 1) { v0 += bk[h*HD+e];        v1 += bk[h*HD+e+1]; }
                else                { v0 += bv[h*HD+e];        v1 += bv[h*HD+e+1]; }
                if (part == 0) {
                    size_t off = ((size_t)bhi*TT + t)*HD + e;
                    *(__half2*)(g_Qh + off) = __floats2half2_rn(v0, v1);
                } else if (part == 1) {
                    size_t off = ((size_t)bhi*TT + t)*HD + e;
                    *(__half2*)(g_Kh + off) = __floats2half2_rn(v0, v1);
                } else {
                    size_t off = ((size_t)bhi*HD + e)*TT + t;
                    g_VTh[off]      = __float2half_rn(v0);
                    g_VTh[off + TT] = __float2half_rn(v1);
                }
            }
        }
}

// ---------------- Output projection ----------------
__global__ void __launch_bounds__(512)
oproj_mma(float* __restrict__ out)
{
    extern __shared__ __align__(16) char smc[];
    const uint32_t sb = smem_u32(smc);
    const int m0 = blockIdx.x * 128, n0g = blockIdx.y * 192;
    const int tid = threadIdx.x, lane = tid & 31, w = tid >> 5;
    const int WM = (w >> 2) * 32, WN = (w & 3) * 48;

    float acc[2][6][4];
    #pragma unroll
    for (int mt = 0; mt < 2; mt++)
        #pragma unroll
        for (int nt = 0; nt < 6; nt++)
            #pragma unroll
            for (int c = 0; c < 4; c++) acc[mt][nt][c] = 0.0f;

    gemm_main(sb, tid, lane, WM, WN,
              g_Ah + (size_t)m0*DM, g_W2Th + (size_t)n0g*DM, acc);

    #pragma unroll
    for (int mt = 0; mt < 2; mt++)
        #pragma unroll
        for (int rh = 0; rh < 2; rh++) {
            int m = m0 + WM + mt*16 + (lane >> 2) + rh*8;
            #pragma unroll
            for (int nt = 0; nt < 6; nt++) {
                int col = n0g + WN + nt*8 + (lane & 3)*2;
                float2 v;
                v.x = acc[mt][nt][rh*2 + 0] + g_b2[col];
                v.y = acc[mt][nt][rh*2 + 1] + g_b2[col + 1];
                *(float2*)(out + (size_t)m*DM + col) = v;
            }
        }
}

// ======================= Flash attention =======================
// smem: QH 0 [128][72] (18432), KH(s) 18432+s*18432 [128][72],
//       VH(s) 55296+s*17408 [64][136], l2r 90112 (2*128 f32) -> 91136
// End: O partials (2 planes x 32KB) overlay offset 0.
#define FQH 0u
#define FKH(s) (18432u + (uint32_t)(s)*18432u)
#define FVH(s) (55296u + (uint32_t)(s)*17408u)
#define FL2 90112u
#define F_SMEM 91136

__device__ __forceinline__ void flash_load_kv(uint32_t sb, int s, int kt, int tid,
                                              const __half* Kh, const __half* VTh)
{
    const __half* Khc = Kh + (size_t)kt*128*HD;
    #pragma unroll
    for (int i = 0; i < 2; i++) {
        int f = tid + i*512, r = f >> 3, c = (f & 7) * 8;
        cp16(sb + FKH(s) + (uint32_t)(r*144 + c*2), Khc + (size_t)r*HD + c);
    }
    #pragma unroll
    for (int i = 0; i < 2; i++) {
        int f = tid + i*512, e = f >> 4, c = (f & 15) * 8;
        cp16(sb + FVH(s) + (uint32_t)(e*272 + c*2), VTh + (size_t)e*TT + kt*128 + c);
    }
}

__global__ void __launch_bounds__(512)
flash_mma()
{
    extern __shared__ __align__(16) char smc[];
    const uint32_t sb = smem_u32(smc);
    const int qt = blockIdx.x, bhid = blockIdx.y;
    const int tid = threadIdx.x, lane = tid & 31, w = tid >> 5;
    const int WM = (w >> 1) * 16, wn = w & 1;

    const __half* Qh = g_Qh + ((size_t)bhid*TT + qt*128)*HD;
    const __half* Kh = g_Kh + (size_t)bhid*TT*HD;
    const __half* VTh = g_VTh + (size_t)bhid*HD*TT;

    {
        int f = tid, r = f >> 3, c = (f & 7) * 8;
        cp16(sb + FQH + (uint32_t)(r*144 + c*2), Qh + (size_t)r*HD + c);
        f = tid + 512; r = f >> 3; c = (f & 7) * 8;
        cp16(sb + FQH + (uint32_t)(r*144 + c*2), Qh + (size_t)r*HD + c);
    }
    flash_load_kv(sb, 0, 0, tid, Kh, VTh);
    CP_COMMIT();

    float oacc[8][4];
    float lreg[2];
    uint32_t qh[4][4];    // hoisted Q fragments
    #pragma unroll
    for (int nt = 0; nt < 8; nt++)
        #pragma unroll
        for (int c = 0; c < 4; c++) oacc[nt][c] = 0.0f;
    lreg[0] = 0.0f; lreg[1] = 0.0f;

    #pragma unroll 1
    for (int kt = 0; kt < 16; kt++) {
        if (kt < 15) {
            flash_load_kv(sb, (kt+1) & 1, kt+1, tid, Kh, VTh);
            CP_COMMIT();
            CP_WAIT1();
        } else {
            CP_WAIT0();
        }
        __syncthreads();
        const int s = kt & 1;

        if (kt == 0) {
            #pragma unroll
            for (int ks = 0; ks < 4; ks++)
                lda_frag(qh[ks], sb + FQH, WM, ks*16, 72, lane);
        }

        // --- QK^T: warp S region [WM..WM+16) x [wn*64..+64), 1 pass ---
        float sacc[8][4];
        #pragma unroll
        for (int nt = 0; nt < 8; nt++)
            #pragma unroll
            for (int c = 0; c < 4; c++) sacc[nt][c] = 0.0f;
        #pragma unroll
        for (int ks = 0; ks < 4; ks++) {
            int kk = ks * 16;
            uint32_t bhf[4][4];
            #pragma unroll
            for (int np = 0; np < 4; np++)
                ldb_frag2(bhf[np], sb + FKH(s), wn*64 + np*16, kk, 72, lane);
            #pragma unroll
            for (int np = 0; np < 4; np++)
                #pragma unroll
                for (int hp = 0; hp < 2; hp++)
                    mma16816(sacc[np*2+hp], qh[ks], bhf[np] + hp*2);
        }

        // --- softmax + P->A-frag per ks, immediately consumed by PV ---
        #pragma unroll
        for (int ks = 0; ks < 4; ks++) {
            uint32_t pa[4];
            #pragma unroll
            for (int half = 0; half < 2; half++) {
                int nt = ks*2 + half;
                float p0 = fexp2(sacc[nt][0]);
                float p1 = fexp2(sacc[nt][1]);
                float p2 = fexp2(sacc[nt][2]);
                float p3 = fexp2(sacc[nt][3]);
                lreg[0] += p0 + p1;
                lreg[1] += p2 + p3;
                pa[half*2 + 0] = h2pack(p0, p1);
                pa[half*2 + 1] = h2pack(p2, p3);
            }
            #pragma unroll
            for (int np = 0; np < 4; np++) {
                uint32_t vb[4];
                ldb_frag2(vb, sb + FVH(s), np*16, wn*64 + ks*16, 136, lane);
                mma16816(oacc[np*2+0], pa, vb);
                mma16816(oacc[np*2+1], pa, vb + 2);
            }
        }
        __syncthreads();
    }

    // --- l partial store ---
    float* l2r = (float*)(smc + FL2);
    {
        float v0 = lreg[0], v1 = lreg[1];
        v0 += __shfl_xor_sync(0xffffffffu, v0, 1);
        v0 += __shfl_xor_sync(0xffffffffu, v0, 2);
        v1 += __shfl_xor_sync(0xffffffffu, v1, 1);
        v1 += __shfl_xor_sync(0xffffffffu, v1, 2);
        if ((lane & 3) == 0) {
            if (wn == 0) {
                l2r[WM + (lane >> 2)]     = v0;
                l2r[WM + (lane >> 2) + 8] = v1;
            }
        }
        __syncthreads();
        if ((lane & 3) == 0 && wn == 1) {
            atomicAdd(&l2r[WM + (lane >> 2)],     v0);
            atomicAdd(&l2r[WM + (lane >> 2) + 8], v1);
        }
    }

    // --- O partial store into smem planes (overlay Q/K area) ---
    float* plane = (float*)(smc + (uint32_t)wn * 32768u);
    #pragma unroll
    for (int nt = 0; nt < 8; nt++)
        #pragma unroll
        for (int rh = 0; rh < 2; rh++) {
            int row = WM + (lane >> 2) + rh*8;
            int e = nt*8 + (lane & 3)*2;
            *(float2*)(plane + row*64 + e) = make_float2(oacc[nt][rh*2], oacc[nt][rh*2+1]);
        }
    __syncthreads();

    // --- final reduce + normalize + fp16 write ---
    const int b = bhid / NH, h = bhid % NH;
    float* pl0 = (float*)smc;
    float* pl1 = (float*)(smc + 32768u);
    #pragma unroll
    for (int it = 0; it < 8; it++) {
        int idx = tid + it*512;
        int row = idx >> 5, e2 = (idx & 31) * 2;
        float s0 = pl0[row*64 + e2]     + pl1[row*64 + e2];
        float s1 = pl0[row*64 + e2 + 1] + pl1[row*64 + e2 + 1];
        float inv = 1.0f / l2r[row];
        size_t off = ((size_t)(b*TT + qt*128 + row))*DM + h*HD + e2;
        *(__half2*)(g_Ah + off) = __floats2half2_rn(s0 * inv, s1 * inv);
    }
}

// ---------------------------------------------------------------------------
extern "C" void kernel_launch(void* const* d_in, const int* in_sizes, int n_in,
                              void* d_out, int out_size)
{
    const float* X    = (const float*)d_in[0];
    const float* Wq   = (const float*)d_in[1];
    const float* bq   = (const float*)d_in[2];
    const float* Wk   = (const float*)d_in[3];
    const float* bk   = (const float*)d_in[4];
    const float* Wv   = (const float*)d_in[5];
    const float* bv   = (const float*)d_in[6];
    const float* Wo   = (const float*)d_in[7];
    const float* bo   = (const float*)d_in[8];
    const float* gate = (const float*)d_in[9];
    float* out = (float*)d_out;

    static int init = 0;
    if (!init) {
        cudaFuncSetAttribute(qkv_mma,   cudaFuncAttributeMaxDynamicSharedMemorySize, G_SMEM);
        cudaFuncSetAttribute(oproj_mma, cudaFuncAttributeMaxDynamicSharedMemorySize, G_SMEM);
        cudaFuncSetAttribute(flash_mma, cudaFuncAttributeMaxDynamicSharedMemorySize, F_SMEM);
        init = 1;
    }

    prep_x<<<MTOT*DM/1024, 256>>>(X);
    prep_w3<<<(NH*192*DM + 255)/256, 256>>>(Wq, Wk, Wv);
    prep_w2<<<(DM*DM + 255)/256, 256>>>(Wo, gate);
    prep_b2<<<(DM + 255)/256, 256>>>(bo, gate);
    qkv_mma<<<dim3(MTOT/128, NH), 512, G_SMEM>>>(bq, bk, bv);
    flash_mma<<<dim3(TT/128, NBH), 512, F_SMEM>>>();
    oproj_mma<<<dim3(MTOT/128, DM/192), 512, G_SMEM>>>(out);
}

// round 15
// speedup vs baseline: 6.5155x; 1.0999x over previous
#include <cuda_runtime.h>
#include <cuda_fp16.h>
#include <cstdint>

#define NH 12
#define TT 2048
#define BB 4
#define DM 768
#define HD 64
#define MTOT (BB*TT)
#define NBH (BB*NH)
#define QSCALE 0.18033688011112042f   // log2(e)/sqrt(64)

// ---------------- global scratch (allocation-free) ----------------
__device__ __half g_Xh[MTOT*DM];                         // fp16 input
__device__ __half g_W3h[NH*192*DM];                      // [h][n=q|k|v*64+e][k]
__device__ __half g_W2Th[DM*DM];                         // [n][k], gate folded
__device__ float  g_b2[DM];
__device__ __half g_Qh[NBH*TT*HD];                       // [bh][t][e] (scale folded)
__device__ __half g_Kh[NBH*TT*HD];                       // [bh][t][e]
__device__ __half g_VTh[NBH*HD*TT];                      // [bh][e][t]
__device__ __half g_Ah[MTOT*DM];                         // attn out [8192][768]

// ---------------- helpers ----------------
__device__ __forceinline__ uint32_t smem_u32(const void* p) {
    uint32_t a;
    asm("{ .reg .u64 t; cvta.to.shared.u64 t, %1; cvt.u32.u64 %0, t; }" : "=r"(a) : "l"(p));
    return a;
}
__device__ __forceinline__ float fexp2(float x) {
    float y; asm("ex2.approx.ftz.f32 %0, %1;" : "=f"(y) : "f"(x)); return y;
}
__device__ __forceinline__ void cp16(uint32_t dst, const void* src) {
    asm volatile("cp.async.cg.shared.global [%0], [%1], 16;" :: "r"(dst), "l"(src));
}
#define CP_COMMIT() asm volatile("cp.async.commit_group;" ::: "memory")
#define CP_WAIT0()  asm volatile("cp.async.wait_group 0;" ::: "memory")
#define CP_WAIT1()  asm volatile("cp.async.wait_group 1;" ::: "memory")

__device__ __forceinline__ void ldsm4(uint32_t* r, uint32_t addr) {
    asm volatile("ldmatrix.sync.aligned.m8n8.x4.shared.b16 {%0,%1,%2,%3}, [%4];"
        : "=r"(r[0]), "=r"(r[1]), "=r"(r[2]), "=r"(r[3]) : "r"(addr));
}
__device__ __forceinline__ void mma16816(float* d, const uint32_t* a, const uint32_t* b) {
    asm volatile("mma.sync.aligned.m16n8k16.row.col.f32.f16.f16.f32 "
        "{%0,%1,%2,%3}, {%4,%5,%6,%7}, {%8,%9}, {%0,%1,%2,%3};"
        : "+f"(d[0]), "+f"(d[1]), "+f"(d[2]), "+f"(d[3])
        : "r"(a[0]), "r"(a[1]), "r"(a[2]), "r"(a[3]), "r"(b[0]), "r"(b[1]));
}
// A fragment (16x16) from row-major [m][k]
__device__ __forceinline__ void lda_frag(uint32_t* r, uint32_t sbase, int m0, int k0,
                                         int pitch, int lane) {
    uint32_t addr = sbase + (uint32_t)(((m0 + (lane & 7) + ((lane >> 3) & 1) * 8) * pitch
                                       + k0 + ((lane >> 4) & 1) * 8) * 2);
    ldsm4(r, addr);
}
// paired B fragments (two adjacent 8-n tiles, 16 k) from row-major [n][k]
__device__ __forceinline__ void ldb_frag2(uint32_t* r, uint32_t sbase, int n0, int k0,
                                          int pitch, int lane) {
    uint32_t addr = sbase + (uint32_t)(((n0 + ((lane >> 4) & 1) * 8 + (lane & 7)) * pitch
                                       + k0 + ((lane >> 3) & 1) * 8) * 2);
    ldsm4(r, addr);
}
__device__ __forceinline__ uint32_t h2pack(float a, float b) {
    __half2 h = __floats2half2_rn(a, b);
    return *(uint32_t*)&h;
}

// ---------------- merged prep (one launch) ----------------
// block ranges: [0,6144) prep_x | [6144,13056) prep_w3 | [13056,15360) prep_w2 | [15360,15363) prep_b2
#define PB_X  6144
#define PB_W3 13056
#define PB_W2 15360
#define PB_TOT 15363

__global__ void prep_all(const float* __restrict__ X,
                         const float* __restrict__ Wq, const float* __restrict__ Wk,
                         const float* __restrict__ Wv, const float* __restrict__ Wo,
                         const float* __restrict__ bo, const float* __restrict__ gate)
{
    int blk = blockIdx.x;
    if (blk < PB_X) {
        int idx = (blk * 256 + threadIdx.x) * 4;
        float4 v = *(const float4*)(X + idx);
        *(__half2*)(g_Xh + idx)     = __floats2half2_rn(v.x, v.y);
        *(__half2*)(g_Xh + idx + 2) = __floats2half2_rn(v.z, v.w);
    } else if (blk < PB_W3) {
        int idx = (blk - PB_X) * 256 + threadIdx.x;
        int k = idx % DM;
        int n = (idx / DM) % 192;
        int h = idx / (192*DM);
        int part = n >> 6, e = n & 63;
        const float* W = (part == 0) ? Wq : (part == 1) ? Wk : Wv;
        float v = W[((size_t)h*DM + k)*HD + e];
        if (part == 0) v *= QSCALE;
        g_W3h[idx] = __float2half_rn(v);
    } else if (blk < PB_W2) {
        int idx = (blk - PB_W3) * 256 + threadIdx.x;
        int k = idx % DM, n = idx / DM;
        int h = k >> 6, e = k & 63;
        float g = gate[h]; g = (g < 1e-6f) ? 0.0f : g;
        g_W2Th[idx] = __float2half_rn(Wo[((size_t)h*HD + e)*DM + n] * g);
    } else {
        int d = (blk - PB_W2) * 256 + threadIdx.x;
        if (d < DM) {
            float s = 0.0f;
            #pragma unroll
            for (int h = 0; h < NH; h++) {
                float g = gate[h]; g = (g < 1e-6f) ? 0.0f : g;
                s += g * bo[h*DM + d];
            }
            g_b2[d] = s;
        }
    }
}

// ======================= GEMM 128m x 192n, K=768, BK=32, 512 thr ===========
// per-stage smem: Ah[128][40] @0, Bh[192][40] @10240  (25600 B), 3 stages
#define GS_AH 0u
#define GS_BH 10240u
#define G_STAGE 25600u
#define G_SMEM 76800

__device__ __forceinline__ void gemm_load_stage(
    uint32_t sb, int s, int k0, int tid,
    const __half* Ah, const __half* Bh)
{
    uint32_t base = sb + (uint32_t)s * G_STAGE;
    {
        int r = tid >> 2, c = (tid & 3) * 8;
        cp16(base + GS_AH + (uint32_t)(r*80 + c*2), Ah + (size_t)r*DM + k0 + c);
    }
    #pragma unroll
    for (int i = 0; i < 2; i++) {
        int f = tid + i*512;
        if (f < 768) {
            int r = f >> 2, c = (f & 3) * 8;
            cp16(base + GS_BH + (uint32_t)(r*80 + c*2), Bh + (size_t)r*DM + k0 + c);
        }
    }
}

__device__ __forceinline__ void gemm_main(
    uint32_t sb, int tid, int lane, int WM, int WN,
    const __half* Ah, const __half* Bh,
    float acc[2][6][4])
{
    gemm_load_stage(sb, 0, 0, tid, Ah, Bh);
    CP_COMMIT();
    gemm_load_stage(sb, 1, 32, tid, Ah, Bh);
    CP_COMMIT();
    int sidx = 0;
    #pragma unroll 1
    for (int ch = 0; ch < 24; ch++) {
        CP_WAIT1();
        __syncthreads();
        if (ch + 2 < 24) {
            int sn = sidx + 2; if (sn >= 3) sn -= 3;
            gemm_load_stage(sb, sn, (ch+2)*32, tid, Ah, Bh);
            CP_COMMIT();
        }
        uint32_t base = sb + (uint32_t)sidx * G_STAGE;
        #pragma unroll
        for (int ks = 0; ks < 2; ks++) {
            int kk = ks * 16;
            uint32_t ah[2][4], bhf[3][4];
            #pragma unroll
            for (int mt = 0; mt < 2; mt++)
                lda_frag(ah[mt], base + GS_AH, WM + mt*16, kk, 40, lane);
            #pragma unroll
            for (int np = 0; np < 3; np++)
                ldb_frag2(bhf[np], base + GS_BH, WN + np*16, kk, 40, lane);
            #pragma unroll
            for (int mt = 0; mt < 2; mt++)
                #pragma unroll
                for (int np = 0; np < 3; np++)
                    #pragma unroll
                    for (int hp = 0; hp < 2; hp++)
                        mma16816(acc[mt][np*2+hp], ah[mt], bhf[np] + hp*2);
        }
        if (++sidx >= 3) sidx = 0;
    }
    __syncthreads();
}

// ---------------- QKV projection ----------------
__global__ void __launch_bounds__(512)
qkv_mma(const float* __restrict__ bq, const float* __restrict__ bk,
        const float* __restrict__ bv)
{
    extern __shared__ __align__(16) char smc[];
    const uint32_t sb = smem_u32(smc);
    const int m0 = blockIdx.x * 128, h = blockIdx.y;
    const int tid = threadIdx.x, lane = tid & 31, w = tid >> 5;
    const int WM = (w >> 2) * 32, WN = (w & 3) * 48;

    float acc[2][6][4];
    #pragma unroll
    for (int mt = 0; mt < 2; mt++)
        #pragma unroll
        for (int nt = 0; nt < 6; nt++)
            #pragma unroll
            for (int c = 0; c < 4; c++) acc[mt][nt][c] = 0.0f;

    gemm_main(sb, tid, lane, WM, WN,
              g_Xh + (size_t)m0*DM, g_W3h + (size_t)h*192*DM, acc);

    #pragma unroll
    for (int mt = 0; mt < 2; mt++)
        #pragma unroll
        for (int rh = 0; rh < 2; rh++) {
            int m = m0 + WM + mt*16 + (lane >> 2) + rh*8;
            int b = m >> 11, t = m & (TT-1);
            int bhi = b*NH + h;
            #pragma unroll
            for (int nt = 0; nt < 6; nt++) {
                int col = WN + nt*8 + (lane & 3)*2;
                int part = col >> 6, e = col & 63;
                float v0 = acc[mt][nt][rh*2 + 0];
                float v1 = acc[mt][nt][rh*2 + 1];
                if (part == 0)      { v0 += bq[h*HD+e]*QSCALE; v1 += bq[h*HD+e+1]*QSCALE; }
                else if (part == 1) { v0 += bk[h*HD+e];        v1 += bk[h*HD+e+1]; }
                else                { v0 += bv[h*HD+e];        v1 += bv[h*HD+e+1]; }
                if (part == 0) {
                    size_t off = ((size_t)bhi*TT + t)*HD + e;
                    *(__half2*)(g_Qh + off) = __floats2half2_rn(v0, v1);
                } else if (part == 1) {
                    size_t off = ((size_t)bhi*TT + t)*HD + e;
                    *(__half2*)(g_Kh + off) = __floats2half2_rn(v0, v1);
                } else {
                    size_t off = ((size_t)bhi*HD + e)*TT + t;
                    g_VTh[off]      = __float2half_rn(v0);
                    g_VTh[off + TT] = __float2half_rn(v1);
                }
            }
        }
}

// ---------------- Output projection ----------------
__global__ void __launch_bounds__(512)
oproj_mma(float* __restrict__ out)
{
    extern __shared__ __align__(16) char smc[];
    const uint32_t sb = smem_u32(smc);
    const int m0 = blockIdx.x * 128, n0g = blockIdx.y * 192;
    const int tid = threadIdx.x, lane = tid & 31, w = tid >> 5;
    const int WM = (w >> 2) * 32, WN = (w & 3) * 48;

    float acc[2][6][4];
    #pragma unroll
    for (int mt = 0; mt < 2; mt++)
        #pragma unroll
        for (int nt = 0; nt < 6; nt++)
            #pragma unroll
            for (int c = 0; c < 4; c++) acc[mt][nt][c] = 0.0f;

    gemm_main(sb, tid, lane, WM, WN,
              g_Ah + (size_t)m0*DM, g_W2Th + (size_t)n0g*DM, acc);

    #pragma unroll
    for (int mt = 0; mt < 2; mt++)
        #pragma unroll
        for (int rh = 0; rh < 2; rh++) {
            int m = m0 + WM + mt*16 + (lane >> 2) + rh*8;
            #pragma unroll
            for (int nt = 0; nt < 6; nt++) {
                int col = n0g + WN + nt*8 + (lane & 3)*2;
                float2 v;
                v.x = acc[mt][nt][rh*2 + 0] + g_b2[col];
                v.y = acc[mt][nt][rh*2 + 1] + g_b2[col + 1];
                *(float2*)(out + (size_t)m*DM + col) = v;
            }
        }
}

// ======================= Flash attention =======================
// smem: QH 0 [128][72] (18432), 3 KV stages @18432 + s*35840:
//   KH(s) = 18432 + s*35840 [128][72], VH(s) = KH(s)+18432 [64][136]
// l2r @125952 (2*128 f32) -> total 126976
// End: O partials (2 planes x 32KB) overlay offset 0.
#define FQH 0u
#define FKH(s) (18432u + (uint32_t)(s)*35840u)
#define FVH(s) (FKH(s) + 18432u)
#define FL2 125952u
#define F_SMEM 126976

__device__ __forceinline__ void flash_load_kv(uint32_t sb, int s, int kt, int tid,
                                              const __half* Kh, const __half* VTh)
{
    const __half* Khc = Kh + (size_t)kt*128*HD;
    #pragma unroll
    for (int i = 0; i < 2; i++) {
        int f = tid + i*512, r = f >> 3, c = (f & 7) * 8;
        cp16(sb + FKH(s) + (uint32_t)(r*144 + c*2), Khc + (size_t)r*HD + c);
    }
    #pragma unroll
    for (int i = 0; i < 2; i++) {
        int f = tid + i*512, e = f >> 4, c = (f & 15) * 8;
        cp16(sb + FVH(s) + (uint32_t)(e*272 + c*2), VTh + (size_t)e*TT + kt*128 + c);
    }
}

__global__ void __launch_bounds__(512)
flash_mma()
{
    extern __shared__ __align__(16) char smc[];
    const uint32_t sb = smem_u32(smc);
    const int qt = blockIdx.x, bhid = blockIdx.y;
    const int tid = threadIdx.x, lane = tid & 31, w = tid >> 5;
    const int WM = (w >> 1) * 16, wn = w & 1;

    const __half* Qh = g_Qh + ((size_t)bhid*TT + qt*128)*HD;
    const __half* Kh = g_Kh + (size_t)bhid*TT*HD;
    const __half* VTh = g_VTh + (size_t)bhid*HD*TT;

    {
        int f = tid, r = f >> 3, c = (f & 7) * 8;
        cp16(sb + FQH + (uint32_t)(r*144 + c*2), Qh + (size_t)r*HD + c);
        f = tid + 512; r = f >> 3; c = (f & 7) * 8;
        cp16(sb + FQH + (uint32_t)(r*144 + c*2), Qh + (size_t)r*HD + c);
    }
    flash_load_kv(sb, 0, 0, tid, Kh, VTh);
    CP_COMMIT();
    flash_load_kv(sb, 1, 1, tid, Kh, VTh);
    CP_COMMIT();

    float oacc[8][4];
    float lreg[2];
    uint32_t qh[4][4];    // hoisted Q fragments
    #pragma unroll
    for (int nt = 0; nt < 8; nt++)
        #pragma unroll
        for (int c = 0; c < 4; c++) oacc[nt][c] = 0.0f;
    lreg[0] = 0.0f; lreg[1] = 0.0f;

    int sidx = 0;
    #pragma unroll 1
    for (int kt = 0; kt < 16; kt++) {
        CP_WAIT1();
        __syncthreads();
        if (kt + 2 < 16) {
            int sn = sidx + 2; if (sn >= 3) sn -= 3;
            flash_load_kv(sb, sn, kt+2, tid, Kh, VTh);
            CP_COMMIT();
        }
        const int s = sidx;

        if (kt == 0) {
            #pragma unroll
            for (int ks = 0; ks < 4; ks++)
                lda_frag(qh[ks], sb + FQH, WM, ks*16, 72, lane);
        }

        // --- QK^T: warp S region [WM..WM+16) x [wn*64..+64), 1 pass ---
        float sacc[8][4];
        #pragma unroll
        for (int nt = 0; nt < 8; nt++)
            #pragma unroll
            for (int c = 0; c < 4; c++) sacc[nt][c] = 0.0f;
        #pragma unroll
        for (int ks = 0; ks < 4; ks++) {
            int kk = ks * 16;
            uint32_t bhf[4][4];
            #pragma unroll
            for (int np = 0; np < 4; np++)
                ldb_frag2(bhf[np], sb + FKH(s), wn*64 + np*16, kk, 72, lane);
            #pragma unroll
            for (int np = 0; np < 4; np++)
                #pragma unroll
                for (int hp = 0; hp < 2; hp++)
                    mma16816(sacc[np*2+hp], qh[ks], bhf[np] + hp*2);
        }

        // --- softmax + P->A-frag per ks, immediately consumed by PV ---
        #pragma unroll
        for (int ks = 0; ks < 4; ks++) {
            uint32_t pa[4];
            #pragma unroll
            for (int half = 0; half < 2; half++) {
                int nt = ks*2 + half;
                float p0 = fexp2(sacc[nt][0]);
                float p1 = fexp2(sacc[nt][1]);
                float p2 = fexp2(sacc[nt][2]);
                float p3 = fexp2(sacc[nt][3]);
                lreg[0] += p0 + p1;
                lreg[1] += p2 + p3;
                pa[half*2 + 0] = h2pack(p0, p1);
                pa[half*2 + 1] = h2pack(p2, p3);
            }
            #pragma unroll
            for (int np = 0; np < 4; np++) {
                uint32_t vb[4];
                ldb_frag2(vb, sb + FVH(s), np*16, wn*64 + ks*16, 136, lane);
                mma16816(oacc[np*2+0], pa, vb);
                mma16816(oacc[np*2+1], pa, vb + 2);
            }
        }
        if (++sidx >= 3) sidx = 0;
    }
    __syncthreads();

    // --- l partial store ---
    float* l2r = (float*)(smc + FL2);
    {
        float v0 = lreg[0], v1 = lreg[1];
        v0 += __shfl_xor_sync(0xffffffffu, v0, 1);
        v0 += __shfl_xor_sync(0xffffffffu, v0, 2);
        v1 += __shfl_xor_sync(0xffffffffu, v1, 1);
        v1 += __shfl_xor_sync(0xffffffffu, v1, 2);
        if ((lane & 3) == 0) {
            if (wn == 0) {
                l2r[WM + (lane >> 2)]     = v0;
                l2r[WM + (lane >> 2) + 8] = v1;
            }
        }
        __syncthreads();
        if ((lane & 3) == 0 && wn == 1) {
            atomicAdd(&l2r[WM + (lane >> 2)],     v0);
            atomicAdd(&l2r[WM + (lane >> 2) + 8], v1);
        }
    }

    // --- O partial store into smem planes (overlay Q/K area) ---
    float* plane = (float*)(smc + (uint32_t)wn * 32768u);
    #pragma unroll
    for (int nt = 0; nt < 8; nt++)
        #pragma unroll
        for (int rh = 0; rh < 2; rh++) {
            int row = WM + (lane >> 2) + rh*8;
            int e = nt*8 + (lane & 3)*2;
            *(float2*)(plane + row*64 + e) = make_float2(oacc[nt][rh*2], oacc[nt][rh*2+1]);
        }
    __syncthreads();

    // --- final reduce + normalize + fp16 write ---
    const int b = bhid / NH, h = bhid % NH;
    float* pl0 = (float*)smc;
    float* pl1 = (float*)(smc + 32768u);
    #pragma unroll
    for (int it = 0; it < 8; it++) {
        int idx = tid + it*512;
        int row = idx >> 5, e2 = (idx & 31) * 2;
        float s0 = pl0[row*64 + e2]     + pl1[row*64 + e2];
        float s1 = pl0[row*64 + e2 + 1] + pl1[row*64 + e2 + 1];
        float inv = 1.0f / l2r[row];
        size_t off = ((size_t)(b*TT + qt*128 + row))*DM + h*HD + e2;
        *(__half2*)(g_Ah + off) = __floats2half2_rn(s0 * inv, s1 * inv);
    }
}

// ---------------------------------------------------------------------------
extern "C" void kernel_launch(void* const* d_in, const int* in_sizes, int n_in,
                              void* d_out, int out_size)
{
    const float* X    = (const float*)d_in[0];
    const float* Wq   = (const float*)d_in[1];
    const float* bq   = (const float*)d_in[2];
    const float* Wk   = (const float*)d_in[3];
    const float* bk   = (const float*)d_in[4];
    const float* Wv   = (const float*)d_in[5];
    const float* bv   = (const float*)d_in[6];
    const float* Wo   = (const float*)d_in[7];
    const float* bo   = (const float*)d_in[8];
    const float* gate = (const float*)d_in[9];
    float* out = (float*)d_out;

    static int init = 0;
    if (!init) {
        cudaFuncSetAttribute(qkv_mma,   cudaFuncAttributeMaxDynamicSharedMemorySize, G_SMEM);
        cudaFuncSetAttribute(oproj_mma, cudaFuncAttributeMaxDynamicSharedMemorySize, G_SMEM);
        cudaFuncSetAttribute(flash_mma, cudaFuncAttributeMaxDynamicSharedMemorySize, F_SMEM);
        init = 1;
    }

    prep_all<<<PB_TOT, 256>>>(X, Wq, Wk, Wv, Wo, bo, gate);
    qkv_mma<<<dim3(MTOT/128, NH), 512, G_SMEM>>>(bq, bk, bv);
    flash_mma<<<dim3(TT/128, NBH), 512, F_SMEM>>>();
    oproj_mma<<<dim3(MTOT/128, DM/192), 512, G_SMEM>>>(out);
}

// round 16
// speedup vs baseline: 6.9071x; 1.0601x over previous
#include <cuda_runtime.h>
#include <cuda_fp16.h>
#include <cstdint>

#define NH 12
#define TT 2048
#define BB 4
#define DM 768
#define HD 64
#define MTOT (BB*TT)
#define NBH (BB*NH)
#define QSCALE 0.18033688011112042f   // log2(e)/sqrt(64)

// ---------------- global scratch (allocation-free) ----------------
__device__ __half g_Xh[MTOT*DM];                         // fp16 input
__device__ __half g_W3h[NH*192*DM];                      // [h][n=q|k|v*64+e][k]
__device__ __half g_W2Th[DM*DM];                         // [n][k], gate folded
__device__ float  g_b2[DM];
__device__ __half g_Qh[NBH*TT*HD];                       // [bh][t][e] (scale folded)
__device__ __half g_Kh[NBH*TT*HD];                       // [bh][t][e]
__device__ __half g_VTh[NBH*HD*TT];                      // [bh][e][t]
__device__ __half g_Ah[MTOT*DM];                         // attn out [8192][768]

// ---------------- helpers ----------------
__device__ __forceinline__ uint32_t smem_u32(const void* p) {
    uint32_t a;
    asm("{ .reg .u64 t; cvta.to.shared.u64 t, %1; cvt.u32.u64 %0, t; }" : "=r"(a) : "l"(p));
    return a;
}
__device__ __forceinline__ float fexp2(float x) {
    float y; asm("ex2.approx.ftz.f32 %0, %1;" : "=f"(y) : "f"(x)); return y;
}
__device__ __forceinline__ void cp16(uint32_t dst, const void* src) {
    asm volatile("cp.async.cg.shared.global [%0], [%1], 16;" :: "r"(dst), "l"(src));
}
#define CP_COMMIT() asm volatile("cp.async.commit_group;" ::: "memory")
#define CP_WAIT0()  asm volatile("cp.async.wait_group 0;" ::: "memory")
#define CP_WAIT1()  asm volatile("cp.async.wait_group 1;" ::: "memory")

__device__ __forceinline__ void ldsm4(uint32_t* r, uint32_t addr) {
    asm volatile("ldmatrix.sync.aligned.m8n8.x4.shared.b16 {%0,%1,%2,%3}, [%4];"
        : "=r"(r[0]), "=r"(r[1]), "=r"(r[2]), "=r"(r[3]) : "r"(addr));
}
__device__ __forceinline__ void mma16816(float* d, const uint32_t* a, const uint32_t* b) {
    asm volatile("mma.sync.aligned.m16n8k16.row.col.f32.f16.f16.f32 "
        "{%0,%1,%2,%3}, {%4,%5,%6,%7}, {%8,%9}, {%0,%1,%2,%3};"
        : "+f"(d[0]), "+f"(d[1]), "+f"(d[2]), "+f"(d[3])
        : "r"(a[0]), "r"(a[1]), "r"(a[2]), "r"(a[3]), "r"(b[0]), "r"(b[1]));
}
// A fragment (16x16) from row-major [m][k]
__device__ __forceinline__ void lda_frag(uint32_t* r, uint32_t sbase, int m0, int k0,
                                         int pitch, int lane) {
    uint32_t addr = sbase + (uint32_t)(((m0 + (lane & 7) + ((lane >> 3) & 1) * 8) * pitch
                                       + k0 + ((lane >> 4) & 1) * 8) * 2);
    ldsm4(r, addr);
}
// paired B fragments (two adjacent 8-n tiles, 16 k) from row-major [n][k]
__device__ __forceinline__ void ldb_frag2(uint32_t* r, uint32_t sbase, int n0, int k0,
                                          int pitch, int lane) {
    uint32_t addr = sbase + (uint32_t)(((n0 + ((lane >> 4) & 1) * 8 + (lane & 7)) * pitch
                                       + k0 + ((lane >> 3) & 1) * 8) * 2);
    ldsm4(r, addr);
}
__device__ __forceinline__ uint32_t h2pack(float a, float b) {
    __half2 h = __floats2half2_rn(a, b);
    return *(uint32_t*)&h;
}

// ---------------- merged prep (one launch) ----------------
#define PB_X  6144
#define PB_W3 13056
#define PB_W2 15360
#define PB_TOT 15363

__global__ void prep_all(const float* __restrict__ X,
                         const float* __restrict__ Wq, const float* __restrict__ Wk,
                         const float* __restrict__ Wv, const float* __restrict__ Wo,
                         const float* __restrict__ bo, const float* __restrict__ gate)
{
    int blk = blockIdx.x;
    if (blk < PB_X) {
        int idx = (blk * 256 + threadIdx.x) * 4;
        float4 v = *(const float4*)(X + idx);
        *(__half2*)(g_Xh + idx)     = __floats2half2_rn(v.x, v.y);
        *(__half2*)(g_Xh + idx + 2) = __floats2half2_rn(v.z, v.w);
    } else if (blk < PB_W3) {
        int idx = (blk - PB_X) * 256 + threadIdx.x;
        int k = idx % DM;
        int n = (idx / DM) % 192;
        int h = idx / (192*DM);
        int part = n >> 6, e = n & 63;
        const float* W = (part == 0) ? Wq : (part == 1) ? Wk : Wv;
        float v = W[((size_t)h*DM + k)*HD + e];
        if (part == 0) v *= QSCALE;
        g_W3h[idx] = __float2half_rn(v);
    } else if (blk < PB_W2) {
        int idx = (blk - PB_W3) * 256 + threadIdx.x;
        int k = idx % DM, n = idx / DM;
        int h = k >> 6, e = k & 63;
        float g = gate[h]; g = (g < 1e-6f) ? 0.0f : g;
        g_W2Th[idx] = __float2half_rn(Wo[((size_t)h*HD + e)*DM + n] * g);
    } else {
        int d = (blk - PB_W2) * 256 + threadIdx.x;
        if (d < DM) {
            float s = 0.0f;
            #pragma unroll
            for (int h = 0; h < NH; h++) {
                float g = gate[h]; g = (g < 1e-6f) ? 0.0f : g;
                s += g * bo[h*DM + d];
            }
            g_b2[d] = s;
        }
    }
}

// ============== GEMM 128m x 96n, K=768, BK=32, 256 thr, 3 CTAs/SM ==========
// per-stage smem: Ah[128][40] @0 (10240), Bh[96][40] @10240 (7680) = 17920, x3
#define GS_AH 0u
#define GS_BH 10240u
#define G_STAGE 17920u
#define G_SMEM 53760

__device__ __forceinline__ void gemm_load_stage(
    uint32_t sb, int s, int k0, int tid,
    const __half* Ah, const __half* Bh)
{
    uint32_t base = sb + (uint32_t)s * G_STAGE;
    #pragma unroll
    for (int i = 0; i < 2; i++) {
        int f = tid + i*256;
        int r = f >> 2, c = (f & 3) * 8;
        cp16(base + GS_AH + (uint32_t)(r*80 + c*2), Ah + (size_t)r*DM + k0 + c);
    }
    {
        int f = tid;
        int r = f >> 2, c = (f & 3) * 8;
        cp16(base + GS_BH + (uint32_t)(r*80 + c*2), Bh + (size_t)r*DM + k0 + c);
    }
    if (tid < 128) {
        int f = tid + 256;
        int r = f >> 2, c = (f & 3) * 8;
        cp16(base + GS_BH + (uint32_t)(r*80 + c*2), Bh + (size_t)r*DM + k0 + c);
    }
}

__device__ __forceinline__ void gemm_main(
    uint32_t sb, int tid, int lane, int WM, int WN,
    const __half* Ah, const __half* Bh,
    float acc[2][6][4])
{
    gemm_load_stage(sb, 0, 0, tid, Ah, Bh);
    CP_COMMIT();
    gemm_load_stage(sb, 1, 32, tid, Ah, Bh);
    CP_COMMIT();
    int sidx = 0;
    #pragma unroll 1
    for (int ch = 0; ch < 24; ch++) {
        CP_WAIT1();
        __syncthreads();
        if (ch + 2 < 24) {
            int sn = sidx + 2; if (sn >= 3) sn -= 3;
            gemm_load_stage(sb, sn, (ch+2)*32, tid, Ah, Bh);
            CP_COMMIT();
        }
        uint32_t base = sb + (uint32_t)sidx * G_STAGE;
        #pragma unroll
        for (int ks = 0; ks < 2; ks++) {
            int kk = ks * 16;
            uint32_t ah[2][4], bhf[3][4];
            #pragma unroll
            for (int mt = 0; mt < 2; mt++)
                lda_frag(ah[mt], base + GS_AH, WM + mt*16, kk, 40, lane);
            #pragma unroll
            for (int np = 0; np < 3; np++)
                ldb_frag2(bhf[np], base + GS_BH, WN + np*16, kk, 40, lane);
            #pragma unroll
            for (int mt = 0; mt < 2; mt++)
                #pragma unroll
                for (int np = 0; np < 3; np++)
                    #pragma unroll
                    for (int hp = 0; hp < 2; hp++)
                        mma16816(acc[mt][np*2+hp], ah[mt], bhf[np] + hp*2);
        }
        if (++sidx >= 3) sidx = 0;
    }
    __syncthreads();
}

// ---------------- QKV projection: grid (64, 12, 2), n-split 96 -------------
__global__ void __launch_bounds__(256, 3)
qkv_mma(const float* __restrict__ bq, const float* __restrict__ bk,
        const float* __restrict__ bv)
{
    extern __shared__ __align__(16) char smc[];
    const uint32_t sb = smem_u32(smc);
    const int m0 = blockIdx.x * 128, h = blockIdx.y;
    const int n0g = blockIdx.z * 96;
    const int tid = threadIdx.x, lane = tid & 31, w = tid >> 5;
    const int WM = (w >> 1) * 32, WN = (w & 1) * 48;

    float acc[2][6][4];
    #pragma unroll
    for (int mt = 0; mt < 2; mt++)
        #pragma unroll
        for (int nt = 0; nt < 6; nt++)
            #pragma unroll
            for (int c = 0; c < 4; c++) acc[mt][nt][c] = 0.0f;

    gemm_main(sb, tid, lane, WM, WN,
              g_Xh + (size_t)m0*DM, g_W3h + (size_t)h*192*DM + (size_t)n0g*DM, acc);

    #pragma unroll
    for (int mt = 0; mt < 2; mt++)
        #pragma unroll
        for (int rh = 0; rh < 2; rh++) {
            int m = m0 + WM + mt*16 + (lane >> 2) + rh*8;
            int b = m >> 11, t = m & (TT-1);
            int bhi = b*NH + h;
            #pragma unroll
            for (int nt = 0; nt < 6; nt++) {
                int col = n0g + WN + nt*8 + (lane & 3)*2;
                int part = col >> 6, e = col & 63;
                float v0 = acc[mt][nt][rh*2 + 0];
                float v1 = acc[mt][nt][rh*2 + 1];
                if (part == 0)      { v0 += bq[h*HD+e]*QSCALE; v1 += bq[h*HD+e+1]*QSCALE; }
                else if (part == 1) { v0 += bk[h*HD+e];        v1 += bk[h*HD+e+1]; }
                else                { v0 += bv[h*HD+e];        v1 += bv[h*HD+e+1]; }
                if (part == 0) {
                    size_t off = ((size_t)bhi*TT + t)*HD + e;
                    *(__half2*)(g_Qh + off) = __floats2half2_rn(v0, v1);
                } else if (part == 1) {
                    size_t off = ((size_t)bhi*TT + t)*HD + e;
                    *(__half2*)(g_Kh + off) = __floats2half2_rn(v0, v1);
                } else {
                    size_t off = ((size_t)bhi*HD + e)*TT + t;
                    g_VTh[off]      = __float2half_rn(v0);
                    g_VTh[off + TT] = __float2half_rn(v1);
                }
            }
        }
}

// ---------------- Output projection: grid (64, 8), n-split 96 --------------
__global__ void __launch_bounds__(256, 3)
oproj_mma(float* __restrict__ out)
{
    extern __shared__ __align__(16) char smc[];
    const uint32_t sb = smem_u32(smc);
    const int m0 = blockIdx.x * 128, n0g = blockIdx.y * 96;
    const int tid = threadIdx.x, lane = tid & 31, w = tid >> 5;
    const int WM = (w >> 1) * 32, WN = (w & 1) * 48;

    float acc[2][6][4];
    #pragma unroll
    for (int mt = 0; mt < 2; mt++)
        #pragma unroll
        for (int nt = 0; nt < 6; nt++)
            #pragma unroll
            for (int c = 0; c < 4; c++) acc[mt][nt][c] = 0.0f;

    gemm_main(sb, tid, lane, WM, WN,
              g_Ah + (size_t)m0*DM, g_W2Th + (size_t)n0g*DM, acc);

    #pragma unroll
    for (int mt = 0; mt < 2; mt++)
        #pragma unroll
        for (int rh = 0; rh < 2; rh++) {
            int m = m0 + WM + mt*16 + (lane >> 2) + rh*8;
            #pragma unroll
            for (int nt = 0; nt < 6; nt++) {
                int col = n0g + WN + nt*8 + (lane & 3)*2;
                float2 v;
                v.x = acc[mt][nt][rh*2 + 0] + g_b2[col];
                v.y = acc[mt][nt][rh*2 + 1] + g_b2[col + 1];
                *(float2*)(out + (size_t)m*DM + col) = v;
            }
        }
}

// ======================= Flash attention (unchanged) =======================
// smem: QH 0 [128][72] (18432), 3 KV stages @18432 + s*35840:
//   KH(s) = 18432 + s*35840 [128][72], VH(s) = KH(s)+18432 [64][136]
// l2r @125952 (2*128 f32) -> total 126976
#define FQH 0u
#define FKH(s) (18432u + (uint32_t)(s)*35840u)
#define FVH(s) (FKH(s) + 18432u)
#define FL2 125952u
#define F_SMEM 126976

__device__ __forceinline__ void flash_load_kv(uint32_t sb, int s, int kt, int tid,
                                              const __half* Kh, const __half* VTh)
{
    const __half* Khc = Kh + (size_t)kt*128*HD;
    #pragma unroll
    for (int i = 0; i < 2; i++) {
        int f = tid + i*512, r = f >> 3, c = (f & 7) * 8;
        cp16(sb + FKH(s) + (uint32_t)(r*144 + c*2), Khc + (size_t)r*HD + c);
    }
    #pragma unroll
    for (int i = 0; i < 2; i++) {
        int f = tid + i*512, e = f >> 4, c = (f & 15) * 8;
        cp16(sb + FVH(s) + (uint32_t)(e*272 + c*2), VTh + (size_t)e*TT + kt*128 + c);
    }
}

__global__ void __launch_bounds__(512)
flash_mma()
{
    extern __shared__ __align__(16) char smc[];
    const uint32_t sb = smem_u32(smc);
    const int qt = blockIdx.x, bhid = blockIdx.y;
    const int tid = threadIdx.x, lane = tid & 31, w = tid >> 5;
    const int WM = (w >> 1) * 16, wn = w & 1;

    const __half* Qh = g_Qh + ((size_t)bhid*TT + qt*128)*HD;
    const __half* Kh = g_Kh + (size_t)bhid*TT*HD;
    const __half* VTh = g_VTh + (size_t)bhid*HD*TT;

    {
        int f = tid, r = f >> 3, c = (f & 7) * 8;
        cp16(sb + FQH + (uint32_t)(r*144 + c*2), Qh + (size_t)r*HD + c);
        f = tid + 512; r = f >> 3; c = (f & 7) * 8;
        cp16(sb + FQH + (uint32_t)(r*144 + c*2), Qh + (size_t)r*HD + c);
    }
    flash_load_kv(sb, 0, 0, tid, Kh, VTh);
    CP_COMMIT();
    flash_load_kv(sb, 1, 1, tid, Kh, VTh);
    CP_COMMIT();

    float oacc[8][4];
    float lreg[2];
    uint32_t qh[4][4];
    #pragma unroll
    for (int nt = 0; nt < 8; nt++)
        #pragma unroll
        for (int c = 0; c < 4; c++) oacc[nt][c] = 0.0f;
    lreg[0] = 0.0f; lreg[1] = 0.0f;

    int sidx = 0;
    #pragma unroll 1
    for (int kt = 0; kt < 16; kt++) {
        CP_WAIT1();
        __syncthreads();
        if (kt + 2 < 16) {
            int sn = sidx + 2; if (sn >= 3) sn -= 3;
            flash_load_kv(sb, sn, kt+2, tid, Kh, VTh);
            CP_COMMIT();
        }
        const int s = sidx;

        if (kt == 0) {
            #pragma unroll
            for (int ks = 0; ks < 4; ks++)
                lda_frag(qh[ks], sb + FQH, WM, ks*16, 72, lane);
        }

        float sacc[8][4];
        #pragma unroll
        for (int nt = 0; nt < 8; nt++)
            #pragma unroll
            for (int c = 0; c < 4; c++) sacc[nt][c] = 0.0f;
        #pragma unroll
        for (int ks = 0; ks < 4; ks++) {
            int kk = ks * 16;
            uint32_t bhf[4][4];
            #pragma unroll
            for (int np = 0; np < 4; np++)
                ldb_frag2(bhf[np], sb + FKH(s), wn*64 + np*16, kk, 72, lane);
            #pragma unroll
            for (int np = 0; np < 4; np++)
                #pragma unroll
                for (int hp = 0; hp < 2; hp++)
                    mma16816(sacc[np*2+hp], qh[ks], bhf[np] + hp*2);
        }

        #pragma unroll
        for (int ks = 0; ks < 4; ks++) {
            uint32_t pa[4];
            #pragma unroll
            for (int half = 0; half < 2; half++) {
                int nt = ks*2 + half;
                float p0 = fexp2(sacc[nt][0]);
                float p1 = fexp2(sacc[nt][1]);
                float p2 = fexp2(sacc[nt][2]);
                float p3 = fexp2(sacc[nt][3]);
                lreg[0] += p0 + p1;
                lreg[1] += p2 + p3;
                pa[half*2 + 0] = h2pack(p0, p1);
                pa[half*2 + 1] = h2pack(p2, p3);
            }
            #pragma unroll
            for (int np = 0; np < 4; np++) {
                uint32_t vb[4];
                ldb_frag2(vb, sb + FVH(s), np*16, wn*64 + ks*16, 136, lane);
                mma16816(oacc[np*2+0], pa, vb);
                mma16816(oacc[np*2+1], pa, vb + 2);
            }
        }
        if (++sidx >= 3) sidx = 0;
    }
    __syncthreads();

    float* l2r = (float*)(smc + FL2);
    {
        float v0 = lreg[0], v1 = lreg[1];
        v0 += __shfl_xor_sync(0xffffffffu, v0, 1);
        v0 += __shfl_xor_sync(0xffffffffu, v0, 2);
        v1 += __shfl_xor_sync(0xffffffffu, v1, 1);
        v1 += __shfl_xor_sync(0xffffffffu, v1, 2);
        if ((lane & 3) == 0) {
            if (wn == 0) {
                l2r[WM + (lane >> 2)]     = v0;
                l2r[WM + (lane >> 2) + 8] = v1;
            }
        }
        __syncthreads();
        if ((lane & 3) == 0 && wn == 1) {
            atomicAdd(&l2r[WM + (lane >> 2)],     v0);
            atomicAdd(&l2r[WM + (lane >> 2) + 8], v1);
        }
    }

    float* plane = (float*)(smc + (uint32_t)wn * 32768u);
    #pragma unroll
    for (int nt = 0; nt < 8; nt++)
        #pragma unroll
        for (int rh = 0; rh < 2; rh++) {
            int row = WM + (lane >> 2) + rh*8;
            int e = nt*8 + (lane & 3)*2;
            *(float2*)(plane + row*64 + e) = make_float2(oacc[nt][rh*2], oacc[nt][rh*2+1]);
        }
    __syncthreads();

    const int b = bhid / NH, h = bhid % NH;
    float* pl0 = (float*)smc;
    float* pl1 = (float*)(smc + 32768u);
    #pragma unroll
    for (int it = 0; it < 8; it++) {
        int idx = tid + it*512;
        int row = idx >> 5, e2 = (idx & 31) * 2;
        float s0 = pl0[row*64 + e2]     + pl1[row*64 + e2];
        float s1 = pl0[row*64 + e2 + 1] + pl1[row*64 + e2 + 1];
        float inv = 1.0f / l2r[row];
        size_t off = ((size_t)(b*TT + qt*128 + row))*DM + h*HD + e2;
        *(__half2*)(g_Ah + off) = __floats2half2_rn(s0 * inv, s1 * inv);
    }
}

// ---------------------------------------------------------------------------
extern "C" void kernel_launch(void* const* d_in, const int* in_sizes, int n_in,
                              void* d_out, int out_size)
{
    const float* X    = (const float*)d_in[0];
    const float* Wq   = (const float*)d_in[1];
    const float* bq   = (const float*)d_in[2];
    const float* Wk   = (const float*)d_in[3];
    const float* bk   = (const float*)d_in[4];
    const float* Wv   = (const float*)d_in[5];
    const float* bv   = (const float*)d_in[6];
    const float* Wo   = (const float*)d_in[7];
    const float* bo   = (const float*)d_in[8];
    const float* gate = (const float*)d_in[9];
    float* out = (float*)d_out;

    static int init = 0;
    if (!init) {
        cudaFuncSetAttribute(qkv_mma,   cudaFuncAttributeMaxDynamicSharedMemorySize, G_SMEM);
        cudaFuncSetAttribute(oproj_mma, cudaFuncAttributeMaxDynamicSharedMemorySize, G_SMEM);
        cudaFuncSetAttribute(flash_mma, cudaFuncAttributeMaxDynamicSharedMemorySize, F_SMEM);
        init = 1;
    }

    prep_all<<<PB_TOT, 256>>>(X, Wq, Wk, Wv, Wo, bo, gate);
    qkv_mma<<<dim3(MTOT/128, NH, 2), 256, G_SMEM>>>(bq, bk, bv);
    flash_mma<<<dim3(TT/128, NBH), 512, F_SMEM>>>();
    oproj_mma<<<dim3(MTOT/128, DM/96), 256, G_SMEM>>>(out);
}